// round 5
// baseline (speedup 1.0000x reference)
#include <cuda_runtime.h>
#include <math.h>

// Problem constants
// x: [32, 128, 128, 64], weights w0..w3: [64,64,16,2], MLPs 64->128->64 (x2)
// out: [2, 32, 128, 128, 64] float32

#define NB 32

// Intermediates (device globals; allocation-free rule)
__device__ float2 gA[NB * 128 * 16 * 64];  // [b][m][ky][i]
__device__ float2 gY[NB * 32 * 16 * 64];   // [b][s][ky][i]
__device__ float2 gT[NB * 32 * 16 * 64];   // [b][s][ky][j]
__device__ float2 gF[NB * 16 * 32 * 64];   // [b][ky][s][o]
__device__ float2 gD[NB * 128 * 16 * 64];  // [b][u][ky][o]

__device__ __forceinline__ unsigned long long pack2(float lo, float hi) {
    unsigned long long r;
    asm("mov.b64 %0, {%1,%2};" : "=l"(r) : "f"(lo), "f"(hi));
    return r;
}
__device__ __forceinline__ void unpack2(unsigned long long v, float& lo, float& hi) {
    asm("mov.b64 {%0,%1}, %2;" : "=f"(lo), "=f"(hi) : "l"(v));
}
__device__ __forceinline__ void ffma2(unsigned long long& d, unsigned long long a, unsigned long long b) {
    asm("fma.rn.f32x2 %0, %1, %2, %0;" : "+l"(d) : "l"(a), "l"(b));
}

// ---------------------------------------------------------------------------
// K1: stage-A forward DFT along n (real input), 16 ky modes.
// A[b,m,ky,i] = sum_n x[b,m,n,i] * (cos(2pi ky n/128) - i sin(...))
// grid 4096 = b*128+m, 256 threads
// ---------------------------------------------------------------------------
__global__ __launch_bounds__(256) void k1_stageA(const float* __restrict__ x) {
    __shared__ float xs[128 * 64];
    __shared__ float2 tab[128];  // {cos, -sin}(2 pi t / 128)
    int bm = blockIdx.x;
    int t = threadIdx.x;

    const float4* src = (const float4*)(x + (size_t)bm * (128 * 64));
    float4* d4 = (float4*)xs;
    #pragma unroll
    for (int e = t; e < 2048; e += 256) d4[e] = src[e];
    if (t < 128) {
        float sv, cv;
        sincospif((float)t * (1.0f / 64.0f), &sv, &cv);
        tab[t] = make_float2(cv, -sv);
    }
    __syncthreads();

    int i = t & 63;
    int kg = t >> 6;      // 0..3 -> ky group of 4
    int ky0 = kg * 4;
    unsigned long long a0 = 0ull, a1 = 0ull, a2 = 0ull, a3 = 0ull;
    int i0 = 0, i1 = 0, i2 = 0, i3 = 0;
    const unsigned long long* tb = (const unsigned long long*)tab;

    #pragma unroll 4
    for (int n = 0; n < 128; n++) {
        float xv = xs[n * 64 + i];
        unsigned long long xv2 = pack2(xv, xv);
        ffma2(a0, xv2, tb[i0]); i0 = (i0 + ky0 + 0) & 127;
        ffma2(a1, xv2, tb[i1]); i1 = (i1 + ky0 + 1) & 127;
        ffma2(a2, xv2, tb[i2]); i2 = (i2 + ky0 + 2) & 127;
        ffma2(a3, xv2, tb[i3]); i3 = (i3 + ky0 + 3) & 127;
    }
    float2* outp = gA + (size_t)bm * (16 * 64);
    float lo, hi;
    unpack2(a0, lo, hi); outp[(ky0 + 0) * 64 + i] = make_float2(lo, hi);
    unpack2(a1, lo, hi); outp[(ky0 + 1) * 64 + i] = make_float2(lo, hi);
    unpack2(a2, lo, hi); outp[(ky0 + 2) * 64 + i] = make_float2(lo, hi);
    unpack2(a3, lo, hi); outp[(ky0 + 3) * 64 + i] = make_float2(lo, hi);
}

// ---------------------------------------------------------------------------
// K2: stage-B forward DFT along m for 32 kx (0..15, 112..127).
// Y[b,s,ky,i] = sum_m A[b,m,ky,i] * e^{-2pi i kx(s) m/128}
// grid 512 = b*16+ky, 256 threads, dynamic smem 66,560 B
// ---------------------------------------------------------------------------
__global__ __launch_bounds__(256) void k2_stageB() {
    extern __shared__ float2 sm2[];
    float2* As = sm2;              // 128*64
    float2* tab = sm2 + 128 * 64;  // 128 {cos, sin}
    int blk = blockIdx.x;
    int b = blk >> 4, ky = blk & 15;
    int t = threadIdx.x;

    for (int e = t; e < 8192; e += 256) {
        int m = e >> 6, i = e & 63;
        As[e] = gA[(((size_t)b * 128 + m) * 16 + ky) * 64 + i];
    }
    if (t < 128) {
        float sv, cv;
        sincospif((float)t * (1.0f / 64.0f), &sv, &cv);
        tab[t] = make_float2(cv, sv);
    }
    __syncthreads();

    int i = t & 63, sg = t >> 6;
    float ar[8], ai[8];
    int idx[8], kxv[8];
    #pragma unroll
    for (int q = 0; q < 8; q++) {
        ar[q] = 0.f; ai[q] = 0.f; idx[q] = 0;
        int s_ = sg * 8 + q;
        kxv[q] = (s_ < 16) ? s_ : (96 + s_);
    }
    for (int m = 0; m < 128; m++) {
        float2 a = As[m * 64 + i];
        #pragma unroll
        for (int q = 0; q < 8; q++) {
            float2 cs = tab[idx[q]];
            // (Ar + iAi)(c - i s): re = Ar c + Ai s ; im = Ai c - Ar s
            ar[q] += a.x * cs.x + a.y * cs.y;
            ai[q] += a.y * cs.x - a.x * cs.y;
            idx[q] = (idx[q] + kxv[q]) & 127;
        }
    }
    #pragma unroll
    for (int q = 0; q < 8; q++) {
        int s_ = sg * 8 + q;
        gY[(((size_t)b * 32 + s_) * 16 + ky) * 64 + i] = make_float2(ar[q], ai[q]);
    }
}

// ---------------------------------------------------------------------------
// K3a: first channel mix. T[b,s,ky,j] = sum_i Wa[i,j,lx] * Y[b,s,ky,i]
// Wa = w0 (s<16) or w2 (s>=16), lx = s & 15.   grid 1024 = b*32+s
// ---------------------------------------------------------------------------
__global__ __launch_bounds__(256) void k3a_mix1(const float* __restrict__ w0,
                                               const float* __restrict__ w2) {
    __shared__ float2 Ys[16 * 64];   // 8KB
    __shared__ float2 Was[64 * 64];  // 32KB
    int blk = blockIdx.x;
    int s = blk & 31;
    int lx = s & 15;
    const float2* w = (const float2*)((s < 16) ? w0 : w2);
    int t = threadIdx.x;

    for (int e = t; e < 1024; e += 256) Ys[e] = gY[(size_t)blk * 1024 + e];
    for (int e = t; e < 4096; e += 256) Was[e] = w[e * 16 + lx];  // [i*64+j]
    __syncthreads();

    int j = t & 63, kg = t >> 6;
    float2 acc[4];
    #pragma unroll
    for (int q = 0; q < 4; q++) acc[q] = make_float2(0.f, 0.f);
    for (int ii = 0; ii < 64; ii++) {
        float2 wv = Was[ii * 64 + j];
        #pragma unroll
        for (int q = 0; q < 4; q++) {
            float2 y = Ys[(kg * 4 + q) * 64 + ii];
            acc[q].x += wv.x * y.x - wv.y * y.y;
            acc[q].y += wv.x * y.y + wv.y * y.x;
        }
    }
    #pragma unroll
    for (int q = 0; q < 4; q++)
        gT[(size_t)blk * 1024 + (kg * 4 + q) * 64 + j] = acc[q];
}

// ---------------------------------------------------------------------------
// K3b: second channel mix. F[b,ky,s,o] = sum_j Wb[j,o,ky] * T[b,s,ky,j]
// Wb = w1 (s<16) or w3 (s>=16).   grid 512 = b*16+ky, dyn smem 81,920 B
// ---------------------------------------------------------------------------
__global__ __launch_bounds__(256) void k3b_mix2(const float* __restrict__ w1,
                                               const float* __restrict__ w3) {
    extern __shared__ float2 sm2b[];
    float2* Ts = sm2b;          // 32*64
    float2* Wb0 = sm2b + 2048;  // 64*64
    float2* Wb1 = Wb0 + 4096;   // 64*64
    int blk = blockIdx.x;
    int b = blk >> 4, ky = blk & 15;
    int t = threadIdx.x;

    for (int e = t; e < 2048; e += 256) {
        int s_ = e >> 6, j = e & 63;
        Ts[e] = gT[(((size_t)b * 32 + s_) * 16 + ky) * 64 + j];
    }
    const float2* w1f = (const float2*)w1;
    const float2* w3f = (const float2*)w3;
    for (int e = t; e < 4096; e += 256) {
        Wb0[e] = w1f[e * 16 + ky];
        Wb1[e] = w3f[e * 16 + ky];
    }
    __syncthreads();

    int o = t & 63, sg = t >> 6;
    const float2* Wb = (sg < 2) ? Wb0 : Wb1;
    float2 acc[8];
    #pragma unroll
    for (int q = 0; q < 8; q++) acc[q] = make_float2(0.f, 0.f);
    for (int j = 0; j < 64; j++) {
        float2 wv = Wb[j * 64 + o];
        #pragma unroll
        for (int q = 0; q < 8; q++) {
            float2 tv = Ts[(sg * 8 + q) * 64 + j];
            acc[q].x += tv.x * wv.x - tv.y * wv.y;
            acc[q].y += tv.x * wv.y + tv.y * wv.x;
        }
    }
    #pragma unroll
    for (int q = 0; q < 8; q++) {
        int s_ = sg * 8 + q;
        gF[(size_t)blk * 2048 + s_ * 64 + o] = acc[q];
    }
}

// ---------------------------------------------------------------------------
// K4: inverse DFT over kx: D[b,u,ky,o] = sum_s F[b,ky,s,o] e^{+2pi i kx(s) u/128}
// grid 512 = b*16+ky
// ---------------------------------------------------------------------------
__global__ __launch_bounds__(256) void k4_invkx() {
    __shared__ float2 Fs[32 * 64];  // 16KB
    __shared__ float2 tab[128];     // {cos, sin}
    int blk = blockIdx.x;
    int b = blk >> 4, ky = blk & 15;
    int t = threadIdx.x;

    for (int e = t; e < 2048; e += 256) Fs[e] = gF[(size_t)blk * 2048 + e];
    if (t < 128) {
        float sv, cv;
        sincospif((float)t * (1.0f / 64.0f), &sv, &cv);
        tab[t] = make_float2(cv, sv);
    }
    __syncthreads();

    int o = t & 63, ug = t >> 6;
    for (int q = 0; q < 32; q++) {
        int u = ug * 32 + q;
        float accr = 0.f, acci = 0.f;
        int idx = 0;  // kx = s for s<16
        #pragma unroll
        for (int s_ = 0; s_ < 16; s_++) {
            float2 f = Fs[s_ * 64 + o];
            float2 cs = tab[idx];
            accr += f.x * cs.x - f.y * cs.y;
            acci += f.x * cs.y + f.y * cs.x;
            idx = (idx + u) & 127;
        }
        idx = (112 * u) & 127;  // kx = 96+s for s>=16 -> start 112*u
        #pragma unroll
        for (int s_ = 16; s_ < 32; s_++) {
            float2 f = Fs[s_ * 64 + o];
            float2 cs = tab[idx];
            accr += f.x * cs.x - f.y * cs.y;
            acci += f.x * cs.y + f.y * cs.x;
            idx = (idx + u) & 127;
        }
        gD[(((size_t)b * 128 + u) * 16 + ky) * 64 + o] = make_float2(accr, acci);
    }
}

// ---------------------------------------------------------------------------
// K5 (fused): inverse over ky -> xo tile in smem -> both MLPs -> out.
// grid 4096 = b*128+u, 256 threads, dyn smem 164,608 B
// smem floats: xs[8192] w1s[8192] w2s[8192] b1s[128] b2s[64] hs[16384]
// (Ds/tab alias the hs region during the xo stage)
// ---------------------------------------------------------------------------
__global__ __launch_bounds__(256, 1) void k5_inv_mlp(
    const float* __restrict__ bw1, const float* __restrict__ bb1,
    const float* __restrict__ bw2, const float* __restrict__ bb2,
    const float* __restrict__ fw1, const float* __restrict__ fb1,
    const float* __restrict__ fw2, const float* __restrict__ fb2,
    float* __restrict__ out) {
    extern __shared__ float sm[];
    float* xs = sm;            // 128 x 64
    float* w1s = sm + 8192;    // 64 x 128
    float* w2s = sm + 16384;   // 128 x 64
    float* b1s = sm + 24576;   // 128
    float* b2s = sm + 24704;   // 64
    float* hs = sm + 24768;    // 128 x 128

    int blk = blockIdx.x;  // b*128 + u
    int t = threadIdx.x;

    // ---- stage 1: xo[v,o] = Re sum_ky alpha_ky/(128*128) * D e^{+2pi i ky v/128}
    {
        float2* Ds = (float2*)hs;      // 1024 float2 (scaled)
        float2* tab2 = Ds + 1024;      // 128 {cos, -sin}
        for (int e = t; e < 1024; e += 256) {
            int ky = e >> 6;
            float sc = ((ky == 0) ? 1.0f : 2.0f) * (1.0f / 16384.0f);
            float2 d = gD[(size_t)blk * 1024 + e];
            Ds[e] = make_float2(d.x * sc, d.y * sc);
        }
        if (t < 128) {
            float sv, cv;
            sincospif((float)t * (1.0f / 64.0f), &sv, &cv);
            tab2[t] = make_float2(cv, -sv);
        }
        __syncthreads();
        int o = t & 63, vg = t >> 6;
        const unsigned long long* tb = (const unsigned long long*)tab2;
        const unsigned long long* D2 = (const unsigned long long*)Ds;
        for (int q = 0; q < 32; q++) {
            int v = vg * 32 + q;
            unsigned long long acc = 0ull;  // {sum Dr*c, sum Di*(-s)}
            int idx = 0;
            #pragma unroll
            for (int ky = 0; ky < 16; ky++) {
                ffma2(acc, D2[ky * 64 + o], tb[idx]);
                idx = (idx + v) & 127;
            }
            float lo, hi;
            unpack2(acc, lo, hi);
            xs[v * 64 + o] = lo + hi;
        }
        __syncthreads();
    }

    // ---- stage 2: two MLPs (bc, fc), weights staged in smem
    size_t rowBase = (size_t)blk * 128;
    for (int p = 0; p < 2; p++) {
        const float* W1 = p ? fw1 : bw1;
        const float* B1 = p ? fb1 : bb1;
        const float* W2 = p ? fw2 : bw2;
        const float* B2 = p ? fb2 : bb2;
        float* outp = out + (size_t)p * 33554432ull;

        __syncthreads();  // prior pass done with w2s/hs
        for (int e = t; e < 8192; e += 256) w1s[e] = W1[e];
        for (int e = t; e < 8192; e += 256) w2s[e] = W2[e];
        if (t < 128) b1s[t] = B1[t];
        if (t < 64) b2s[t] = B2[t];
        __syncthreads();

        // GEMM1: H[128,128] = relu(X[128,64] @ W1[64,128] + b1), tile 8x8
        {
            int rg = t >> 4, cg = t & 15;
            int r0 = rg * 8, c0 = cg * 8;
            unsigned long long acc[8][4];
            unsigned long long binit[4];
            #pragma unroll
            for (int c = 0; c < 4; c++)
                binit[c] = pack2(b1s[c0 + 2 * c], b1s[c0 + 2 * c + 1]);
            #pragma unroll
            for (int j = 0; j < 8; j++)
                #pragma unroll
                for (int c = 0; c < 4; c++) acc[j][c] = binit[c];

            #pragma unroll 2
            for (int k = 0; k < 64; k++) {
                unsigned long long ap[8];
                #pragma unroll
                for (int j = 0; j < 8; j++) {
                    float a = xs[(r0 + j) * 64 + k];
                    ap[j] = pack2(a, a);
                }
                ulonglong2 wv0 = *(const ulonglong2*)&w1s[k * 128 + c0];
                ulonglong2 wv1 = *(const ulonglong2*)&w1s[k * 128 + c0 + 4];
                #pragma unroll
                for (int j = 0; j < 8; j++) {
                    ffma2(acc[j][0], ap[j], wv0.x);
                    ffma2(acc[j][1], ap[j], wv0.y);
                    ffma2(acc[j][2], ap[j], wv1.x);
                    ffma2(acc[j][3], ap[j], wv1.y);
                }
            }
            #pragma unroll
            for (int j = 0; j < 8; j++) {
                #pragma unroll
                for (int c = 0; c < 4; c++) {
                    float lo, hi;
                    unpack2(acc[j][c], lo, hi);
                    lo = fmaxf(lo, 0.f);
                    hi = fmaxf(hi, 0.f);
                    *(float2*)&hs[(r0 + j) * 128 + c0 + 2 * c] = make_float2(lo, hi);
                }
            }
        }
        __syncthreads();

        // GEMM2: O[128,64] = H[128,128] @ W2[128,64] + b2, tile 4x8
        {
            int rg = t >> 3, cg = t & 7;
            int r0 = rg * 4, c0 = cg * 8;
            unsigned long long acc[4][4];
            unsigned long long binit[4];
            #pragma unroll
            for (int c = 0; c < 4; c++)
                binit[c] = pack2(b2s[c0 + 2 * c], b2s[c0 + 2 * c + 1]);
            #pragma unroll
            for (int j = 0; j < 4; j++)
                #pragma unroll
                for (int c = 0; c < 4; c++) acc[j][c] = binit[c];

            #pragma unroll 2
            for (int h = 0; h < 128; h++) {
                unsigned long long ap[4];
                #pragma unroll
                for (int j = 0; j < 4; j++) {
                    float a = hs[(r0 + j) * 128 + h];
                    ap[j] = pack2(a, a);
                }
                ulonglong2 wv0 = *(const ulonglong2*)&w2s[h * 64 + c0];
                ulonglong2 wv1 = *(const ulonglong2*)&w2s[h * 64 + c0 + 4];
                #pragma unroll
                for (int j = 0; j < 4; j++) {
                    ffma2(acc[j][0], ap[j], wv0.x);
                    ffma2(acc[j][1], ap[j], wv0.y);
                    ffma2(acc[j][2], ap[j], wv1.x);
                    ffma2(acc[j][3], ap[j], wv1.y);
                }
            }
            #pragma unroll
            for (int j = 0; j < 4; j++) {
                float v0, v1, v2, v3, v4, v5, v6, v7;
                unpack2(acc[j][0], v0, v1);
                unpack2(acc[j][1], v2, v3);
                unpack2(acc[j][2], v4, v5);
                unpack2(acc[j][3], v6, v7);
                float4* dst = (float4*)(outp + (rowBase + r0 + j) * 64 + c0);
                dst[0] = make_float4(v0, v1, v2, v3);
                dst[1] = make_float4(v4, v5, v6, v7);
            }
        }
    }
}

// ---------------------------------------------------------------------------
extern "C" void kernel_launch(void* const* d_in, const int* in_sizes, int n_in,
                              void* d_out, int out_size) {
    const float* x = (const float*)d_in[0];
    const float* w0 = (const float*)d_in[1];
    const float* w1 = (const float*)d_in[2];
    const float* w2 = (const float*)d_in[3];
    const float* w3 = (const float*)d_in[4];
    const float* bw1 = (const float*)d_in[5];
    const float* bb1 = (const float*)d_in[6];
    const float* bw2 = (const float*)d_in[7];
    const float* bb2 = (const float*)d_in[8];
    const float* fw1 = (const float*)d_in[9];
    const float* fb1 = (const float*)d_in[10];
    const float* fw2 = (const float*)d_in[11];
    const float* fb2 = (const float*)d_in[12];
    float* out = (float*)d_out;

    const int SM_K2 = (128 * 64 + 128) * 8;            // 66,560 B
    const int SM_K3B = (2048 + 4096 + 4096) * 8;       // 81,920 B
    const int SM_K5 = (24768 + 16384) * 4;             // 164,608 B
    cudaFuncSetAttribute(k2_stageB, cudaFuncAttributeMaxDynamicSharedMemorySize, SM_K2);
    cudaFuncSetAttribute(k3b_mix2, cudaFuncAttributeMaxDynamicSharedMemorySize, SM_K3B);
    cudaFuncSetAttribute(k5_inv_mlp, cudaFuncAttributeMaxDynamicSharedMemorySize, SM_K5);

    k1_stageA<<<NB * 128, 256>>>(x);
    k2_stageB<<<NB * 16, 256, SM_K2>>>();
    k3a_mix1<<<NB * 32, 256>>>(w0, w2);
    k3b_mix2<<<NB * 16, 256, SM_K3B>>>(w1, w3);
    k4_invkx<<<NB * 16, 256>>>();
    k5_inv_mlp<<<NB * 128, 256, SM_K5>>>(bw1, bb1, bw2, bb2, fw1, fb1, fw2, fb2, out);
}

// round 6
// speedup vs baseline: 1.0000x; 1.0000x over previous
#include <cuda_runtime.h>
#include <math.h>

// Problem constants
// x: [32, 128, 128, 64], weights w0..w3: [64,64,16,2], MLPs 64->128->64 (x2)
// out: [2, 32, 128, 128, 64] float32

#define NB 32

// Intermediates (device globals; allocation-free rule)
__device__ float2 gA[NB * 128 * 16 * 64];  // [b][m][ky][i]
__device__ float2 gY[NB * 32 * 16 * 64];   // [b][s][ky][i]
__device__ float2 gT[NB * 32 * 16 * 64];   // [b][s][ky][j]
__device__ float2 gF[NB * 16 * 32 * 64];   // [b][ky][s][o]
__device__ float2 gD[NB * 128 * 16 * 64];  // [b][u][ky][o]

__device__ __forceinline__ unsigned long long pack2(float lo, float hi) {
    unsigned long long r;
    asm("mov.b64 %0, {%1,%2};" : "=l"(r) : "f"(lo), "f"(hi));
    return r;
}
__device__ __forceinline__ void unpack2(unsigned long long v, float& lo, float& hi) {
    asm("mov.b64 {%0,%1}, %2;" : "=f"(lo), "=f"(hi) : "l"(v));
}
__device__ __forceinline__ void ffma2(unsigned long long& d, unsigned long long a, unsigned long long b) {
    asm("fma.rn.f32x2 %0, %1, %2, %0;" : "+l"(d) : "l"(a), "l"(b));
}

// ---------------------------------------------------------------------------
// K1: stage-A forward DFT along n (real input), 16 ky modes.
// A[b,m,ky,i] = sum_n x[b,m,n,i] * (cos(2pi ky n/128) - i sin(...))
// grid 4096 = b*128+m, 256 threads
// ---------------------------------------------------------------------------
__global__ __launch_bounds__(256) void k1_stageA(const float* __restrict__ x) {
    __shared__ float xs[128 * 64];
    __shared__ float2 tab[128];  // {cos, -sin}(2 pi t / 128)
    int bm = blockIdx.x;
    int t = threadIdx.x;

    const float4* src = (const float4*)(x + (size_t)bm * (128 * 64));
    float4* d4 = (float4*)xs;
    #pragma unroll
    for (int e = t; e < 2048; e += 256) d4[e] = src[e];
    if (t < 128) {
        float sv, cv;
        sincospif((float)t * (1.0f / 64.0f), &sv, &cv);
        tab[t] = make_float2(cv, -sv);
    }
    __syncthreads();

    int i = t & 63;
    int kg = t >> 6;      // 0..3 -> ky group of 4
    int ky0 = kg * 4;
    unsigned long long a0 = 0ull, a1 = 0ull, a2 = 0ull, a3 = 0ull;
    int i0 = 0, i1 = 0, i2 = 0, i3 = 0;
    const unsigned long long* tb = (const unsigned long long*)tab;

    #pragma unroll 4
    for (int n = 0; n < 128; n++) {
        float xv = xs[n * 64 + i];
        unsigned long long xv2 = pack2(xv, xv);
        ffma2(a0, xv2, tb[i0]); i0 = (i0 + ky0 + 0) & 127;
        ffma2(a1, xv2, tb[i1]); i1 = (i1 + ky0 + 1) & 127;
        ffma2(a2, xv2, tb[i2]); i2 = (i2 + ky0 + 2) & 127;
        ffma2(a3, xv2, tb[i3]); i3 = (i3 + ky0 + 3) & 127;
    }
    float2* outp = gA + (size_t)bm * (16 * 64);
    float lo, hi;
    unpack2(a0, lo, hi); outp[(ky0 + 0) * 64 + i] = make_float2(lo, hi);
    unpack2(a1, lo, hi); outp[(ky0 + 1) * 64 + i] = make_float2(lo, hi);
    unpack2(a2, lo, hi); outp[(ky0 + 2) * 64 + i] = make_float2(lo, hi);
    unpack2(a3, lo, hi); outp[(ky0 + 3) * 64 + i] = make_float2(lo, hi);
}

// ---------------------------------------------------------------------------
// K2: stage-B forward DFT along m for 32 kx (0..15, 112..127).
// Y[b,s,ky,i] = sum_m A[b,m,ky,i] * e^{-2pi i kx(s) m/128}
// grid 512 = b*16+ky, 256 threads, dynamic smem 66,560 B
// ---------------------------------------------------------------------------
__global__ __launch_bounds__(256) void k2_stageB() {
    extern __shared__ float2 sm2[];
    float2* As = sm2;              // 128*64
    float2* tab = sm2 + 128 * 64;  // 128 {cos, sin}
    int blk = blockIdx.x;
    int b = blk >> 4, ky = blk & 15;
    int t = threadIdx.x;

    for (int e = t; e < 8192; e += 256) {
        int m = e >> 6, i = e & 63;
        As[e] = gA[(((size_t)b * 128 + m) * 16 + ky) * 64 + i];
    }
    if (t < 128) {
        float sv, cv;
        sincospif((float)t * (1.0f / 64.0f), &sv, &cv);
        tab[t] = make_float2(cv, sv);
    }
    __syncthreads();

    int i = t & 63, sg = t >> 6;
    float ar[8], ai[8];
    int idx[8], kxv[8];
    #pragma unroll
    for (int q = 0; q < 8; q++) {
        ar[q] = 0.f; ai[q] = 0.f; idx[q] = 0;
        int s_ = sg * 8 + q;
        kxv[q] = (s_ < 16) ? s_ : (96 + s_);
    }
    for (int m = 0; m < 128; m++) {
        float2 a = As[m * 64 + i];
        #pragma unroll
        for (int q = 0; q < 8; q++) {
            float2 cs = tab[idx[q]];
            // (Ar + iAi)(c - i s): re = Ar c + Ai s ; im = Ai c - Ar s
            ar[q] += a.x * cs.x + a.y * cs.y;
            ai[q] += a.y * cs.x - a.x * cs.y;
            idx[q] = (idx[q] + kxv[q]) & 127;
        }
    }
    #pragma unroll
    for (int q = 0; q < 8; q++) {
        int s_ = sg * 8 + q;
        gY[(((size_t)b * 32 + s_) * 16 + ky) * 64 + i] = make_float2(ar[q], ai[q]);
    }
}

// ---------------------------------------------------------------------------
// K3a: first channel mix. T[b,s,ky,j] = sum_i Wa[i,j,lx] * Y[b,s,ky,i]
// Wa = w0 (s<16) or w2 (s>=16), lx = s & 15.   grid 1024 = b*32+s
// ---------------------------------------------------------------------------
__global__ __launch_bounds__(256) void k3a_mix1(const float* __restrict__ w0,
                                               const float* __restrict__ w2) {
    __shared__ float2 Ys[16 * 64];   // 8KB
    __shared__ float2 Was[64 * 64];  // 32KB
    int blk = blockIdx.x;
    int s = blk & 31;
    int lx = s & 15;
    const float2* w = (const float2*)((s < 16) ? w0 : w2);
    int t = threadIdx.x;

    for (int e = t; e < 1024; e += 256) Ys[e] = gY[(size_t)blk * 1024 + e];
    for (int e = t; e < 4096; e += 256) Was[e] = w[e * 16 + lx];  // [i*64+j]
    __syncthreads();

    int j = t & 63, kg = t >> 6;
    float2 acc[4];
    #pragma unroll
    for (int q = 0; q < 4; q++) acc[q] = make_float2(0.f, 0.f);
    for (int ii = 0; ii < 64; ii++) {
        float2 wv = Was[ii * 64 + j];
        #pragma unroll
        for (int q = 0; q < 4; q++) {
            float2 y = Ys[(kg * 4 + q) * 64 + ii];
            acc[q].x += wv.x * y.x - wv.y * y.y;
            acc[q].y += wv.x * y.y + wv.y * y.x;
        }
    }
    #pragma unroll
    for (int q = 0; q < 4; q++)
        gT[(size_t)blk * 1024 + (kg * 4 + q) * 64 + j] = acc[q];
}

// ---------------------------------------------------------------------------
// K3b: second channel mix. F[b,ky,s,o] = sum_j Wb[j,o,ky] * T[b,s,ky,j]
// Wb = w1 (s<16) or w3 (s>=16).   grid 512 = b*16+ky, dyn smem 81,920 B
// ---------------------------------------------------------------------------
__global__ __launch_bounds__(256) void k3b_mix2(const float* __restrict__ w1,
                                               const float* __restrict__ w3) {
    extern __shared__ float2 sm2b[];
    float2* Ts = sm2b;          // 32*64
    float2* Wb0 = sm2b + 2048;  // 64*64
    float2* Wb1 = Wb0 + 4096;   // 64*64
    int blk = blockIdx.x;
    int b = blk >> 4, ky = blk & 15;
    int t = threadIdx.x;

    for (int e = t; e < 2048; e += 256) {
        int s_ = e >> 6, j = e & 63;
        Ts[e] = gT[(((size_t)b * 32 + s_) * 16 + ky) * 64 + j];
    }
    const float2* w1f = (const float2*)w1;
    const float2* w3f = (const float2*)w3;
    for (int e = t; e < 4096; e += 256) {
        Wb0[e] = w1f[e * 16 + ky];
        Wb1[e] = w3f[e * 16 + ky];
    }
    __syncthreads();

    int o = t & 63, sg = t >> 6;
    const float2* Wb = (sg < 2) ? Wb0 : Wb1;
    float2 acc[8];
    #pragma unroll
    for (int q = 0; q < 8; q++) acc[q] = make_float2(0.f, 0.f);
    for (int j = 0; j < 64; j++) {
        float2 wv = Wb[j * 64 + o];
        #pragma unroll
        for (int q = 0; q < 8; q++) {
            float2 tv = Ts[(sg * 8 + q) * 64 + j];
            acc[q].x += tv.x * wv.x - tv.y * wv.y;
            acc[q].y += tv.x * wv.y + tv.y * wv.x;
        }
    }
    #pragma unroll
    for (int q = 0; q < 8; q++) {
        int s_ = sg * 8 + q;
        gF[(size_t)blk * 2048 + s_ * 64 + o] = acc[q];
    }
}

// ---------------------------------------------------------------------------
// K4: inverse DFT over kx: D[b,u,ky,o] = sum_s F[b,ky,s,o] e^{+2pi i kx(s) u/128}
// grid 512 = b*16+ky
// ---------------------------------------------------------------------------
__global__ __launch_bounds__(256) void k4_invkx() {
    __shared__ float2 Fs[32 * 64];  // 16KB
    __shared__ float2 tab[128];     // {cos, sin}
    int blk = blockIdx.x;
    int b = blk >> 4, ky = blk & 15;
    int t = threadIdx.x;

    for (int e = t; e < 2048; e += 256) Fs[e] = gF[(size_t)blk * 2048 + e];
    if (t < 128) {
        float sv, cv;
        sincospif((float)t * (1.0f / 64.0f), &sv, &cv);
        tab[t] = make_float2(cv, sv);
    }
    __syncthreads();

    int o = t & 63, ug = t >> 6;
    for (int q = 0; q < 32; q++) {
        int u = ug * 32 + q;
        float accr = 0.f, acci = 0.f;
        int idx = 0;  // kx = s for s<16
        #pragma unroll
        for (int s_ = 0; s_ < 16; s_++) {
            float2 f = Fs[s_ * 64 + o];
            float2 cs = tab[idx];
            accr += f.x * cs.x - f.y * cs.y;
            acci += f.x * cs.y + f.y * cs.x;
            idx = (idx + u) & 127;
        }
        idx = (112 * u) & 127;  // kx = 96+s for s>=16 -> start 112*u
        #pragma unroll
        for (int s_ = 16; s_ < 32; s_++) {
            float2 f = Fs[s_ * 64 + o];
            float2 cs = tab[idx];
            accr += f.x * cs.x - f.y * cs.y;
            acci += f.x * cs.y + f.y * cs.x;
            idx = (idx + u) & 127;
        }
        gD[(((size_t)b * 128 + u) * 16 + ky) * 64 + o] = make_float2(accr, acci);
    }
}

// ---------------------------------------------------------------------------
// K5 (fused): inverse over ky -> xo tile in smem -> both MLPs -> out.
// grid 4096 = b*128+u, 256 threads, dyn smem 164,608 B
// smem floats: xs[8192] w1s[8192] w2s[8192] b1s[128] b2s[64] hs[16384]
// (Ds/tab alias the hs region during the xo stage)
// ---------------------------------------------------------------------------
__global__ __launch_bounds__(256, 1) void k5_inv_mlp(
    const float* __restrict__ bw1, const float* __restrict__ bb1,
    const float* __restrict__ bw2, const float* __restrict__ bb2,
    const float* __restrict__ fw1, const float* __restrict__ fb1,
    const float* __restrict__ fw2, const float* __restrict__ fb2,
    float* __restrict__ out) {
    extern __shared__ float sm[];
    float* xs = sm;            // 128 x 64
    float* w1s = sm + 8192;    // 64 x 128
    float* w2s = sm + 16384;   // 128 x 64
    float* b1s = sm + 24576;   // 128
    float* b2s = sm + 24704;   // 64
    float* hs = sm + 24768;    // 128 x 128

    int blk = blockIdx.x;  // b*128 + u
    int t = threadIdx.x;

    // ---- stage 1: xo[v,o] = Re sum_ky alpha_ky/(128*128) * D e^{+2pi i ky v/128}
    {
        float2* Ds = (float2*)hs;      // 1024 float2 (scaled)
        float2* tab2 = Ds + 1024;      // 128 {cos, -sin}
        for (int e = t; e < 1024; e += 256) {
            int ky = e >> 6;
            float sc = ((ky == 0) ? 1.0f : 2.0f) * (1.0f / 16384.0f);
            float2 d = gD[(size_t)blk * 1024 + e];
            Ds[e] = make_float2(d.x * sc, d.y * sc);
        }
        if (t < 128) {
            float sv, cv;
            sincospif((float)t * (1.0f / 64.0f), &sv, &cv);
            tab2[t] = make_float2(cv, -sv);
        }
        __syncthreads();
        int o = t & 63, vg = t >> 6;
        const unsigned long long* tb = (const unsigned long long*)tab2;
        const unsigned long long* D2 = (const unsigned long long*)Ds;
        for (int q = 0; q < 32; q++) {
            int v = vg * 32 + q;
            unsigned long long acc = 0ull;  // {sum Dr*c, sum Di*(-s)}
            int idx = 0;
            #pragma unroll
            for (int ky = 0; ky < 16; ky++) {
                ffma2(acc, D2[ky * 64 + o], tb[idx]);
                idx = (idx + v) & 127;
            }
            float lo, hi;
            unpack2(acc, lo, hi);
            xs[v * 64 + o] = lo + hi;
        }
        __syncthreads();
    }

    // ---- stage 2: two MLPs (bc, fc), weights staged in smem
    size_t rowBase = (size_t)blk * 128;
    for (int p = 0; p < 2; p++) {
        const float* W1 = p ? fw1 : bw1;
        const float* B1 = p ? fb1 : bb1;
        const float* W2 = p ? fw2 : bw2;
        const float* B2 = p ? fb2 : bb2;
        float* outp = out + (size_t)p * 33554432ull;

        __syncthreads();  // prior pass done with w2s/hs
        for (int e = t; e < 8192; e += 256) w1s[e] = W1[e];
        for (int e = t; e < 8192; e += 256) w2s[e] = W2[e];
        if (t < 128) b1s[t] = B1[t];
        if (t < 64) b2s[t] = B2[t];
        __syncthreads();

        // GEMM1: H[128,128] = relu(X[128,64] @ W1[64,128] + b1), tile 8x8
        {
            int rg = t >> 4, cg = t & 15;
            int r0 = rg * 8, c0 = cg * 8;
            unsigned long long acc[8][4];
            unsigned long long binit[4];
            #pragma unroll
            for (int c = 0; c < 4; c++)
                binit[c] = pack2(b1s[c0 + 2 * c], b1s[c0 + 2 * c + 1]);
            #pragma unroll
            for (int j = 0; j < 8; j++)
                #pragma unroll
                for (int c = 0; c < 4; c++) acc[j][c] = binit[c];

            #pragma unroll 2
            for (int k = 0; k < 64; k++) {
                unsigned long long ap[8];
                #pragma unroll
                for (int j = 0; j < 8; j++) {
                    float a = xs[(r0 + j) * 64 + k];
                    ap[j] = pack2(a, a);
                }
                ulonglong2 wv0 = *(const ulonglong2*)&w1s[k * 128 + c0];
                ulonglong2 wv1 = *(const ulonglong2*)&w1s[k * 128 + c0 + 4];
                #pragma unroll
                for (int j = 0; j < 8; j++) {
                    ffma2(acc[j][0], ap[j], wv0.x);
                    ffma2(acc[j][1], ap[j], wv0.y);
                    ffma2(acc[j][2], ap[j], wv1.x);
                    ffma2(acc[j][3], ap[j], wv1.y);
                }
            }
            #pragma unroll
            for (int j = 0; j < 8; j++) {
                #pragma unroll
                for (int c = 0; c < 4; c++) {
                    float lo, hi;
                    unpack2(acc[j][c], lo, hi);
                    lo = fmaxf(lo, 0.f);
                    hi = fmaxf(hi, 0.f);
                    *(float2*)&hs[(r0 + j) * 128 + c0 + 2 * c] = make_float2(lo, hi);
                }
            }
        }
        __syncthreads();

        // GEMM2: O[128,64] = H[128,128] @ W2[128,64] + b2, tile 4x8
        {
            int rg = t >> 3, cg = t & 7;
            int r0 = rg * 4, c0 = cg * 8;
            unsigned long long acc[4][4];
            unsigned long long binit[4];
            #pragma unroll
            for (int c = 0; c < 4; c++)
                binit[c] = pack2(b2s[c0 + 2 * c], b2s[c0 + 2 * c + 1]);
            #pragma unroll
            for (int j = 0; j < 4; j++)
                #pragma unroll
                for (int c = 0; c < 4; c++) acc[j][c] = binit[c];

            #pragma unroll 2
            for (int h = 0; h < 128; h++) {
                unsigned long long ap[4];
                #pragma unroll
                for (int j = 0; j < 4; j++) {
                    float a = hs[(r0 + j) * 128 + h];
                    ap[j] = pack2(a, a);
                }
                ulonglong2 wv0 = *(const ulonglong2*)&w2s[h * 64 + c0];
                ulonglong2 wv1 = *(const ulonglong2*)&w2s[h * 64 + c0 + 4];
                #pragma unroll
                for (int j = 0; j < 4; j++) {
                    ffma2(acc[j][0], ap[j], wv0.x);
                    ffma2(acc[j][1], ap[j], wv0.y);
                    ffma2(acc[j][2], ap[j], wv1.x);
                    ffma2(acc[j][3], ap[j], wv1.y);
                }
            }
            #pragma unroll
            for (int j = 0; j < 4; j++) {
                float v0, v1, v2, v3, v4, v5, v6, v7;
                unpack2(acc[j][0], v0, v1);
                unpack2(acc[j][1], v2, v3);
                unpack2(acc[j][2], v4, v5);
                unpack2(acc[j][3], v6, v7);
                float4* dst = (float4*)(outp + (rowBase + r0 + j) * 64 + c0);
                dst[0] = make_float4(v0, v1, v2, v3);
                dst[1] = make_float4(v4, v5, v6, v7);
            }
        }
    }
}

// ---------------------------------------------------------------------------
extern "C" void kernel_launch(void* const* d_in, const int* in_sizes, int n_in,
                              void* d_out, int out_size) {
    const float* x = (const float*)d_in[0];
    const float* w0 = (const float*)d_in[1];
    const float* w1 = (const float*)d_in[2];
    const float* w2 = (const float*)d_in[3];
    const float* w3 = (const float*)d_in[4];
    const float* bw1 = (const float*)d_in[5];
    const float* bb1 = (const float*)d_in[6];
    const float* bw2 = (const float*)d_in[7];
    const float* bb2 = (const float*)d_in[8];
    const float* fw1 = (const float*)d_in[9];
    const float* fb1 = (const float*)d_in[10];
    const float* fw2 = (const float*)d_in[11];
    const float* fb2 = (const float*)d_in[12];
    float* out = (float*)d_out;

    const int SM_K2 = (128 * 64 + 128) * 8;            // 66,560 B
    const int SM_K3B = (2048 + 4096 + 4096) * 8;       // 81,920 B
    const int SM_K5 = (24768 + 16384) * 4;             // 164,608 B
    cudaFuncSetAttribute(k2_stageB, cudaFuncAttributeMaxDynamicSharedMemorySize, SM_K2);
    cudaFuncSetAttribute(k3b_mix2, cudaFuncAttributeMaxDynamicSharedMemorySize, SM_K3B);
    cudaFuncSetAttribute(k5_inv_mlp, cudaFuncAttributeMaxDynamicSharedMemorySize, SM_K5);

    k1_stageA<<<NB * 128, 256>>>(x);
    k2_stageB<<<NB * 16, 256, SM_K2>>>();
    k3a_mix1<<<NB * 32, 256>>>(w0, w2);
    k3b_mix2<<<NB * 16, 256, SM_K3B>>>(w1, w3);
    k4_invkx<<<NB * 16, 256>>>();
    k5_inv_mlp<<<NB * 128, 256, SM_K5>>>(bw1, bb1, bw2, bb2, fw1, fb1, fw2, fb2, out);
}

// round 8
// speedup vs baseline: 2.1051x; 2.1050x over previous
#include <cuda_runtime.h>
#include <cuda_bf16.h>
#include <math.h>

#define NB 32

// ---------------- device globals ----------------
__device__ float2 gA[NB * 128 * 16 * 64];
__device__ float2 gY[NB * 32 * 16 * 64];
__device__ float2 gT[NB * 32 * 16 * 64];
__device__ float2 gF[NB * 16 * 32 * 64];
__device__ float2 gD[NB * 128 * 16 * 64];
// padded bf16 hi/lo weight images: W1^T [n=128][k pad 72], W2^T [n=64][k pad 136]
__device__ __align__(16) unsigned short gW1T[2][2][128 * 72];
__device__ __align__(16) unsigned short gW2T[2][2][64 * 136];
// transposed spectral weights
__device__ float2 gW0t[65536], gW1t[65536], gW2t[65536], gW3t[65536];

// ---------------- helpers ----------------
__device__ __forceinline__ unsigned long long pack2(float lo, float hi) {
    unsigned long long r;
    asm("mov.b64 %0, {%1,%2};" : "=l"(r) : "f"(lo), "f"(hi));
    return r;
}
__device__ __forceinline__ void unpack2(unsigned long long v, float& lo, float& hi) {
    asm("mov.b64 {%0,%1}, %2;" : "=f"(lo), "=f"(hi) : "l"(v));
}
__device__ __forceinline__ void ffma2(unsigned long long& d, unsigned long long a, unsigned long long b) {
    asm("fma.rn.f32x2 %0, %1, %2, %0;" : "+l"(d) : "l"(a), "l"(b));
}
__device__ __forceinline__ unsigned smem_u32(const void* p) {
    unsigned a;
    asm("{ .reg .u64 t; cvta.to.shared.u64 t, %1; cvt.u32.u64 %0, t; }" : "=r"(a) : "l"(p));
    return a;
}
__device__ __forceinline__ void ldm4(unsigned* r, unsigned addr) {
    asm volatile("ldmatrix.sync.aligned.m8n8.x4.shared.b16 {%0,%1,%2,%3}, [%4];"
                 : "=r"(r[0]), "=r"(r[1]), "=r"(r[2]), "=r"(r[3]) : "r"(addr));
}
__device__ __forceinline__ void mma16816(float* c, const unsigned* a, const unsigned* b) {
    asm volatile("mma.sync.aligned.m16n8k16.row.col.f32.bf16.bf16.f32 "
                 "{%0,%1,%2,%3}, {%4,%5,%6,%7}, {%8,%9}, {%0,%1,%2,%3};"
                 : "+f"(c[0]), "+f"(c[1]), "+f"(c[2]), "+f"(c[3])
                 : "r"(a[0]), "r"(a[1]), "r"(a[2]), "r"(a[3]), "r"(b[0]), "r"(b[1]));
}
__device__ __forceinline__ unsigned packbf(float v0, float v1) {
    __nv_bfloat16 h0 = __float2bfloat16(v0), h1 = __float2bfloat16(v1);
    return ((unsigned)__bfloat16_as_ushort(h1) << 16) | __bfloat16_as_ushort(h0);
}

// ---------------- prep: split+pad MLP weights ----------------
__global__ void prep_mlp(const float* __restrict__ bw1, const float* __restrict__ fw1,
                         const float* __restrict__ bw2, const float* __restrict__ fw2) {
    int tid = blockIdx.x * 256 + threadIdx.x;  // 0..35839
    if (tid < 18432) {  // W1^T: [2][128 n][72 k]
        int p = tid / 9216, rem = tid % 9216;
        int n = rem / 72, k = rem % 72;
        const float* W1 = p ? fw1 : bw1;  // [64][128]
        float v = (k < 64) ? W1[k * 128 + n] : 0.f;
        __nv_bfloat16 hi = __float2bfloat16(v);
        __nv_bfloat16 lo = __float2bfloat16(v - __bfloat162float(hi));
        gW1T[p][0][n * 72 + k] = __bfloat16_as_ushort(hi);
        gW1T[p][1][n * 72 + k] = __bfloat16_as_ushort(lo);
    } else if (tid < 35840) {  // W2^T: [2][64 n][136 k]
        int t2 = tid - 18432;
        int p = t2 / 8704, rem = t2 % 8704;
        int n = rem / 136, k = rem % 136;
        const float* W2 = p ? fw2 : bw2;  // [128][64]
        float v = (k < 128) ? W2[k * 64 + n] : 0.f;
        __nv_bfloat16 hi = __float2bfloat16(v);
        __nv_bfloat16 lo = __float2bfloat16(v - __bfloat162float(hi));
        gW2T[p][0][n * 136 + k] = __bfloat16_as_ushort(hi);
        gW2T[p][1][n * 136 + k] = __bfloat16_as_ushort(lo);
    }
}

// ---------------- prep: transpose spectral weights ----------------
__global__ void prep_spec(const float* __restrict__ w0, const float* __restrict__ w1,
                          const float* __restrict__ w2, const float* __restrict__ w3) {
    int e = blockIdx.x * 256 + threadIdx.x;  // 0..65535
    int lx = e >> 12, ij = e & 4095;
    int src = ij * 16 + lx;
    gW0t[e] = ((const float2*)w0)[src];
    gW1t[e] = ((const float2*)w1)[src];
    gW2t[e] = ((const float2*)w2)[src];
    gW3t[e] = ((const float2*)w3)[src];
}

// ---------------- K1: forward DFT along n ----------------
__global__ __launch_bounds__(256) void k1_stageA(const float* __restrict__ x) {
    __shared__ float xs[128 * 64];
    __shared__ float2 tab[128];
    int bm = blockIdx.x, t = threadIdx.x;
    const float4* src = (const float4*)(x + (size_t)bm * (128 * 64));
    float4* d4 = (float4*)xs;
    #pragma unroll
    for (int e = t; e < 2048; e += 256) d4[e] = src[e];
    if (t < 128) {
        float sv, cv;
        sincospif((float)t * (1.0f / 64.0f), &sv, &cv);
        tab[t] = make_float2(cv, -sv);
    }
    __syncthreads();
    int i = t & 63, kg = t >> 6, ky0 = kg * 4;
    unsigned long long a0 = 0ull, a1 = 0ull, a2 = 0ull, a3 = 0ull;
    int i0 = 0, i1 = 0, i2 = 0, i3 = 0;
    const unsigned long long* tb = (const unsigned long long*)tab;
    #pragma unroll 4
    for (int n = 0; n < 128; n++) {
        float xv = xs[n * 64 + i];
        unsigned long long xv2 = pack2(xv, xv);
        ffma2(a0, xv2, tb[i0]); i0 = (i0 + ky0 + 0) & 127;
        ffma2(a1, xv2, tb[i1]); i1 = (i1 + ky0 + 1) & 127;
        ffma2(a2, xv2, tb[i2]); i2 = (i2 + ky0 + 2) & 127;
        ffma2(a3, xv2, tb[i3]); i3 = (i3 + ky0 + 3) & 127;
    }
    float2* outp = gA + (size_t)bm * (16 * 64);
    float lo, hi;
    unpack2(a0, lo, hi); outp[(ky0 + 0) * 64 + i] = make_float2(lo, hi);
    unpack2(a1, lo, hi); outp[(ky0 + 1) * 64 + i] = make_float2(lo, hi);
    unpack2(a2, lo, hi); outp[(ky0 + 2) * 64 + i] = make_float2(lo, hi);
    unpack2(a3, lo, hi); outp[(ky0 + 3) * 64 + i] = make_float2(lo, hi);
}

// ---------------- K2: forward DFT along m ----------------
__global__ __launch_bounds__(256) void k2_stageB() {
    extern __shared__ float2 sm2[];
    float2* As = sm2;
    float2* tab = sm2 + 128 * 64;
    int blk = blockIdx.x, b = blk >> 4, ky = blk & 15, t = threadIdx.x;
    for (int e = t; e < 8192; e += 256) {
        int m = e >> 6, i = e & 63;
        As[e] = gA[(((size_t)b * 128 + m) * 16 + ky) * 64 + i];
    }
    if (t < 128) {
        float sv, cv;
        sincospif((float)t * (1.0f / 64.0f), &sv, &cv);
        tab[t] = make_float2(cv, sv);
    }
    __syncthreads();
    int i = t & 63, sg = t >> 6;
    float ar[8], ai[8];
    int idx[8], kxv[8];
    #pragma unroll
    for (int q = 0; q < 8; q++) {
        ar[q] = 0.f; ai[q] = 0.f; idx[q] = 0;
        int s_ = sg * 8 + q;
        kxv[q] = (s_ < 16) ? s_ : (96 + s_);
    }
    for (int m = 0; m < 128; m++) {
        float2 a = As[m * 64 + i];
        #pragma unroll
        for (int q = 0; q < 8; q++) {
            float2 cs = tab[idx[q]];
            ar[q] += a.x * cs.x + a.y * cs.y;
            ai[q] += a.y * cs.x - a.x * cs.y;
            idx[q] = (idx[q] + kxv[q]) & 127;
        }
    }
    #pragma unroll
    for (int q = 0; q < 8; q++) {
        int s_ = sg * 8 + q;
        gY[(((size_t)b * 32 + s_) * 16 + ky) * 64 + i] = make_float2(ar[q], ai[q]);
    }
}

// ---------------- K3a ----------------
__global__ __launch_bounds__(256) void k3a_mix1() {
    __shared__ float2 Ys[16 * 64];
    __shared__ float2 Was[64 * 64];
    int blk = blockIdx.x, s = blk & 31, lx = s & 15, t = threadIdx.x;
    const float2* wt = (s < 16) ? gW0t : gW2t;
    for (int e = t; e < 1024; e += 256) Ys[e] = gY[(size_t)blk * 1024 + e];
    for (int e = t; e < 4096; e += 256) Was[e] = wt[lx * 4096 + e];
    __syncthreads();
    int j = t & 63, kg = t >> 6;
    float2 acc[4];
    #pragma unroll
    for (int q = 0; q < 4; q++) acc[q] = make_float2(0.f, 0.f);
    for (int ii = 0; ii < 64; ii++) {
        float2 wv = Was[ii * 64 + j];
        #pragma unroll
        for (int q = 0; q < 4; q++) {
            float2 y = Ys[(kg * 4 + q) * 64 + ii];
            acc[q].x += wv.x * y.x - wv.y * y.y;
            acc[q].y += wv.x * y.y + wv.y * y.x;
        }
    }
    #pragma unroll
    for (int q = 0; q < 4; q++)
        gT[(size_t)blk * 1024 + (kg * 4 + q) * 64 + j] = acc[q];
}

// ---------------- K3b ----------------
__global__ __launch_bounds__(256) void k3b_mix2() {
    extern __shared__ float2 sm2b[];
    float2* Ts = sm2b;
    float2* Wb0 = sm2b + 2048;
    float2* Wb1 = Wb0 + 4096;
    int blk = blockIdx.x, b = blk >> 4, ky = blk & 15, t = threadIdx.x;
    for (int e = t; e < 2048; e += 256) {
        int s_ = e >> 6, j = e & 63;
        Ts[e] = gT[(((size_t)b * 32 + s_) * 16 + ky) * 64 + j];
    }
    for (int e = t; e < 4096; e += 256) {
        Wb0[e] = gW1t[ky * 4096 + e];
        Wb1[e] = gW3t[ky * 4096 + e];
    }
    __syncthreads();
    int o = t & 63, sg = t >> 6;
    const float2* Wb = (sg < 2) ? Wb0 : Wb1;
    float2 acc[8];
    #pragma unroll
    for (int q = 0; q < 8; q++) acc[q] = make_float2(0.f, 0.f);
    for (int j = 0; j < 64; j++) {
        float2 wv = Wb[j * 64 + o];
        #pragma unroll
        for (int q = 0; q < 8; q++) {
            float2 tv = Ts[(sg * 8 + q) * 64 + j];
            acc[q].x += tv.x * wv.x - tv.y * wv.y;
            acc[q].y += tv.x * wv.y + tv.y * wv.x;
        }
    }
    #pragma unroll
    for (int q = 0; q < 8; q++) {
        int s_ = sg * 8 + q;
        gF[(size_t)blk * 2048 + s_ * 64 + o] = acc[q];
    }
}

// ---------------- K4: inverse DFT over kx ----------------
__global__ __launch_bounds__(256) void k4_invkx() {
    __shared__ float2 Fs[32 * 64];
    __shared__ float2 tab[128];
    int blk = blockIdx.x, b = blk >> 4, ky = blk & 15, t = threadIdx.x;
    for (int e = t; e < 2048; e += 256) Fs[e] = gF[(size_t)blk * 2048 + e];
    if (t < 128) {
        float sv, cv;
        sincospif((float)t * (1.0f / 64.0f), &sv, &cv);
        tab[t] = make_float2(cv, sv);
    }
    __syncthreads();
    int o = t & 63, ug = t >> 6;
    for (int q = 0; q < 32; q++) {
        int u = ug * 32 + q;
        float accr = 0.f, acci = 0.f;
        int idx = 0;
        #pragma unroll
        for (int s_ = 0; s_ < 16; s_++) {
            float2 f = Fs[s_ * 64 + o];
            float2 cs = tab[idx];
            accr += f.x * cs.x - f.y * cs.y;
            acci += f.x * cs.y + f.y * cs.x;
            idx = (idx + u) & 127;
        }
        idx = (112 * u) & 127;
        #pragma unroll
        for (int s_ = 16; s_ < 32; s_++) {
            float2 f = Fs[s_ * 64 + o];
            float2 cs = tab[idx];
            accr += f.x * cs.x - f.y * cs.y;
            acci += f.x * cs.y + f.y * cs.x;
            idx = (idx + u) & 127;
        }
        gD[(((size_t)b * 128 + u) * 16 + ky) * 64 + o] = make_float2(accr, acci);
    }
}

// ---------------- K5: inverse ky + both MLPs via mma.sync ----------------
// smem byte offsets. X/W1: row stride 144B (72 bf16); H/W2: 272B (136 bf16).
#define OFF_XHI   0u
#define OFF_XLO   18432u
#define OFF_W1HI  36864u
#define OFF_W1LO  55296u
#define OFF_W2HI  73728u
#define OFF_W2LO  91136u
#define OFF_HHI   108544u
#define OFF_HLO   143360u
#define OFF_B1    178176u
#define OFF_B2    178688u
#define SMEM_K5   178944

__global__ __launch_bounds__(256, 1) void k5_mma(
    const float* __restrict__ bb1, const float* __restrict__ bb2,
    const float* __restrict__ fb1, const float* __restrict__ fb2,
    float* __restrict__ out) {
    extern __shared__ __align__(16) char sm[];
    unsigned sb = smem_u32(sm);
    int t = threadIdx.x, w = t >> 5, l = t & 31;
    int blk = blockIdx.x;

    // ---- stage 1: E [128v][32c], Dp [32c][64o] in scratch (aliases H region)
    float* E = (float*)(sm + OFF_HHI);
    float* Dp = (float*)(sm + OFF_HHI + 16384);
    for (int e = t; e < 4096; e += 256) {
        int v = e >> 5, c = e & 31, k = c >> 1;
        float sv, cv;
        sincospif((float)(v * k) * (1.0f / 64.0f), &sv, &cv);
        E[e] = (c & 1) ? sv : cv;
    }
    for (int e = t; e < 1024; e += 256) {
        int ky = e >> 6, o = e & 63;
        float2 d = gD[(size_t)blk * 1024 + e];
        float sc = (ky ? 2.0f : 1.0f) * (1.0f / 16384.0f);
        Dp[(2 * ky) * 64 + o] = d.x * sc;
        Dp[(2 * ky + 1) * 64 + o] = -d.y * sc;
    }
    __syncthreads();

    // xo = E @ Dp (128x64, K=32) -> bf16 hi/lo A operand (padded 144B rows)
    {
        int rg = t >> 4, cg = t & 15;
        int r0 = rg * 8, c0 = cg * 4;
        unsigned long long acc[8][2];
        #pragma unroll
        for (int j = 0; j < 8; j++) { acc[j][0] = 0ull; acc[j][1] = 0ull; }
        for (int c = 0; c < 32; c++) {
            float4 dp = *(const float4*)&Dp[c * 64 + c0];
            unsigned long long d01 = pack2(dp.x, dp.y), d23 = pack2(dp.z, dp.w);
            #pragma unroll
            for (int j = 0; j < 8; j++) {
                float ev = E[(r0 + j) * 32 + c];
                unsigned long long e2 = pack2(ev, ev);
                ffma2(acc[j][0], e2, d01);
                ffma2(acc[j][1], e2, d23);
            }
        }
        #pragma unroll
        for (int j = 0; j < 8; j++) {
            float x0, x1, x2, x3;
            unpack2(acc[j][0], x0, x1);
            unpack2(acc[j][1], x2, x3);
            __nv_bfloat16 h0 = __float2bfloat16(x0), h1 = __float2bfloat16(x1);
            __nv_bfloat16 h2 = __float2bfloat16(x2), h3 = __float2bfloat16(x3);
            float r0f = x0 - __bfloat162float(h0), r1f = x1 - __bfloat162float(h1);
            float r2f = x2 - __bfloat162float(h2), r3f = x3 - __bfloat162float(h3);
            unsigned relb = (unsigned)(r0 + j) * 144u + (unsigned)c0 * 2u;
            *(uint2*)(sm + OFF_XHI + relb) = make_uint2(packbf(x0, x1) * 0u + (((unsigned)__bfloat16_as_ushort(h1) << 16) | __bfloat16_as_ushort(h0)),
                                                       ((unsigned)__bfloat16_as_ushort(h3) << 16) | __bfloat16_as_ushort(h2));
            *(uint2*)(sm + OFF_XLO + relb) = make_uint2(packbf(r0f, r1f), packbf(r2f, r3f));
        }
    }

    size_t rowBase = (size_t)blk * 128;

    for (int p = 0; p < 2; p++) {
        __syncthreads();
        // ---- stage weights + biases into smem
        {
            const uint4* s0 = (const uint4*)gW1T[p][0];
            const uint4* s1 = (const uint4*)gW1T[p][1];
            const uint4* s2 = (const uint4*)gW2T[p][0];
            const uint4* s3 = (const uint4*)gW2T[p][1];
            uint4* d0 = (uint4*)(sm + OFF_W1HI);
            uint4* d1 = (uint4*)(sm + OFF_W1LO);
            uint4* d2 = (uint4*)(sm + OFF_W2HI);
            uint4* d3 = (uint4*)(sm + OFF_W2LO);
            for (int e = t; e < 1152; e += 256) { d0[e] = s0[e]; d1[e] = s1[e]; }
            for (int e = t; e < 1088; e += 256) { d2[e] = s2[e]; d3[e] = s3[e]; }
            if (t < 128) ((float*)(sm + OFF_B1))[t] = p ? fb1[t] : bb1[t];
            if (t < 64) ((float*)(sm + OFF_B2))[t] = p ? fb2[t] : bb2[t];
        }
        __syncthreads();

        int wm = w & 1, wn = w >> 1;
        unsigned kA = ((l >> 4) & 1) * 8;
        unsigned kB = ((l >> 3) & 1) * 8;
        unsigned rowA = (unsigned)(wm * 64 + (l & 7) + ((l >> 3) & 1) * 8);

        // ---- GEMM1: C1[128,128] = X @ W1 (3-term bf16 split)
        {
            float acc[4][4][4];
            #pragma unroll
            for (int a = 0; a < 4; a++)
                #pragma unroll
                for (int b = 0; b < 4; b++)
                    #pragma unroll
                    for (int c = 0; c < 4; c++) acc[a][b][c] = 0.f;

            unsigned rowB = (unsigned)(wn * 32 + ((l >> 4) << 3) + (l & 7));
            unsigned aXhi = sb + OFF_XHI + rowA * 144 + kA * 2;
            unsigned aXlo = sb + OFF_XLO + rowA * 144 + kA * 2;
            unsigned aBhi = sb + OFF_W1HI + rowB * 144 + kB * 2;
            unsigned aBlo = sb + OFF_W1LO + rowB * 144 + kB * 2;

            #pragma unroll
            for (int ki = 0; ki < 4; ki++) {
                unsigned kb = ki * 32;
                unsigned ah[4][4], al[4][4], bh[2][4], bl[2][4];
                #pragma unroll
                for (int mf = 0; mf < 4; mf++) {
                    ldm4(ah[mf], aXhi + mf * (16 * 144) + kb);
                    ldm4(al[mf], aXlo + mf * (16 * 144) + kb);
                }
                #pragma unroll
                for (int h2 = 0; h2 < 2; h2++) {
                    ldm4(bh[h2], aBhi + h2 * (16 * 144) + kb);
                    ldm4(bl[h2], aBlo + h2 * (16 * 144) + kb);
                }
                #pragma unroll
                for (int mf = 0; mf < 4; mf++)
                    #pragma unroll
                    for (int nf = 0; nf < 4; nf++) {
                        const unsigned* bph = &bh[nf >> 1][(nf & 1) * 2];
                        const unsigned* bpl = &bl[nf >> 1][(nf & 1) * 2];
                        mma16816(acc[mf][nf], ah[mf], bph);
                        mma16816(acc[mf][nf], ah[mf], bpl);
                        mma16816(acc[mf][nf], al[mf], bph);
                    }
            }
            // epilogue 1: bias + relu + split -> H (272B rows)
            const float* b1s = (const float*)(sm + OFF_B1);
            int rbase = wm * 64 + (l >> 2);
            int ncol = 2 * (l & 3);
            #pragma unroll
            for (int mf = 0; mf < 4; mf++)
                #pragma unroll
                for (int nf = 0; nf < 4; nf++) {
                    int n = wn * 32 + nf * 8 + ncol;
                    float bv0 = b1s[n], bv1 = b1s[n + 1];
                    #pragma unroll
                    for (int half = 0; half < 2; half++) {
                        int r = rbase + mf * 16 + half * 8;
                        float v0 = fmaxf(acc[mf][nf][half * 2 + 0] + bv0, 0.f);
                        float v1 = fmaxf(acc[mf][nf][half * 2 + 1] + bv1, 0.f);
                        __nv_bfloat16 h0 = __float2bfloat16(v0), h1 = __float2bfloat16(v1);
                        float g0 = v0 - __bfloat162float(h0), g1 = v1 - __bfloat162float(h1);
                        unsigned off = (unsigned)r * 272u + (unsigned)n * 2u;
                        *(unsigned*)(sm + OFF_HHI + off) =
                            ((unsigned)__bfloat16_as_ushort(h1) << 16) | __bfloat16_as_ushort(h0);
                        *(unsigned*)(sm + OFF_HLO + off) = packbf(g0, g1);
                    }
                }
        }
        __syncthreads();

        // ---- GEMM2: C2[128,64] = H @ W2 (3-term bf16 split)
        {
            float acc[4][2][4];
            #pragma unroll
            for (int a = 0; a < 4; a++)
                #pragma unroll
                for (int b = 0; b < 2; b++)
                    #pragma unroll
                    for (int c = 0; c < 4; c++) acc[a][b][c] = 0.f;

            unsigned rowB = (unsigned)(wn * 16 + ((l >> 4) << 3) + (l & 7));
            unsigned aHhi = sb + OFF_HHI + rowA * 272 + kA * 2;
            unsigned aHlo = sb + OFF_HLO + rowA * 272 + kA * 2;
            unsigned aChi = sb + OFF_W2HI + rowB * 272 + kB * 2;
            unsigned aClo = sb + OFF_W2LO + rowB * 272 + kB * 2;

            #pragma unroll
            for (int ki = 0; ki < 8; ki++) {
                unsigned kb = ki * 32;
                unsigned ah[4][4], al[4][4], bh[4], bl[4];
                #pragma unroll
                for (int mf = 0; mf < 4; mf++) {
                    ldm4(ah[mf], aHhi + mf * (16 * 272) + kb);
                    ldm4(al[mf], aHlo + mf * (16 * 272) + kb);
                }
                ldm4(bh, aChi + kb);
                ldm4(bl, aClo + kb);
                #pragma unroll
                for (int mf = 0; mf < 4; mf++)
                    #pragma unroll
                    for (int nf = 0; nf < 2; nf++) {
                        const unsigned* bph = &bh[nf * 2];
                        const unsigned* bpl = &bl[nf * 2];
                        mma16816(acc[mf][nf], ah[mf], bph);
                        mma16816(acc[mf][nf], ah[mf], bpl);
                        mma16816(acc[mf][nf], al[mf], bph);
                    }
            }
            // epilogue 2: bias + store to global
            const float* b2s = (const float*)(sm + OFF_B2);
            float* outp = out + (size_t)p * 33554432ull + rowBase * 64;
            int rbase = wm * 64 + (l >> 2);
            int ncol = 2 * (l & 3);
            #pragma unroll
            for (int mf = 0; mf < 4; mf++)
                #pragma unroll
                for (int nf = 0; nf < 2; nf++) {
                    int n = wn * 16 + nf * 8 + ncol;
                    float bv0 = b2s[n], bv1 = b2s[n + 1];
                    #pragma unroll
                    for (int half = 0; half < 2; half++) {
                        int r = rbase + mf * 16 + half * 8;
                        float2 val = make_float2(acc[mf][nf][half * 2 + 0] + bv0,
                                                 acc[mf][nf][half * 2 + 1] + bv1);
                        *(float2*)(outp + (size_t)r * 64 + n) = val;
                    }
                }
        }
    }
}

// ---------------------------------------------------------------------------
extern "C" void kernel_launch(void* const* d_in, const int* in_sizes, int n_in,
                              void* d_out, int out_size) {
    const float* x = (const float*)d_in[0];
    const float* w0 = (const float*)d_in[1];
    const float* w1 = (const float*)d_in[2];
    const float* w2 = (const float*)d_in[3];
    const float* w3 = (const float*)d_in[4];
    const float* bw1 = (const float*)d_in[5];
    const float* bb1 = (const float*)d_in[6];
    const float* bw2 = (const float*)d_in[7];
    const float* bb2 = (const float*)d_in[8];
    const float* fw1 = (const float*)d_in[9];
    const float* fb1 = (const float*)d_in[10];
    const float* fw2 = (const float*)d_in[11];
    const float* fb2 = (const float*)d_in[12];
    float* out = (float*)d_out;

    const int SM_K2 = (128 * 64 + 128) * 8;
    const int SM_K3B = (2048 + 4096 + 4096) * 8;
    cudaFuncSetAttribute(k2_stageB, cudaFuncAttributeMaxDynamicSharedMemorySize, SM_K2);
    cudaFuncSetAttribute(k3b_mix2, cudaFuncAttributeMaxDynamicSharedMemorySize, SM_K3B);
    cudaFuncSetAttribute(k5_mma, cudaFuncAttributeMaxDynamicSharedMemorySize, SMEM_K5);

    prep_mlp<<<140, 256>>>(bw1, fw1, bw2, fw2);
    prep_spec<<<256, 256>>>(w0, w1, w2, w3);
    k1_stageA<<<NB * 128, 256>>>(x);
    k2_stageB<<<NB * 16, 256, SM_K2>>>();
    k3a_mix1<<<NB * 32, 256>>>();
    k3b_mix2<<<NB * 16, 256, SM_K3B>>>();
    k4_invkx<<<NB * 16, 256>>>();
    k5_mma<<<NB * 128, 256, SMEM_K5>>>(bb1, bb2, fb1, fb2, out);
}

// round 9
// speedup vs baseline: 2.3550x; 1.1187x over previous
#include <cuda_runtime.h>
#include <cuda_bf16.h>
#include <math.h>

#define NB 32

// ---------------- device globals ----------------
__device__ float2 gA[NB * 128 * 16 * 64];
__device__ float2 gY[NB * 32 * 16 * 64];
__device__ float2 gT[NB * 32 * 16 * 64];
__device__ float2 gF[NB * 16 * 32 * 64];
__device__ float2 gD[NB * 128 * 16 * 64];
// padded bf16 hi/lo weight images: W1^T [n=128][k pad 72], W2^T [n=64][k pad 136]
__device__ __align__(16) unsigned short gW1T[2][2][128 * 72];
__device__ __align__(16) unsigned short gW2T[2][2][64 * 136];
// transposed spectral weights
__device__ float2 gW0t[65536], gW1t[65536], gW2t[65536], gW3t[65536];
// duplicated inverse-ky basis: E2[v*32+c] = {e,e}
__device__ __align__(16) float2 gE2[4096];

// ---------------- helpers ----------------
typedef unsigned long long ull;
__device__ __forceinline__ ull pack2(float lo, float hi) {
    ull r;
    asm("mov.b64 %0, {%1,%2};" : "=l"(r) : "f"(lo), "f"(hi));
    return r;
}
__device__ __forceinline__ void unpack2(ull v, float& lo, float& hi) {
    asm("mov.b64 {%0,%1}, %2;" : "=f"(lo), "=f"(hi) : "l"(v));
}
__device__ __forceinline__ void ffma2(ull& d, ull a, ull b) {
    asm("fma.rn.f32x2 %0, %1, %2, %0;" : "+l"(d) : "l"(a), "l"(b));
}
__device__ __forceinline__ unsigned smem_u32(const void* p) {
    unsigned a;
    asm("{ .reg .u64 t; cvta.to.shared.u64 t, %1; cvt.u32.u64 %0, t; }" : "=r"(a) : "l"(p));
    return a;
}
__device__ __forceinline__ void ldm4(unsigned* r, unsigned addr) {
    asm volatile("ldmatrix.sync.aligned.m8n8.x4.shared.b16 {%0,%1,%2,%3}, [%4];"
                 : "=r"(r[0]), "=r"(r[1]), "=r"(r[2]), "=r"(r[3]) : "r"(addr));
}
__device__ __forceinline__ void mma16816(float* c, const unsigned* a, const unsigned* b) {
    asm volatile("mma.sync.aligned.m16n8k16.row.col.f32.bf16.bf16.f32 "
                 "{%0,%1,%2,%3}, {%4,%5,%6,%7}, {%8,%9}, {%0,%1,%2,%3};"
                 : "+f"(c[0]), "+f"(c[1]), "+f"(c[2]), "+f"(c[3])
                 : "r"(a[0]), "r"(a[1]), "r"(a[2]), "r"(a[3]), "r"(b[0]), "r"(b[1]));
}
// packed split: v0,v1 -> bf16x2 hi image + bf16x2 residual image
__device__ __forceinline__ void split2(float v0, float v1, unsigned& hp, unsigned& lp) {
    asm("cvt.rn.bf16x2.f32 %0, %1, %2;" : "=r"(hp) : "f"(v1), "f"(v0));
    float h0 = __uint_as_float(hp << 16);
    float h1 = __uint_as_float(hp & 0xFFFF0000u);
    float l0 = v0 - h0, l1 = v1 - h1;
    asm("cvt.rn.bf16x2.f32 %0, %1, %2;" : "=r"(lp) : "f"(l1), "f"(l0));
}

// ---------------- prep: split+pad MLP weights ----------------
__global__ void prep_mlp(const float* __restrict__ bw1, const float* __restrict__ fw1,
                         const float* __restrict__ bw2, const float* __restrict__ fw2) {
    int tid = blockIdx.x * 256 + threadIdx.x;
    if (tid < 18432) {  // W1^T: [2][128 n][72 k]
        int p = tid / 9216, rem = tid % 9216;
        int n = rem / 72, k = rem % 72;
        const float* W1 = p ? fw1 : bw1;
        float v = (k < 64) ? W1[k * 128 + n] : 0.f;
        __nv_bfloat16 hi = __float2bfloat16(v);
        __nv_bfloat16 lo = __float2bfloat16(v - __bfloat162float(hi));
        gW1T[p][0][n * 72 + k] = __bfloat16_as_ushort(hi);
        gW1T[p][1][n * 72 + k] = __bfloat16_as_ushort(lo);
    } else if (tid < 35840) {  // W2^T: [2][64 n][136 k]
        int t2 = tid - 18432;
        int p = t2 / 8704, rem = t2 % 8704;
        int n = rem / 136, k = rem % 136;
        const float* W2 = p ? fw2 : bw2;
        float v = (k < 128) ? W2[k * 64 + n] : 0.f;
        __nv_bfloat16 hi = __float2bfloat16(v);
        __nv_bfloat16 lo = __float2bfloat16(v - __bfloat162float(hi));
        gW2T[p][0][n * 136 + k] = __bfloat16_as_ushort(hi);
        gW2T[p][1][n * 136 + k] = __bfloat16_as_ushort(lo);
    }
}

// ---------------- prep: transpose spectral weights ----------------
__global__ void prep_spec(const float* __restrict__ w0, const float* __restrict__ w1,
                          const float* __restrict__ w2, const float* __restrict__ w3) {
    int e = blockIdx.x * 256 + threadIdx.x;
    int lx = e >> 12, ij = e & 4095;
    int src = ij * 16 + lx;
    gW0t[e] = ((const float2*)w0)[src];
    gW1t[e] = ((const float2*)w1)[src];
    gW2t[e] = ((const float2*)w2)[src];
    gW3t[e] = ((const float2*)w3)[src];
}

// ---------------- prep: E table for k5 stage-1 ----------------
__global__ void prep_e() {
    int e = blockIdx.x * 256 + threadIdx.x;  // 0..4095
    int v = e >> 5, c = e & 31, k = c >> 1;
    float sv, cv;
    sincospif((float)(v * k) * (1.0f / 64.0f), &sv, &cv);
    float val = (c & 1) ? sv : cv;
    gE2[e] = make_float2(val, val);
}

// ---------------- K1: forward DFT along n (folded, 16 ky) ----------------
// dyn smem: xs[8192]f, sd[4032]f2, tab[128]f2 = 66048 B
__global__ __launch_bounds__(256) void k1_stageA(const float* __restrict__ x) {
    extern __shared__ float smf[];
    float* xs = smf;
    float2* sd = (float2*)(smf + 8192);
    float2* tab = (float2*)(smf + 8192 + 8064);
    int bm = blockIdx.x, t = threadIdx.x;
    const float4* src = (const float4*)(x + (size_t)bm * (128 * 64));
    float4* d4 = (float4*)xs;
    #pragma unroll
    for (int e = t; e < 2048; e += 256) d4[e] = src[e];
    if (t < 128) {
        float sv, cv;
        sincospif((float)t * (1.0f / 64.0f), &sv, &cv);
        tab[t] = make_float2(cv, -sv);
    }
    __syncthreads();
    // fold: sd[(n-1)*64+i] = {x_n + x_{128-n}, x_n - x_{128-n}}
    for (int e = t; e < 4032; e += 256) {
        int n = (e >> 6) + 1, i = e & 63;
        float a = xs[n * 64 + i], b = xs[(128 - n) * 64 + i];
        sd[e] = make_float2(a + b, a - b);
    }
    __syncthreads();

    int i = t & 63, kg = t >> 6;
    float x0 = xs[i], x64 = xs[4096 + i];
    const ull* tb = (const ull*)tab;
    const ull* sd2 = (const ull*)sd;
    ull a0, a1, a2, a3;
    int ky0 = kg * 4;
    a0 = pack2(x0 + (((ky0 + 0) & 1) ? -x64 : x64), 0.f);
    a1 = pack2(x0 + (((ky0 + 1) & 1) ? -x64 : x64), 0.f);
    a2 = pack2(x0 + (((ky0 + 2) & 1) ? -x64 : x64), 0.f);
    a3 = pack2(x0 + (((ky0 + 3) & 1) ? -x64 : x64), 0.f);
    int i0 = ky0, i1 = ky0 + 1, i2 = ky0 + 2, i3 = ky0 + 3;
    #pragma unroll 7
    for (int n = 1; n <= 63; n++) {
        ull sdv = sd2[(n - 1) * 64 + i];
        ffma2(a0, sdv, tb[i0]); i0 = (i0 + ky0 + 0) & 127;
        ffma2(a1, sdv, tb[i1]); i1 = (i1 + ky0 + 1) & 127;
        ffma2(a2, sdv, tb[i2]); i2 = (i2 + ky0 + 2) & 127;
        ffma2(a3, sdv, tb[i3]); i3 = (i3 + ky0 + 3) & 127;
    }
    float2* outp = gA + (size_t)bm * (16 * 64);
    float lo, hi;
    unpack2(a0, lo, hi); outp[(ky0 + 0) * 64 + i] = make_float2(lo, hi);
    unpack2(a1, lo, hi); outp[(ky0 + 1) * 64 + i] = make_float2(lo, hi);
    unpack2(a2, lo, hi); outp[(ky0 + 2) * 64 + i] = make_float2(lo, hi);
    unpack2(a3, lo, hi); outp[(ky0 + 3) * 64 + i] = make_float2(lo, hi);
}

// ---------------- K2: forward DFT along m (paired +-kx) ----------------
__global__ __launch_bounds__(256) void k2_stageB() {
    extern __shared__ float2 sm2[];
    float2* As = sm2;
    float2* tab = sm2 + 128 * 64;
    int blk = blockIdx.x, b = blk >> 4, ky = blk & 15, t = threadIdx.x;
    for (int e = t; e < 8192; e += 256) {
        int m = e >> 6, i = e & 63;
        As[e] = gA[(((size_t)b * 128 + m) * 16 + ky) * 64 + i];
    }
    if (t < 128) {
        float sv, cv;
        sincospif((float)t * (1.0f / 64.0f), &sv, &cv);
        tab[t] = make_float2(cv, sv);
    }
    __syncthreads();

    int i = t & 63, ug = t >> 6;
    float u1[4], u2[4], u3[4], u4[4];
    int idx[4], stp[4];
    #pragma unroll
    for (int q = 0; q < 4; q++) {
        stp[q] = ug * 4 + q + 1;  // k = 1..16
        idx[q] = 0;
        u1[q] = u2[q] = u3[q] = u4[q] = 0.f;
    }
    float sx = 0.f, sy = 0.f;
    for (int m = 0; m < 128; m++) {
        float2 a = As[m * 64 + i];
        #pragma unroll
        for (int q = 0; q < 4; q++) {
            float2 cs = tab[idx[q]];
            u1[q] += a.x * cs.x;
            u2[q] += a.y * cs.y;
            u3[q] += a.y * cs.x;
            u4[q] += a.x * cs.y;
            idx[q] = (idx[q] + stp[q]) & 127;
        }
        if (ug == 3) { sx += a.x; sy += a.y; }
    }
    float2* yb = gY + (((size_t)b * 32) * 16 + ky) * 64 + i;
    #pragma unroll
    for (int q = 0; q < 4; q++) {
        int k = stp[q];
        if (k < 16) yb[(size_t)k * 1024] = make_float2(u1[q] + u2[q], u3[q] - u4[q]);
        yb[(size_t)(32 - k) * 1024] = make_float2(u1[q] - u2[q], u3[q] + u4[q]);
    }
    if (ug == 3) yb[0] = make_float2(sx, sy);
}

// ---------------- K3a: first channel mix (ffma2 + float4 Y) ----------------
__global__ __launch_bounds__(256) void k3a_mix1() {
    __shared__ float4 Ys4[16 * 64];  // {yr, yi, -yi, yr}
    __shared__ float2 Was[64 * 64];
    int blk = blockIdx.x, s = blk & 31, lx = s & 15, t = threadIdx.x;
    const float2* wt = (s < 16) ? gW0t : gW2t;
    for (int e = t; e < 1024; e += 256) {
        float2 y = gY[(size_t)blk * 1024 + e];
        Ys4[e] = make_float4(y.x, y.y, -y.y, y.x);
    }
    for (int e = t; e < 4096; e += 256) Was[e] = wt[lx * 4096 + e];
    __syncthreads();
    int j = t & 63, kg = t >> 6;
    ull acc[4];
    #pragma unroll
    for (int q = 0; q < 4; q++) acc[q] = 0ull;
    for (int ii = 0; ii < 64; ii++) {
        float2 wv = Was[ii * 64 + j];
        ull wr2 = pack2(wv.x, wv.x), wi2 = pack2(wv.y, wv.y);
        #pragma unroll
        for (int q = 0; q < 4; q++) {
            const ull* y2 = (const ull*)&Ys4[(kg * 4 + q) * 64 + ii];
            ffma2(acc[q], wr2, y2[0]);
            ffma2(acc[q], wi2, y2[1]);
        }
    }
    #pragma unroll
    for (int q = 0; q < 4; q++) {
        float re, im;
        unpack2(acc[q], re, im);
        gT[(size_t)blk * 1024 + (kg * 4 + q) * 64 + j] = make_float2(re, im);
    }
}

// ---------------- K3b: second channel mix ----------------
__global__ __launch_bounds__(256) void k3b_mix2() {
    extern __shared__ float2 sm2b[];
    float2* Ts = sm2b;
    float2* Wb0 = sm2b + 2048;
    float2* Wb1 = Wb0 + 4096;
    int blk = blockIdx.x, b = blk >> 4, ky = blk & 15, t = threadIdx.x;
    for (int e = t; e < 2048; e += 256) {
        int s_ = e >> 6, j = e & 63;
        Ts[e] = gT[(((size_t)b * 32 + s_) * 16 + ky) * 64 + j];
    }
    for (int e = t; e < 4096; e += 256) {
        Wb0[e] = gW1t[ky * 4096 + e];
        Wb1[e] = gW3t[ky * 4096 + e];
    }
    __syncthreads();
    int o = t & 63, sg = t >> 6;
    const float2* Wb = (sg < 2) ? Wb0 : Wb1;
    float2 acc[8];
    #pragma unroll
    for (int q = 0; q < 8; q++) acc[q] = make_float2(0.f, 0.f);
    for (int j = 0; j < 64; j++) {
        float2 wv = Wb[j * 64 + o];
        #pragma unroll
        for (int q = 0; q < 8; q++) {
            float2 tv = Ts[(sg * 8 + q) * 64 + j];
            acc[q].x += tv.x * wv.x - tv.y * wv.y;
            acc[q].y += tv.x * wv.y + tv.y * wv.x;
        }
    }
    #pragma unroll
    for (int q = 0; q < 8; q++) {
        int s_ = sg * 8 + q;
        gF[(size_t)blk * 2048 + s_ * 64 + o] = acc[q];
    }
}

// ---------------- K4: inverse DFT over kx (paired, reg-hoisted P/Q) ----------------
__global__ __launch_bounds__(256) void k4_invkx() {
    __shared__ float2 Fs[32 * 64];
    __shared__ float4 PQ[16 * 64];  // [0]=special F16 pack, [k]={P.re,P.im,-Q.im,Q.re}
    __shared__ float2 tab[128];
    int blk = blockIdx.x, b = blk >> 4, ky = blk & 15, t = threadIdx.x;
    for (int e = t; e < 2048; e += 256) Fs[e] = gF[(size_t)blk * 2048 + e];
    if (t < 128) {
        float sv, cv;
        sincospif((float)t * (1.0f / 64.0f), &sv, &cv);
        tab[t] = make_float2(cv, sv);
    }
    __syncthreads();
    for (int e = t; e < 1024; e += 256) {
        int k = e >> 6, o = e & 63;
        if (k == 0) {
            float2 f = Fs[16 * 64 + o];  // kx = -16
            PQ[o] = make_float4(f.x, f.y, f.y, -f.x);
        } else {
            float2 fa = Fs[k * 64 + o], fb = Fs[(32 - k) * 64 + o];
            PQ[k * 64 + o] = make_float4(fa.x + fb.x, fa.y + fb.y, -(fa.y - fb.y), fa.x - fb.x);
        }
    }
    __syncthreads();

    int o = t & 63, ug = t >> 6;
    float2 F0 = Fs[o];
    float4 pq[16];
    #pragma unroll
    for (int k = 0; k < 16; k++) pq[k] = PQ[k * 64 + o];

    for (int q = 0; q < 32; q++) {
        int u = ug * 32 + q;
        ull acc = pack2(F0.x, F0.y);
        int idx = u;
        #pragma unroll
        for (int k = 1; k < 16; k++) {
            float2 cs = tab[idx];
            ffma2(acc, pack2(cs.x, cs.x), ((const ull*)&pq[k])[0]);
            ffma2(acc, pack2(cs.y, cs.y), ((const ull*)&pq[k])[1]);
            idx = (idx + u) & 127;
        }
        {
            float2 cs = tab[(16 * u) & 127];
            ffma2(acc, pack2(cs.x, cs.x), ((const ull*)&pq[0])[0]);
            ffma2(acc, pack2(cs.y, cs.y), ((const ull*)&pq[0])[1]);
        }
        float re, im;
        unpack2(acc, re, im);
        gD[(((size_t)b * 128 + u) * 16 + ky) * 64 + o] = make_float2(re, im);
    }
}

// ---------------- K5: inverse ky + both MLPs via mma.sync ----------------
#define OFF_XHI   0u
#define OFF_XLO   18432u
#define OFF_W1HI  36864u
#define OFF_W1LO  55296u
#define OFF_W2HI  73728u
#define OFF_W2LO  91136u
#define OFF_HHI   108544u
#define OFF_HLO   143360u
#define OFF_B1    178176u
#define OFF_B2    178688u
#define SMEM_K5   178944

__global__ __launch_bounds__(256, 1) void k5_mma(
    const float* __restrict__ bb1, const float* __restrict__ bb2,
    const float* __restrict__ fb1, const float* __restrict__ fb2,
    float* __restrict__ out) {
    extern __shared__ __align__(16) char sm[];
    unsigned sb = smem_u32(sm);
    int t = threadIdx.x, w = t >> 5, l = t & 31;
    int blk = blockIdx.x;

    // ---- stage 1 scratch (aliases H region): E2 (32KB) + Dp (8KB)
    float2* E2 = (float2*)(sm + OFF_HHI);
    float* Dp = (float*)(sm + OFF_HHI + 32768);
    for (int e = t; e < 2048; e += 256)
        ((float4*)E2)[e] = ((const float4*)gE2)[e];
    for (int e = t; e < 1024; e += 256) {
        int ky = e >> 6, o = e & 63;
        float2 d = gD[(size_t)blk * 1024 + e];
        float sc = (ky ? 2.0f : 1.0f) * (1.0f / 16384.0f);
        Dp[(2 * ky) * 64 + o] = d.x * sc;
        Dp[(2 * ky + 1) * 64 + o] = -d.y * sc;
    }
    __syncthreads();

    // xo = E @ Dp (128x64, K=32) -> bf16 hi/lo A operand (144B rows)
    {
        int rg = t >> 4, cg = t & 15;
        int r0 = rg * 8, c0 = cg * 4;
        ull acc[8][2];
        #pragma unroll
        for (int j = 0; j < 8; j++) { acc[j][0] = 0ull; acc[j][1] = 0ull; }
        const ull* E2u = (const ull*)E2;
        for (int c = 0; c < 32; c++) {
            ulonglong2 dd = *(const ulonglong2*)&Dp[c * 64 + c0];
            #pragma unroll
            for (int j = 0; j < 8; j++) {
                ull e2 = E2u[(r0 + j) * 32 + c];
                ffma2(acc[j][0], e2, dd.x);
                ffma2(acc[j][1], e2, dd.y);
            }
        }
        #pragma unroll
        for (int j = 0; j < 8; j++) {
            float x0, x1, x2, x3;
            unpack2(acc[j][0], x0, x1);
            unpack2(acc[j][1], x2, x3);
            unsigned hA, lA, hB, lB;
            split2(x0, x1, hA, lA);
            split2(x2, x3, hB, lB);
            unsigned relb = (unsigned)(r0 + j) * 144u + (unsigned)c0 * 2u;
            *(uint2*)(sm + OFF_XHI + relb) = make_uint2(hA, hB);
            *(uint2*)(sm + OFF_XLO + relb) = make_uint2(lA, lB);
        }
    }

    size_t rowBase = (size_t)blk * 128;

    for (int p = 0; p < 2; p++) {
        __syncthreads();
        // ---- stage weights + biases
        {
            const uint4* s0 = (const uint4*)gW1T[p][0];
            const uint4* s1 = (const uint4*)gW1T[p][1];
            const uint4* s2 = (const uint4*)gW2T[p][0];
            const uint4* s3 = (const uint4*)gW2T[p][1];
            uint4* d0 = (uint4*)(sm + OFF_W1HI);
            uint4* d1 = (uint4*)(sm + OFF_W1LO);
            uint4* d2 = (uint4*)(sm + OFF_W2HI);
            uint4* d3 = (uint4*)(sm + OFF_W2LO);
            for (int e = t; e < 1152; e += 256) { d0[e] = s0[e]; d1[e] = s1[e]; }
            for (int e = t; e < 1088; e += 256) { d2[e] = s2[e]; d3[e] = s3[e]; }
            if (t < 128) ((float*)(sm + OFF_B1))[t] = p ? fb1[t] : bb1[t];
            if (t < 64) ((float*)(sm + OFF_B2))[t] = p ? fb2[t] : bb2[t];
        }
        __syncthreads();

        int wm = w & 1, wn = w >> 1;
        unsigned kA = ((l >> 4) & 1) * 8;
        unsigned kB = ((l >> 3) & 1) * 8;
        unsigned rowA = (unsigned)(wm * 64 + (l & 7) + ((l >> 3) & 1) * 8);

        // ---- GEMM1: C1[128,128] = X @ W1 (3-term bf16 split)
        {
            float acc[4][4][4];
            #pragma unroll
            for (int a = 0; a < 4; a++)
                #pragma unroll
                for (int b = 0; b < 4; b++)
                    #pragma unroll
                    for (int c = 0; c < 4; c++) acc[a][b][c] = 0.f;

            unsigned rowB = (unsigned)(wn * 32 + ((l >> 4) << 3) + (l & 7));
            unsigned aXhi = sb + OFF_XHI + rowA * 144 + kA * 2;
            unsigned aXlo = sb + OFF_XLO + rowA * 144 + kA * 2;
            unsigned aBhi = sb + OFF_W1HI + rowB * 144 + kB * 2;
            unsigned aBlo = sb + OFF_W1LO + rowB * 144 + kB * 2;

            #pragma unroll
            for (int ki = 0; ki < 4; ki++) {
                unsigned kb = ki * 32;
                unsigned ah[4][4], al[4][4], bh[2][4], bl[2][4];
                #pragma unroll
                for (int mf = 0; mf < 4; mf++) {
                    ldm4(ah[mf], aXhi + mf * (16 * 144) + kb);
                    ldm4(al[mf], aXlo + mf * (16 * 144) + kb);
                }
                #pragma unroll
                for (int h2 = 0; h2 < 2; h2++) {
                    ldm4(bh[h2], aBhi + h2 * (16 * 144) + kb);
                    ldm4(bl[h2], aBlo + h2 * (16 * 144) + kb);
                }
                #pragma unroll
                for (int mf = 0; mf < 4; mf++)
                    #pragma unroll
                    for (int nf = 0; nf < 4; nf++) {
                        const unsigned* bph = &bh[nf >> 1][(nf & 1) * 2];
                        const unsigned* bpl = &bl[nf >> 1][(nf & 1) * 2];
                        mma16816(acc[mf][nf], ah[mf], bph);
                        mma16816(acc[mf][nf], ah[mf], bpl);
                        mma16816(acc[mf][nf], al[mf], bph);
                    }
            }
            // epilogue 1: bias + relu + split -> H (272B rows)
            const float* b1s = (const float*)(sm + OFF_B1);
            int rbase = wm * 64 + (l >> 2);
            int ncol = 2 * (l & 3);
            #pragma unroll
            for (int mf = 0; mf < 4; mf++)
                #pragma unroll
                for (int nf = 0; nf < 4; nf++) {
                    int n = wn * 32 + nf * 8 + ncol;
                    float bv0 = b1s[n], bv1 = b1s[n + 1];
                    #pragma unroll
                    for (int half = 0; half < 2; half++) {
                        int r = rbase + mf * 16 + half * 8;
                        float v0 = fmaxf(acc[mf][nf][half * 2 + 0] + bv0, 0.f);
                        float v1 = fmaxf(acc[mf][nf][half * 2 + 1] + bv1, 0.f);
                        unsigned hp, lp;
                        split2(v0, v1, hp, lp);
                        unsigned off = (unsigned)r * 272u + (unsigned)n * 2u;
                        *(unsigned*)(sm + OFF_HHI + off) = hp;
                        *(unsigned*)(sm + OFF_HLO + off) = lp;
                    }
                }
        }
        __syncthreads();

        // ---- GEMM2: C2[128,64] = H @ W2 (3-term bf16 split)
        {
            float acc[4][2][4];
            #pragma unroll
            for (int a = 0; a < 4; a++)
                #pragma unroll
                for (int b = 0; b < 2; b++)
                    #pragma unroll
                    for (int c = 0; c < 4; c++) acc[a][b][c] = 0.f;

            unsigned rowB = (unsigned)(wn * 16 + ((l >> 4) << 3) + (l & 7));
            unsigned aHhi = sb + OFF_HHI + rowA * 272 + kA * 2;
            unsigned aHlo = sb + OFF_HLO + rowA * 272 + kA * 2;
            unsigned aChi = sb + OFF_W2HI + rowB * 272 + kB * 2;
            unsigned aClo = sb + OFF_W2LO + rowB * 272 + kB * 2;

            #pragma unroll
            for (int ki = 0; ki < 8; ki++) {
                unsigned kb = ki * 32;
                unsigned ah[4][4], al[4][4], bh[4], bl[4];
                #pragma unroll
                for (int mf = 0; mf < 4; mf++) {
                    ldm4(ah[mf], aHhi + mf * (16 * 272) + kb);
                    ldm4(al[mf], aHlo + mf * (16 * 272) + kb);
                }
                ldm4(bh, aChi + kb);
                ldm4(bl, aClo + kb);
                #pragma unroll
                for (int mf = 0; mf < 4; mf++)
                    #pragma unroll
                    for (int nf = 0; nf < 2; nf++) {
                        const unsigned* bph = &bh[nf * 2];
                        const unsigned* bpl = &bl[nf * 2];
                        mma16816(acc[mf][nf], ah[mf], bph);
                        mma16816(acc[mf][nf], ah[mf], bpl);
                        mma16816(acc[mf][nf], al[mf], bph);
                    }
            }
            // epilogue 2: bias + store to global
            const float* b2s = (const float*)(sm + OFF_B2);
            float* outp = out + (size_t)p * 33554432ull + rowBase * 64;
            int rbase = wm * 64 + (l >> 2);
            int ncol = 2 * (l & 3);
            #pragma unroll
            for (int mf = 0; mf < 4; mf++)
                #pragma unroll
                for (int nf = 0; nf < 2; nf++) {
                    int n = wn * 16 + nf * 8 + ncol;
                    float bv0 = b2s[n], bv1 = b2s[n + 1];
                    #pragma unroll
                    for (int half = 0; half < 2; half++) {
                        int r = rbase + mf * 16 + half * 8;
                        float2 val = make_float2(acc[mf][nf][half * 2 + 0] + bv0,
                                                 acc[mf][nf][half * 2 + 1] + bv1);
                        *(float2*)(outp + (size_t)r * 64 + n) = val;
                    }
                }
        }
    }
}

// ---------------------------------------------------------------------------
extern "C" void kernel_launch(void* const* d_in, const int* in_sizes, int n_in,
                              void* d_out, int out_size) {
    const float* x = (const float*)d_in[0];
    const float* w0 = (const float*)d_in[1];
    const float* w1 = (const float*)d_in[2];
    const float* w2 = (const float*)d_in[3];
    const float* w3 = (const float*)d_in[4];
    const float* bw1 = (const float*)d_in[5];
    const float* bb1 = (const float*)d_in[6];
    const float* bw2 = (const float*)d_in[7];
    const float* bb2 = (const float*)d_in[8];
    const float* fw1 = (const float*)d_in[9];
    const float* fb1 = (const float*)d_in[10];
    const float* fw2 = (const float*)d_in[11];
    const float* fb2 = (const float*)d_in[12];
    float* out = (float*)d_out;

    const int SM_K1 = 66048;
    const int SM_K2 = (128 * 64 + 128) * 8;
    const int SM_K3B = (2048 + 4096 + 4096) * 8;
    cudaFuncSetAttribute(k1_stageA, cudaFuncAttributeMaxDynamicSharedMemorySize, SM_K1);
    cudaFuncSetAttribute(k2_stageB, cudaFuncAttributeMaxDynamicSharedMemorySize, SM_K2);
    cudaFuncSetAttribute(k3b_mix2, cudaFuncAttributeMaxDynamicSharedMemorySize, SM_K3B);
    cudaFuncSetAttribute(k5_mma, cudaFuncAttributeMaxDynamicSharedMemorySize, SMEM_K5);

    prep_mlp<<<140, 256>>>(bw1, fw1, bw2, fw2);
    prep_spec<<<256, 256>>>(w0, w1, w2, w3);
    prep_e<<<16, 256>>>();
    k1_stageA<<<NB * 128, 256, SM_K1>>>(x);
    k2_stageB<<<NB * 16, 256, SM_K2>>>();
    k3a_mix1<<<NB * 32, 256>>>();
    k3b_mix2<<<NB * 16, 256, SM_K3B>>>();
    k4_invkx<<<NB * 16, 256>>>();
    k5_mma<<<NB * 128, 256, SMEM_K5>>>(bb1, bb2, fb1, fb2, out);
}

// round 10
// speedup vs baseline: 2.3661x; 1.0047x over previous
#include <cuda_runtime.h>
#include <cuda_bf16.h>
#include <math.h>

#define NB 32

// ---------------- device globals ----------------
__device__ float2 gA[NB * 128 * 16 * 64];
__device__ float2 gY[NB * 32 * 16 * 64];
__device__ float2 gT[NB * 32 * 16 * 64];
__device__ float2 gF[NB * 16 * 32 * 64];
__device__ float2 gD[NB * 128 * 16 * 64];
// padded bf16 hi/lo weight images: W1^T [n=128][k pad 72], W2^T [n=64][k pad 136]
__device__ __align__(16) unsigned short gW1T[2][2][128 * 72];
__device__ __align__(16) unsigned short gW2T[2][2][64 * 136];
// transposed spectral weights
__device__ float2 gW0t[65536], gW1t[65536], gW2t[65536], gW3t[65536];
// duplicated inverse-ky basis: E2[v*32+c] = {e,e}
__device__ __align__(16) float2 gE2[4096];
// linear twiddle tables: k1 [ky][n] {cos,-sin}; k2 [k-1][m] {cos,sin}
__device__ __align__(16) float2 gTwK1[16 * 64];
__device__ __align__(16) float2 gTw2[16 * 128];

// ---------------- helpers ----------------
typedef unsigned long long ull;
__device__ __forceinline__ ull pack2(float lo, float hi) {
    ull r;
    asm("mov.b64 %0, {%1,%2};" : "=l"(r) : "f"(lo), "f"(hi));
    return r;
}
__device__ __forceinline__ void unpack2(ull v, float& lo, float& hi) {
    asm("mov.b64 {%0,%1}, %2;" : "=f"(lo), "=f"(hi) : "l"(v));
}
__device__ __forceinline__ void ffma2(ull& d, ull a, ull b) {
    asm("fma.rn.f32x2 %0, %1, %2, %0;" : "+l"(d) : "l"(a), "l"(b));
}
__device__ __forceinline__ unsigned smem_u32(const void* p) {
    unsigned a;
    asm("{ .reg .u64 t; cvta.to.shared.u64 t, %1; cvt.u32.u64 %0, t; }" : "=r"(a) : "l"(p));
    return a;
}
__device__ __forceinline__ void ldm4(unsigned* r, unsigned addr) {
    asm volatile("ldmatrix.sync.aligned.m8n8.x4.shared.b16 {%0,%1,%2,%3}, [%4];"
                 : "=r"(r[0]), "=r"(r[1]), "=r"(r[2]), "=r"(r[3]) : "r"(addr));
}
__device__ __forceinline__ void mma16816(float* c, const unsigned* a, const unsigned* b) {
    asm volatile("mma.sync.aligned.m16n8k16.row.col.f32.bf16.bf16.f32 "
                 "{%0,%1,%2,%3}, {%4,%5,%6,%7}, {%8,%9}, {%0,%1,%2,%3};"
                 : "+f"(c[0]), "+f"(c[1]), "+f"(c[2]), "+f"(c[3])
                 : "r"(a[0]), "r"(a[1]), "r"(a[2]), "r"(a[3]), "r"(b[0]), "r"(b[1]));
}
// packed split: v0,v1 -> bf16x2 hi image + bf16x2 residual image
__device__ __forceinline__ void split2(float v0, float v1, unsigned& hp, unsigned& lp) {
    asm("cvt.rn.bf16x2.f32 %0, %1, %2;" : "=r"(hp) : "f"(v1), "f"(v0));
    float h0 = __uint_as_float(hp << 16);
    float h1 = __uint_as_float(hp & 0xFFFF0000u);
    float l0 = v0 - h0, l1 = v1 - h1;
    asm("cvt.rn.bf16x2.f32 %0, %1, %2;" : "=r"(lp) : "f"(l1), "f"(l0));
}

// ---------------- prep: split+pad MLP weights ----------------
__global__ void prep_mlp(const float* __restrict__ bw1, const float* __restrict__ fw1,
                         const float* __restrict__ bw2, const float* __restrict__ fw2) {
    int tid = blockIdx.x * 256 + threadIdx.x;
    if (tid < 18432) {  // W1^T: [2][128 n][72 k]
        int p = tid / 9216, rem = tid % 9216;
        int n = rem / 72, k = rem % 72;
        const float* W1 = p ? fw1 : bw1;
        float v = (k < 64) ? W1[k * 128 + n] : 0.f;
        __nv_bfloat16 hi = __float2bfloat16(v);
        __nv_bfloat16 lo = __float2bfloat16(v - __bfloat162float(hi));
        gW1T[p][0][n * 72 + k] = __bfloat16_as_ushort(hi);
        gW1T[p][1][n * 72 + k] = __bfloat16_as_ushort(lo);
    } else if (tid < 35840) {  // W2^T: [2][64 n][136 k]
        int t2 = tid - 18432;
        int p = t2 / 8704, rem = t2 % 8704;
        int n = rem / 136, k = rem % 136;
        const float* W2 = p ? fw2 : bw2;
        float v = (k < 128) ? W2[k * 64 + n] : 0.f;
        __nv_bfloat16 hi = __float2bfloat16(v);
        __nv_bfloat16 lo = __float2bfloat16(v - __bfloat162float(hi));
        gW2T[p][0][n * 136 + k] = __bfloat16_as_ushort(hi);
        gW2T[p][1][n * 136 + k] = __bfloat16_as_ushort(lo);
    }
}

// ---------------- prep: transpose spectral weights ----------------
__global__ void prep_spec(const float* __restrict__ w0, const float* __restrict__ w1,
                          const float* __restrict__ w2, const float* __restrict__ w3) {
    int e = blockIdx.x * 256 + threadIdx.x;
    int lx = e >> 12, ij = e & 4095;
    int src = ij * 16 + lx;
    gW0t[e] = ((const float2*)w0)[src];
    gW1t[e] = ((const float2*)w1)[src];
    gW2t[e] = ((const float2*)w2)[src];
    gW3t[e] = ((const float2*)w3)[src];
}

// ---------------- prep: E table + linear twiddle tables ----------------
__global__ void prep_e() {
    int e = blockIdx.x * 256 + threadIdx.x;  // 0..8191
    if (e < 4096) {
        int v = e >> 5, c = e & 31, k = c >> 1;
        float sv, cv;
        sincospif((float)(v * k) * (1.0f / 64.0f), &sv, &cv);
        float val = (c & 1) ? sv : cv;
        gE2[e] = make_float2(val, val);
    } else if (e < 5120) {  // gTwK1[ky*64+n]
        int e2 = e - 4096;
        int ky = e2 >> 6, n = e2 & 63;
        float sv, cv;
        sincospif((float)(ky * n) * (1.0f / 64.0f), &sv, &cv);
        gTwK1[e2] = make_float2(cv, -sv);
    } else if (e < 7168) {  // gTw2[(k-1)*128+m]
        int e2 = e - 5120;
        int k = (e2 >> 7) + 1, m = e2 & 127;
        float sv, cv;
        sincospif((float)(k * m) * (1.0f / 64.0f), &sv, &cv);
        gTw2[e2] = make_float2(cv, sv);
    }
}

// ---------------- K1: forward DFT along n (folded, linear tables) ----------------
// dyn smem: xs[8192]f (32KB), sd[4032]f2 (32256B), twk[1024]f2 (8KB) = 73216 B
__global__ __launch_bounds__(256) void k1_stageA(const float* __restrict__ x) {
    extern __shared__ float smf[];
    float* xs = smf;
    float2* sd = (float2*)(smf + 8192);
    float2* twk = (float2*)(smf + 8192 + 8064);
    int bm = blockIdx.x, t = threadIdx.x;
    const float4* src = (const float4*)(x + (size_t)bm * (128 * 64));
    float4* d4 = (float4*)xs;
    #pragma unroll
    for (int e = t; e < 2048; e += 256) d4[e] = src[e];
    #pragma unroll
    for (int e = t; e < 512; e += 256) ((float4*)twk)[e] = ((const float4*)gTwK1)[e];
    __syncthreads();
    // fold: sd[(n-1)*64+i] = {x_n + x_{128-n}, x_n - x_{128-n}}
    for (int e = t; e < 4032; e += 256) {
        int n = (e >> 6) + 1, i = e & 63;
        float a = xs[n * 64 + i], b = xs[(128 - n) * 64 + i];
        sd[e] = make_float2(a + b, a - b);
    }
    __syncthreads();

    int i = t & 63, kg = t >> 6;
    int ky0 = kg * 4;
    float x0 = xs[i], x64 = xs[4096 + i];
    const ull* sd2 = (const ull*)sd + i;
    const ull* tw0 = (const ull*)twk + (ky0 + 0) * 64;
    const ull* tw1 = (const ull*)twk + (ky0 + 1) * 64;
    const ull* tw2 = (const ull*)twk + (ky0 + 2) * 64;
    const ull* tw3 = (const ull*)twk + (ky0 + 3) * 64;
    ull a0 = pack2(x0 + (((ky0 + 0) & 1) ? -x64 : x64), 0.f);
    ull a1 = pack2(x0 + (((ky0 + 1) & 1) ? -x64 : x64), 0.f);
    ull a2 = pack2(x0 + (((ky0 + 2) & 1) ? -x64 : x64), 0.f);
    ull a3 = pack2(x0 + (((ky0 + 3) & 1) ? -x64 : x64), 0.f);
    #pragma unroll
    for (int n = 1; n <= 63; n++) {
        ull sdv = sd2[(n - 1) * 64];
        ffma2(a0, sdv, tw0[n]);
        ffma2(a1, sdv, tw1[n]);
        ffma2(a2, sdv, tw2[n]);
        ffma2(a3, sdv, tw3[n]);
    }
    float2* outp = gA + (size_t)bm * (16 * 64);
    float lo, hi;
    unpack2(a0, lo, hi); outp[(ky0 + 0) * 64 + i] = make_float2(lo, hi);
    unpack2(a1, lo, hi); outp[(ky0 + 1) * 64 + i] = make_float2(lo, hi);
    unpack2(a2, lo, hi); outp[(ky0 + 2) * 64 + i] = make_float2(lo, hi);
    unpack2(a3, lo, hi); outp[(ky0 + 3) * 64 + i] = make_float2(lo, hi);
}

// ---------------- K2: forward DFT along m (paired, packed, linear tables) ----------------
// dyn smem: As 64KB + tw 16KB = 81920 B
__global__ __launch_bounds__(256) void k2_stageB() {
    extern __shared__ float2 sm2[];
    float2* As = sm2;               // 8192
    float2* tw = sm2 + 8192;        // 2048: [k-1][m]
    int blk = blockIdx.x, b = blk >> 4, ky = blk & 15, t = threadIdx.x;
    for (int e = t; e < 8192; e += 256) {
        int m = e >> 6, i = e & 63;
        As[e] = gA[(((size_t)b * 128 + m) * 16 + ky) * 64 + i];
    }
    #pragma unroll
    for (int e = t; e < 1024; e += 256) ((float4*)tw)[e] = ((const float4*)gTw2)[e];
    __syncthreads();

    int i = t & 63, ug = t >> 6;
    ull acc12[4], acc34[4];
    const ull* twu[4];
    #pragma unroll
    for (int q = 0; q < 4; q++) {
        acc12[q] = 0ull; acc34[q] = 0ull;
        twu[q] = (const ull*)tw + (ug * 4 + q) * 128;
    }
    float sx = 0.f, sy = 0.f;
    #pragma unroll 4
    for (int m = 0; m < 128; m++) {
        float2 a = As[m * 64 + i];
        ull axy = pack2(a.x, a.y), ayx = pack2(a.y, a.x);
        #pragma unroll
        for (int q = 0; q < 4; q++) {
            ull tv = twu[q][m];
            ffma2(acc12[q], axy, tv);
            ffma2(acc34[q], ayx, tv);
        }
        if (ug == 3) { sx += a.x; sy += a.y; }
    }
    float2* yb = gY + (((size_t)b * 32) * 16 + ky) * 64 + i;
    #pragma unroll
    for (int q = 0; q < 4; q++) {
        int k = ug * 4 + q + 1;
        float u1, u2, u3, u4;
        unpack2(acc12[q], u1, u2);
        unpack2(acc34[q], u3, u4);
        if (k < 16) yb[(size_t)k * 1024] = make_float2(u1 + u2, u3 - u4);
        yb[(size_t)(32 - k) * 1024] = make_float2(u1 - u2, u3 + u4);
    }
    if (ug == 3) yb[0] = make_float2(sx, sy);
}

// ---------------- K3a: first channel mix (ffma2 + float4 Y) ----------------
__global__ __launch_bounds__(256) void k3a_mix1() {
    __shared__ float4 Ys4[16 * 64];  // {yr, yi, -yi, yr}
    __shared__ float2 Was[64 * 64];
    int blk = blockIdx.x, s = blk & 31, lx = s & 15, t = threadIdx.x;
    const float2* wt = (s < 16) ? gW0t : gW2t;
    for (int e = t; e < 1024; e += 256) {
        float2 y = gY[(size_t)blk * 1024 + e];
        Ys4[e] = make_float4(y.x, y.y, -y.y, y.x);
    }
    for (int e = t; e < 4096; e += 256) Was[e] = wt[lx * 4096 + e];
    __syncthreads();
    int j = t & 63, kg = t >> 6;
    ull acc[4];
    #pragma unroll
    for (int q = 0; q < 4; q++) acc[q] = 0ull;
    for (int ii = 0; ii < 64; ii++) {
        float2 wv = Was[ii * 64 + j];
        ull wr2 = pack2(wv.x, wv.x), wi2 = pack2(wv.y, wv.y);
        #pragma unroll
        for (int q = 0; q < 4; q++) {
            const ull* y2 = (const ull*)&Ys4[(kg * 4 + q) * 64 + ii];
            ffma2(acc[q], wr2, y2[0]);
            ffma2(acc[q], wi2, y2[1]);
        }
    }
    #pragma unroll
    for (int q = 0; q < 4; q++) {
        float re, im;
        unpack2(acc[q], re, im);
        gT[(size_t)blk * 1024 + (kg * 4 + q) * 64 + j] = make_float2(re, im);
    }
}

// ---------------- K3b: second channel mix ----------------
__global__ __launch_bounds__(256) void k3b_mix2() {
    extern __shared__ float2 sm2b[];
    float2* Ts = sm2b;
    float2* Wb0 = sm2b + 2048;
    float2* Wb1 = Wb0 + 4096;
    int blk = blockIdx.x, b = blk >> 4, ky = blk & 15, t = threadIdx.x;
    for (int e = t; e < 2048; e += 256) {
        int s_ = e >> 6, j = e & 63;
        Ts[e] = gT[(((size_t)b * 32 + s_) * 16 + ky) * 64 + j];
    }
    for (int e = t; e < 4096; e += 256) {
        Wb0[e] = gW1t[ky * 4096 + e];
        Wb1[e] = gW3t[ky * 4096 + e];
    }
    __syncthreads();
    int o = t & 63, sg = t >> 6;
    const float2* Wb = (sg < 2) ? Wb0 : Wb1;
    float2 acc[8];
    #pragma unroll
    for (int q = 0; q < 8; q++) acc[q] = make_float2(0.f, 0.f);
    for (int j = 0; j < 64; j++) {
        float2 wv = Wb[j * 64 + o];
        #pragma unroll
        for (int q = 0; q < 8; q++) {
            float2 tv = Ts[(sg * 8 + q) * 64 + j];
            acc[q].x += tv.x * wv.x - tv.y * wv.y;
            acc[q].y += tv.x * wv.y + tv.y * wv.x;
        }
    }
    #pragma unroll
    for (int q = 0; q < 8; q++) {
        int s_ = sg * 8 + q;
        gF[(size_t)blk * 2048 + s_ * 64 + o] = acc[q];
    }
}

// ---------------- K4: inverse DFT over kx (paired, {c,c,s,s} tab) ----------------
__global__ __launch_bounds__(256) void k4_invkx() {
    __shared__ float2 Fs[32 * 64];
    __shared__ float4 PQ[16 * 64];   // [0]=F(-16) pack, [k]={P.re,P.im,-Q.im,Q.re}
    __shared__ float4 tab4[128];     // {c,c,s,s}
    int blk = blockIdx.x, b = blk >> 4, ky = blk & 15, t = threadIdx.x;
    for (int e = t; e < 2048; e += 256) Fs[e] = gF[(size_t)blk * 2048 + e];
    if (t < 128) {
        float sv, cv;
        sincospif((float)t * (1.0f / 64.0f), &sv, &cv);
        tab4[t] = make_float4(cv, cv, sv, sv);
    }
    __syncthreads();
    for (int e = t; e < 1024; e += 256) {
        int k = e >> 6, o = e & 63;
        if (k == 0) {
            float2 f = Fs[16 * 64 + o];  // kx = -16
            PQ[o] = make_float4(f.x, f.y, f.y, -f.x);
        } else {
            float2 fa = Fs[k * 64 + o], fb = Fs[(32 - k) * 64 + o];
            PQ[k * 64 + o] = make_float4(fa.x + fb.x, fa.y + fb.y, -(fa.y - fb.y), fa.x - fb.x);
        }
    }
    __syncthreads();

    int o = t & 63, ug = t >> 6;
    float2 F0 = Fs[o];
    float4 pq[16];
    #pragma unroll
    for (int k = 0; k < 16; k++) pq[k] = PQ[k * 64 + o];

    for (int q = 0; q < 32; q++) {
        int u = ug * 32 + q;
        ull acc = pack2(F0.x, F0.y);
        int idx = u;
        #pragma unroll
        for (int k = 1; k < 16; k++) {
            const ull* cs = (const ull*)&tab4[idx];
            ffma2(acc, cs[0], ((const ull*)&pq[k])[0]);
            ffma2(acc, cs[1], ((const ull*)&pq[k])[1]);
            idx = (idx + u) & 127;
        }
        {
            const ull* cs = (const ull*)&tab4[(16 * u) & 127];
            ffma2(acc, cs[0], ((const ull*)&pq[0])[0]);
            ffma2(acc, cs[1], ((const ull*)&pq[0])[1]);
        }
        float re, im;
        unpack2(acc, re, im);
        gD[(((size_t)b * 128 + u) * 16 + ky) * 64 + o] = make_float2(re, im);
    }
}

// ---------------- K5: inverse ky + both MLPs via mma.sync ----------------
#define OFF_XHI   0u
#define OFF_XLO   18432u
#define OFF_W1HI  36864u
#define OFF_W1LO  55296u
#define OFF_W2HI  73728u
#define OFF_W2LO  91136u
#define OFF_HHI   108544u
#define OFF_HLO   143360u
#define OFF_B1    178176u
#define OFF_B2    178688u
#define SMEM_K5   178944

__global__ __launch_bounds__(256, 1) void k5_mma(
    const float* __restrict__ bb1, const float* __restrict__ bb2,
    const float* __restrict__ fb1, const float* __restrict__ fb2,
    float* __restrict__ out) {
    extern __shared__ __align__(16) char sm[];
    unsigned sb = smem_u32(sm);
    int t = threadIdx.x, w = t >> 5, l = t & 31;
    int blk = blockIdx.x;

    // ---- stage 1 scratch (aliases H region): E2 (32KB) + Dp (8KB)
    float2* E2 = (float2*)(sm + OFF_HHI);
    float* Dp = (float*)(sm + OFF_HHI + 32768);
    for (int e = t; e < 2048; e += 256)
        ((float4*)E2)[e] = ((const float4*)gE2)[e];
    for (int e = t; e < 1024; e += 256) {
        int ky = e >> 6, o = e & 63;
        float2 d = gD[(size_t)blk * 1024 + e];
        float sc = (ky ? 2.0f : 1.0f) * (1.0f / 16384.0f);
        Dp[(2 * ky) * 64 + o] = d.x * sc;
        Dp[(2 * ky + 1) * 64 + o] = -d.y * sc;
    }
    __syncthreads();

    // xo = E @ Dp (128x64, K=32) -> bf16 hi/lo A operand (144B rows)
    {
        int rg = t >> 4, cg = t & 15;
        int r0 = rg * 8, c0 = cg * 4;
        ull acc[8][2];
        #pragma unroll
        for (int j = 0; j < 8; j++) { acc[j][0] = 0ull; acc[j][1] = 0ull; }
        const ull* E2u = (const ull*)E2;
        for (int c = 0; c < 32; c++) {
            ulonglong2 dd = *(const ulonglong2*)&Dp[c * 64 + c0];
            #pragma unroll
            for (int j = 0; j < 8; j++) {
                ull e2 = E2u[(r0 + j) * 32 + c];
                ffma2(acc[j][0], e2, dd.x);
                ffma2(acc[j][1], e2, dd.y);
            }
        }
        #pragma unroll
        for (int j = 0; j < 8; j++) {
            float x0, x1, x2, x3;
            unpack2(acc[j][0], x0, x1);
            unpack2(acc[j][1], x2, x3);
            unsigned hA, lA, hB, lB;
            split2(x0, x1, hA, lA);
            split2(x2, x3, hB, lB);
            unsigned relb = (unsigned)(r0 + j) * 144u + (unsigned)c0 * 2u;
            *(uint2*)(sm + OFF_XHI + relb) = make_uint2(hA, hB);
            *(uint2*)(sm + OFF_XLO + relb) = make_uint2(lA, lB);
        }
    }

    size_t rowBase = (size_t)blk * 128;

    for (int p = 0; p < 2; p++) {
        __syncthreads();
        // ---- stage weights + biases
        {
            const uint4* s0 = (const uint4*)gW1T[p][0];
            const uint4* s1 = (const uint4*)gW1T[p][1];
            const uint4* s2 = (const uint4*)gW2T[p][0];
            const uint4* s3 = (const uint4*)gW2T[p][1];
            uint4* d0 = (uint4*)(sm + OFF_W1HI);
            uint4* d1 = (uint4*)(sm + OFF_W1LO);
            uint4* d2 = (uint4*)(sm + OFF_W2HI);
            uint4* d3 = (uint4*)(sm + OFF_W2LO);
            for (int e = t; e < 1152; e += 256) { d0[e] = s0[e]; d1[e] = s1[e]; }
            for (int e = t; e < 1088; e += 256) { d2[e] = s2[e]; d3[e] = s3[e]; }
            if (t < 128) ((float*)(sm + OFF_B1))[t] = p ? fb1[t] : bb1[t];
            if (t < 64) ((float*)(sm + OFF_B2))[t] = p ? fb2[t] : bb2[t];
        }
        __syncthreads();

        int wm = w & 1, wn = w >> 1;
        unsigned kA = ((l >> 4) & 1) * 8;
        unsigned kB = ((l >> 3) & 1) * 8;
        unsigned rowA = (unsigned)(wm * 64 + (l & 7) + ((l >> 3) & 1) * 8);

        // ---- GEMM1: C1[128,128] = X @ W1 (3-term bf16 split, term-outer order)
        {
            float acc[4][4][4];
            #pragma unroll
            for (int a = 0; a < 4; a++)
                #pragma unroll
                for (int b = 0; b < 4; b++)
                    #pragma unroll
                    for (int c = 0; c < 4; c++) acc[a][b][c] = 0.f;

            unsigned rowB = (unsigned)(wn * 32 + ((l >> 4) << 3) + (l & 7));
            unsigned aXhi = sb + OFF_XHI + rowA * 144 + kA * 2;
            unsigned aXlo = sb + OFF_XLO + rowA * 144 + kA * 2;
            unsigned aBhi = sb + OFF_W1HI + rowB * 144 + kB * 2;
            unsigned aBlo = sb + OFF_W1LO + rowB * 144 + kB * 2;

            #pragma unroll
            for (int ki = 0; ki < 4; ki++) {
                unsigned kb = ki * 32;
                unsigned ah[4][4], al[4][4], bh[2][4], bl[2][4];
                #pragma unroll
                for (int mf = 0; mf < 4; mf++) {
                    ldm4(ah[mf], aXhi + mf * (16 * 144) + kb);
                    ldm4(al[mf], aXlo + mf * (16 * 144) + kb);
                }
                #pragma unroll
                for (int h2 = 0; h2 < 2; h2++) {
                    ldm4(bh[h2], aBhi + h2 * (16 * 144) + kb);
                    ldm4(bl[h2], aBlo + h2 * (16 * 144) + kb);
                }
                // term 0: hi*hi (16 independent MMAs)
                #pragma unroll
                for (int mf = 0; mf < 4; mf++)
                    #pragma unroll
                    for (int nf = 0; nf < 4; nf++)
                        mma16816(acc[mf][nf], ah[mf], &bh[nf >> 1][(nf & 1) * 2]);
                // term 1: hi*lo
                #pragma unroll
                for (int mf = 0; mf < 4; mf++)
                    #pragma unroll
                    for (int nf = 0; nf < 4; nf++)
                        mma16816(acc[mf][nf], ah[mf], &bl[nf >> 1][(nf & 1) * 2]);
                // term 2: lo*hi
                #pragma unroll
                for (int mf = 0; mf < 4; mf++)
                    #pragma unroll
                    for (int nf = 0; nf < 4; nf++)
                        mma16816(acc[mf][nf], al[mf], &bh[nf >> 1][(nf & 1) * 2]);
            }
            // epilogue 1: bias + relu + split -> H (272B rows)
            const float* b1s = (const float*)(sm + OFF_B1);
            int rbase = wm * 64 + (l >> 2);
            int ncol = 2 * (l & 3);
            #pragma unroll
            for (int mf = 0; mf < 4; mf++)
                #pragma unroll
                for (int nf = 0; nf < 4; nf++) {
                    int n = wn * 32 + nf * 8 + ncol;
                    float bv0 = b1s[n], bv1 = b1s[n + 1];
                    #pragma unroll
                    for (int half = 0; half < 2; half++) {
                        int r = rbase + mf * 16 + half * 8;
                        float v0 = fmaxf(acc[mf][nf][half * 2 + 0] + bv0, 0.f);
                        float v1 = fmaxf(acc[mf][nf][half * 2 + 1] + bv1, 0.f);
                        unsigned hp, lp;
                        split2(v0, v1, hp, lp);
                        unsigned off = (unsigned)r * 272u + (unsigned)n * 2u;
                        *(unsigned*)(sm + OFF_HHI + off) = hp;
                        *(unsigned*)(sm + OFF_HLO + off) = lp;
                    }
                }
        }
        __syncthreads();

        // ---- GEMM2: C2[128,64] = H @ W2 (3-term bf16 split, term-outer order)
        {
            float acc[4][2][4];
            #pragma unroll
            for (int a = 0; a < 4; a++)
                #pragma unroll
                for (int b = 0; b < 2; b++)
                    #pragma unroll
                    for (int c = 0; c < 4; c++) acc[a][b][c] = 0.f;

            unsigned rowB = (unsigned)(wn * 16 + ((l >> 4) << 3) + (l & 7));
            unsigned aHhi = sb + OFF_HHI + rowA * 272 + kA * 2;
            unsigned aHlo = sb + OFF_HLO + rowA * 272 + kA * 2;
            unsigned aChi = sb + OFF_W2HI + rowB * 272 + kB * 2;
            unsigned aClo = sb + OFF_W2LO + rowB * 272 + kB * 2;

            #pragma unroll
            for (int ki = 0; ki < 8; ki++) {
                unsigned kb = ki * 32;
                unsigned ah[4][4], al[4][4], bh[4], bl[4];
                #pragma unroll
                for (int mf = 0; mf < 4; mf++) {
                    ldm4(ah[mf], aHhi + mf * (16 * 272) + kb);
                    ldm4(al[mf], aHlo + mf * (16 * 272) + kb);
                }
                ldm4(bh, aChi + kb);
                ldm4(bl, aClo + kb);
                // term 0: hi*hi (8 independent MMAs)
                #pragma unroll
                for (int mf = 0; mf < 4; mf++)
                    #pragma unroll
                    for (int nf = 0; nf < 2; nf++)
                        mma16816(acc[mf][nf], ah[mf], &bh[nf * 2]);
                // term 1: hi*lo
                #pragma unroll
                for (int mf = 0; mf < 4; mf++)
                    #pragma unroll
                    for (int nf = 0; nf < 2; nf++)
                        mma16816(acc[mf][nf], ah[mf], &bl[nf * 2]);
                // term 2: lo*hi
                #pragma unroll
                for (int mf = 0; mf < 4; mf++)
                    #pragma unroll
                    for (int nf = 0; nf < 2; nf++)
                        mma16816(acc[mf][nf], al[mf], &bh[nf * 2]);
            }
            // epilogue 2: bias + store to global
            const float* b2s = (const float*)(sm + OFF_B2);
            float* outp = out + (size_t)p * 33554432ull + rowBase * 64;
            int rbase = wm * 64 + (l >> 2);
            int ncol = 2 * (l & 3);
            #pragma unroll
            for (int mf = 0; mf < 4; mf++)
                #pragma unroll
                for (int nf = 0; nf < 2; nf++) {
                    int n = wn * 16 + nf * 8 + ncol;
                    float bv0 = b2s[n], bv1 = b2s[n + 1];
                    #pragma unroll
                    for (int half = 0; half < 2; half++) {
                        int r = rbase + mf * 16 + half * 8;
                        float2 val = make_float2(acc[mf][nf][half * 2 + 0] + bv0,
                                                 acc[mf][nf][half * 2 + 1] + bv1);
                        *(float2*)(outp + (size_t)r * 64 + n) = val;
                    }
                }
        }
    }
}

// ---------------------------------------------------------------------------
extern "C" void kernel_launch(void* const* d_in, const int* in_sizes, int n_in,
                              void* d_out, int out_size) {
    const float* x = (const float*)d_in[0];
    const float* w0 = (const float*)d_in[1];
    const float* w1 = (const float*)d_in[2];
    const float* w2 = (const float*)d_in[3];
    const float* w3 = (const float*)d_in[4];
    const float* bw1 = (const float*)d_in[5];
    const float* bb1 = (const float*)d_in[6];
    const float* bw2 = (const float*)d_in[7];
    const float* bb2 = (const float*)d_in[8];
    const float* fw1 = (const float*)d_in[9];
    const float* fb1 = (const float*)d_in[10];
    const float* fw2 = (const float*)d_in[11];
    const float* fb2 = (const float*)d_in[12];
    float* out = (float*)d_out;

    const int SM_K1 = 73216;
    const int SM_K2 = 81920;
    const int SM_K3B = (2048 + 4096 + 4096) * 8;
    cudaFuncSetAttribute(k1_stageA, cudaFuncAttributeMaxDynamicSharedMemorySize, SM_K1);
    cudaFuncSetAttribute(k2_stageB, cudaFuncAttributeMaxDynamicSharedMemorySize, SM_K2);
    cudaFuncSetAttribute(k3b_mix2, cudaFuncAttributeMaxDynamicSharedMemorySize, SM_K3B);
    cudaFuncSetAttribute(k5_mma, cudaFuncAttributeMaxDynamicSharedMemorySize, SMEM_K5);

    prep_mlp<<<140, 256>>>(bw1, fw1, bw2, fw2);
    prep_spec<<<256, 256>>>(w0, w1, w2, w3);
    prep_e<<<32, 256>>>();
    k1_stageA<<<NB * 128, 256, SM_K1>>>(x);
    k2_stageB<<<NB * 16, 256, SM_K2>>>();
    k3a_mix1<<<NB * 32, 256>>>();
    k3b_mix2<<<NB * 16, 256, SM_K3B>>>();
    k4_invkx<<<NB * 16, 256>>>();
    k5_mma<<<NB * 128, 256, SMEM_K5>>>(bb1, bb2, fb1, fb2, out);
}

// round 11
// speedup vs baseline: 3.5166x; 1.4863x over previous
#include <cuda_runtime.h>
#include <cuda_bf16.h>
#include <math.h>

#define NB 32

// ---------------- device globals ----------------
__device__ float2 gA[NB * 128 * 16 * 64];
__device__ float2 gY[NB * 32 * 16 * 64];
__device__ float2 gT[NB * 32 * 16 * 64];
__device__ float2 gF[NB * 16 * 32 * 64];
__device__ float2 gD[NB * 128 * 16 * 64];
// transposed spectral weights
__device__ float2 gW0t[65536], gW1t[65536], gW2t[65536], gW3t[65536];
// duplicated inverse-ky basis: E2[v*32+c] = {e,e}
__device__ __align__(16) float2 gE2[4096];
// packed twiddles: k1 [kg][n][4] {cos,-sin}; k2 [ug][m][4] {cos,sin}
__device__ __align__(16) float2 gTwK1p[4096];
__device__ __align__(16) float2 gTw2p[2048];
// pre-built mma B-fragments (written by prep_frag via real ldmatrix)
// gF1: [p][wn][ki=4][term][h2][lane][4 regs]; gF2: [p][wn][ki=8][term][lane][4 regs]
__device__ __align__(16) unsigned gF1[16384];
__device__ __align__(16) unsigned gF2[16384];

// ---------------- helpers ----------------
typedef unsigned long long ull;
__device__ __forceinline__ ull pack2(float lo, float hi) {
    ull r;
    asm("mov.b64 %0, {%1,%2};" : "=l"(r) : "f"(lo), "f"(hi));
    return r;
}
__device__ __forceinline__ void unpack2(ull v, float& lo, float& hi) {
    asm("mov.b64 {%0,%1}, %2;" : "=f"(lo), "=f"(hi) : "l"(v));
}
__device__ __forceinline__ void ffma2(ull& d, ull a, ull b) {
    asm("fma.rn.f32x2 %0, %1, %2, %0;" : "+l"(d) : "l"(a), "l"(b));
}
__device__ __forceinline__ unsigned smem_u32(const void* p) {
    unsigned a;
    asm("{ .reg .u64 t; cvta.to.shared.u64 t, %1; cvt.u32.u64 %0, t; }" : "=r"(a) : "l"(p));
    return a;
}
__device__ __forceinline__ void ldm4(unsigned* r, unsigned addr) {
    asm volatile("ldmatrix.sync.aligned.m8n8.x4.shared.b16 {%0,%1,%2,%3}, [%4];"
                 : "=r"(r[0]), "=r"(r[1]), "=r"(r[2]), "=r"(r[3]) : "r"(addr));
}
__device__ __forceinline__ void mma16816(float* c, const unsigned* a, const unsigned* b) {
    asm volatile("mma.sync.aligned.m16n8k16.row.col.f32.bf16.bf16.f32 "
                 "{%0,%1,%2,%3}, {%4,%5,%6,%7}, {%8,%9}, {%0,%1,%2,%3};"
                 : "+f"(c[0]), "+f"(c[1]), "+f"(c[2]), "+f"(c[3])
                 : "r"(a[0]), "r"(a[1]), "r"(a[2]), "r"(a[3]), "r"(b[0]), "r"(b[1]));
}
__device__ __forceinline__ void split2(float v0, float v1, unsigned& hp, unsigned& lp) {
    asm("cvt.rn.bf16x2.f32 %0, %1, %2;" : "=r"(hp) : "f"(v1), "f"(v0));
    float h0 = __uint_as_float(hp << 16);
    float h1 = __uint_as_float(hp & 0xFFFF0000u);
    float l0 = v0 - h0, l1 = v1 - h1;
    asm("cvt.rn.bf16x2.f32 %0, %1, %2;" : "=r"(lp) : "f"(l1), "f"(l0));
}

// ---------------- prep: B-fragments via real ldmatrix ----------------
// grid=2 (p), 256 thr, dyn smem 71680 B
// smem: W1HI 0 (18432), W1LO 18432, W2HI 36864 (17408), W2LO 54272 (17408)
__global__ void prep_frag(const float* __restrict__ bw1, const float* __restrict__ fw1,
                          const float* __restrict__ bw2, const float* __restrict__ fw2) {
    extern __shared__ __align__(16) char ps[];
    int p = blockIdx.x, t = threadIdx.x, w = t >> 5, l = t & 31;
    const float* W1 = p ? fw1 : bw1;
    const float* W2 = p ? fw2 : bw2;
    for (int e = t; e < 9216; e += 256) {  // W1^T [128n][72k]
        int n = e / 72, k = e % 72;
        float v = (k < 64) ? W1[k * 128 + n] : 0.f;
        __nv_bfloat16 hi = __float2bfloat16(v);
        __nv_bfloat16 lo = __float2bfloat16(v - __bfloat162float(hi));
        ((unsigned short*)(ps + 0))[e] = __bfloat16_as_ushort(hi);
        ((unsigned short*)(ps + 18432))[e] = __bfloat16_as_ushort(lo);
    }
    for (int e = t; e < 8704; e += 256) {  // W2^T [64n][136k]
        int n = e / 136, k = e % 136;
        float v = (k < 128) ? W2[k * 64 + n] : 0.f;
        __nv_bfloat16 hi = __float2bfloat16(v);
        __nv_bfloat16 lo = __float2bfloat16(v - __bfloat162float(hi));
        ((unsigned short*)(ps + 36864))[e] = __bfloat16_as_ushort(hi);
        ((unsigned short*)(ps + 54272))[e] = __bfloat16_as_ushort(lo);
    }
    __syncthreads();
    unsigned sb = smem_u32(ps);
    unsigned kB = ((l >> 3) & 1) * 8;
    if (w < 4) {  // GEMM1 fragments, wn = w
        int wn = w;
        unsigned rowB = (unsigned)(wn * 32 + ((l >> 4) << 3) + (l & 7));
        for (int ki = 0; ki < 4; ki++)
            for (int term = 0; term < 2; term++)
                for (int h2 = 0; h2 < 2; h2++) {
                    unsigned r[4];
                    ldm4(r, sb + (term ? 18432u : 0u) + rowB * 144 + kB * 2 +
                            (unsigned)ki * 32 + (unsigned)h2 * (16 * 144));
                    ((uint4*)gF1)[((((p * 4 + wn) * 4 + ki) * 2 + term) * 2 + h2) * 32 + l] =
                        make_uint4(r[0], r[1], r[2], r[3]);
                }
    } else {  // GEMM2 fragments, wn = w-4
        int wn = w - 4;
        unsigned rowB = (unsigned)(wn * 16 + ((l >> 4) << 3) + (l & 7));
        for (int ki = 0; ki < 8; ki++)
            for (int term = 0; term < 2; term++) {
                unsigned r[4];
                ldm4(r, sb + (term ? 54272u : 36864u) + rowB * 272 + kB * 2 + (unsigned)ki * 32);
                ((uint4*)gF2)[(((p * 4 + wn) * 8 + ki) * 2 + term) * 32 + l] =
                    make_uint4(r[0], r[1], r[2], r[3]);
            }
    }
}

// ---------------- prep: transpose spectral weights ----------------
__global__ void prep_spec(const float* __restrict__ w0, const float* __restrict__ w1,
                          const float* __restrict__ w2, const float* __restrict__ w3) {
    int e = blockIdx.x * 256 + threadIdx.x;
    int lx = e >> 12, ij = e & 4095;
    int src = ij * 16 + lx;
    gW0t[e] = ((const float2*)w0)[src];
    gW1t[e] = ((const float2*)w1)[src];
    gW2t[e] = ((const float2*)w2)[src];
    gW3t[e] = ((const float2*)w3)[src];
}

// ---------------- prep: E table + packed twiddles ----------------
__global__ void prep_e() {
    int e = blockIdx.x * 256 + threadIdx.x;  // 0..10239
    if (e < 4096) {
        int v = e >> 5, c = e & 31, k = c >> 1;
        float sv, cv;
        sincospif((float)(v * k) * (1.0f / 64.0f), &sv, &cv);
        float val = (c & 1) ? sv : cv;
        gE2[e] = make_float2(val, val);
    } else if (e < 8192) {  // gTwK1p[kg][n][j]
        int e2 = e - 4096;
        int kg = e2 >> 8, n = (e2 >> 2) & 63, j = e2 & 3;
        int ky = kg * 4 + j;
        float sv, cv;
        sincospif((float)(ky * n) * (1.0f / 64.0f), &sv, &cv);
        gTwK1p[e2] = make_float2(cv, -sv);
    } else if (e < 10240) {  // gTw2p[ug][m][q]
        int e2 = e - 8192;
        int ug = e2 >> 9, m = (e2 >> 2) & 127, q = e2 & 3;
        int k = ug * 4 + q + 1;
        float sv, cv;
        sincospif((float)(k * m) * (1.0f / 64.0f), &sv, &cv);
        gTw2p[e2] = make_float2(cv, sv);
    }
}

// ---------------- K1: forward DFT along n (folded, packed twiddles) ----------------
// dyn smem: xs 32768 + sd 32256 + twk 8192 = 73216 B
__global__ __launch_bounds__(256) void k1_stageA(const float* __restrict__ x) {
    extern __shared__ float smf[];
    float* xs = smf;
    float2* sd = (float2*)(smf + 8192);
    float2* twk = (float2*)(smf + 8192 + 8064);
    int bm = blockIdx.x, t = threadIdx.x;
    const float4* src = (const float4*)(x + (size_t)bm * (128 * 64));
    float4* d4 = (float4*)xs;
    #pragma unroll
    for (int e = t; e < 2048; e += 256) d4[e] = src[e];
    #pragma unroll
    for (int e = t; e < 512; e += 256) ((float4*)twk)[e] = ((const float4*)gTwK1p)[e];
    __syncthreads();
    for (int e = t; e < 4032; e += 256) {
        int n = (e >> 6) + 1, i = e & 63;
        float a = xs[n * 64 + i], b = xs[(128 - n) * 64 + i];
        sd[e] = make_float2(a + b, a - b);
    }
    __syncthreads();

    int i = t & 63, kg = t >> 6;
    int ky0 = kg * 4;
    float x0 = xs[i], x64 = xs[4096 + i];
    const ull* sd2 = (const ull*)sd + i;
    const ulonglong2* twp = (const ulonglong2*)twk + kg * 128;  // [n][2]
    ull a0 = pack2(x0 + x64, 0.f);
    ull a1 = pack2(x0 - x64, 0.f);
    ull a2 = pack2(x0 + x64, 0.f);
    ull a3 = pack2(x0 - x64, 0.f);
    #pragma unroll
    for (int n = 1; n <= 63; n++) {
        ull sdv = sd2[(n - 1) * 64];
        ulonglong2 t01 = twp[n * 2];
        ulonglong2 t23 = twp[n * 2 + 1];
        ffma2(a0, sdv, t01.x);
        ffma2(a1, sdv, t01.y);
        ffma2(a2, sdv, t23.x);
        ffma2(a3, sdv, t23.y);
    }
    float2* outp = gA + (size_t)bm * (16 * 64);
    float lo, hi;
    unpack2(a0, lo, hi); outp[(ky0 + 0) * 64 + i] = make_float2(lo, hi);
    unpack2(a1, lo, hi); outp[(ky0 + 1) * 64 + i] = make_float2(lo, hi);
    unpack2(a2, lo, hi); outp[(ky0 + 2) * 64 + i] = make_float2(lo, hi);
    unpack2(a3, lo, hi); outp[(ky0 + 3) * 64 + i] = make_float2(lo, hi);
}

// ---------------- K2: forward DFT along m (paired, packed twiddles) ----------------
// dyn smem: As 64KB + tw 16KB = 81920 B
__global__ __launch_bounds__(256) void k2_stageB() {
    extern __shared__ float2 sm2[];
    float2* As = sm2;
    float2* tw = sm2 + 8192;  // 2048: [ug][m][4]
    int blk = blockIdx.x, b = blk >> 4, ky = blk & 15, t = threadIdx.x;
    for (int e = t; e < 8192; e += 256) {
        int m = e >> 6, i = e & 63;
        As[e] = gA[(((size_t)b * 128 + m) * 16 + ky) * 64 + i];
    }
    #pragma unroll
    for (int e = t; e < 1024; e += 256) ((float4*)tw)[e] = ((const float4*)gTw2p)[e];
    __syncthreads();

    int i = t & 63, ug = t >> 6;
    ull acc12[4], acc34[4];
    #pragma unroll
    for (int q = 0; q < 4; q++) { acc12[q] = 0ull; acc34[q] = 0ull; }
    const ulonglong2* twp = (const ulonglong2*)tw + ug * 256;  // [m][2]
    float sx = 0.f, sy = 0.f;
    #pragma unroll 4
    for (int m = 0; m < 128; m++) {
        float2 a = As[m * 64 + i];
        ull axy = pack2(a.x, a.y), ayx = pack2(a.y, a.x);
        ulonglong2 t01 = twp[m * 2];
        ulonglong2 t23 = twp[m * 2 + 1];
        ffma2(acc12[0], axy, t01.x); ffma2(acc34[0], ayx, t01.x);
        ffma2(acc12[1], axy, t01.y); ffma2(acc34[1], ayx, t01.y);
        ffma2(acc12[2], axy, t23.x); ffma2(acc34[2], ayx, t23.x);
        ffma2(acc12[3], axy, t23.y); ffma2(acc34[3], ayx, t23.y);
        if (ug == 3) { sx += a.x; sy += a.y; }
    }
    float2* yb = gY + (((size_t)b * 32) * 16 + ky) * 64 + i;
    #pragma unroll
    for (int q = 0; q < 4; q++) {
        int k = ug * 4 + q + 1;
        float u1, u2, u3, u4;
        unpack2(acc12[q], u1, u2);
        unpack2(acc34[q], u3, u4);
        if (k < 16) yb[(size_t)k * 1024] = make_float2(u1 + u2, u3 - u4);
        yb[(size_t)(32 - k) * 1024] = make_float2(u1 - u2, u3 + u4);
    }
    if (ug == 3) yb[0] = make_float2(sx, sy);
}

// ---------------- K3a ----------------
__global__ __launch_bounds__(256) void k3a_mix1() {
    __shared__ float4 Ys4[16 * 64];
    __shared__ float2 Was[64 * 64];
    int blk = blockIdx.x, s = blk & 31, lx = s & 15, t = threadIdx.x;
    const float2* wt = (s < 16) ? gW0t : gW2t;
    for (int e = t; e < 1024; e += 256) {
        float2 y = gY[(size_t)blk * 1024 + e];
        Ys4[e] = make_float4(y.x, y.y, -y.y, y.x);
    }
    for (int e = t; e < 4096; e += 256) Was[e] = wt[lx * 4096 + e];
    __syncthreads();
    int j = t & 63, kg = t >> 6;
    ull acc[4];
    #pragma unroll
    for (int q = 0; q < 4; q++) acc[q] = 0ull;
    for (int ii = 0; ii < 64; ii++) {
        float2 wv = Was[ii * 64 + j];
        ull wr2 = pack2(wv.x, wv.x), wi2 = pack2(wv.y, wv.y);
        #pragma unroll
        for (int q = 0; q < 4; q++) {
            const ull* y2 = (const ull*)&Ys4[(kg * 4 + q) * 64 + ii];
            ffma2(acc[q], wr2, y2[0]);
            ffma2(acc[q], wi2, y2[1]);
        }
    }
    #pragma unroll
    for (int q = 0; q < 4; q++) {
        float re, im;
        unpack2(acc[q], re, im);
        gT[(size_t)blk * 1024 + (kg * 4 + q) * 64 + j] = make_float2(re, im);
    }
}

// ---------------- K3b ----------------
__global__ __launch_bounds__(256) void k3b_mix2() {
    extern __shared__ float2 sm2b[];
    float2* Ts = sm2b;
    float2* Wb0 = sm2b + 2048;
    float2* Wb1 = Wb0 + 4096;
    int blk = blockIdx.x, b = blk >> 4, ky = blk & 15, t = threadIdx.x;
    for (int e = t; e < 2048; e += 256) {
        int s_ = e >> 6, j = e & 63;
        Ts[e] = gT[(((size_t)b * 32 + s_) * 16 + ky) * 64 + j];
    }
    for (int e = t; e < 4096; e += 256) {
        Wb0[e] = gW1t[ky * 4096 + e];
        Wb1[e] = gW3t[ky * 4096 + e];
    }
    __syncthreads();
    int o = t & 63, sg = t >> 6;
    const float2* Wb = (sg < 2) ? Wb0 : Wb1;
    float2 acc[8];
    #pragma unroll
    for (int q = 0; q < 8; q++) acc[q] = make_float2(0.f, 0.f);
    for (int j = 0; j < 64; j++) {
        float2 wv = Wb[j * 64 + o];
        #pragma unroll
        for (int q = 0; q < 8; q++) {
            float2 tv = Ts[(sg * 8 + q) * 64 + j];
            acc[q].x += tv.x * wv.x - tv.y * wv.y;
            acc[q].y += tv.x * wv.y + tv.y * wv.x;
        }
    }
    #pragma unroll
    for (int q = 0; q < 8; q++) {
        int s_ = sg * 8 + q;
        gF[(size_t)blk * 2048 + s_ * 64 + o] = acc[q];
    }
}

// ---------------- K4: inverse DFT over kx ----------------
__global__ __launch_bounds__(256) void k4_invkx() {
    __shared__ float2 Fs[32 * 64];
    __shared__ float4 PQ[16 * 64];
    __shared__ float4 tab4[128];  // {c,c,s,s}
    int blk = blockIdx.x, b = blk >> 4, ky = blk & 15, t = threadIdx.x;
    for (int e = t; e < 2048; e += 256) Fs[e] = gF[(size_t)blk * 2048 + e];
    if (t < 128) {
        float sv, cv;
        sincospif((float)t * (1.0f / 64.0f), &sv, &cv);
        tab4[t] = make_float4(cv, cv, sv, sv);
    }
    __syncthreads();
    for (int e = t; e < 1024; e += 256) {
        int k = e >> 6, o = e & 63;
        if (k == 0) {
            float2 f = Fs[16 * 64 + o];
            PQ[o] = make_float4(f.x, f.y, f.y, -f.x);
        } else {
            float2 fa = Fs[k * 64 + o], fb = Fs[(32 - k) * 64 + o];
            PQ[k * 64 + o] = make_float4(fa.x + fb.x, fa.y + fb.y, -(fa.y - fb.y), fa.x - fb.x);
        }
    }
    __syncthreads();

    int o = t & 63, ug = t >> 6;
    float2 F0 = Fs[o];
    float4 pq[16];
    #pragma unroll
    for (int k = 0; k < 16; k++) pq[k] = PQ[k * 64 + o];

    for (int q = 0; q < 32; q++) {
        int u = ug * 32 + q;
        ull acc = pack2(F0.x, F0.y);
        int idx = u;
        #pragma unroll
        for (int k = 1; k < 16; k++) {
            const ull* cs = (const ull*)&tab4[idx];
            ffma2(acc, cs[0], ((const ull*)&pq[k])[0]);
            ffma2(acc, cs[1], ((const ull*)&pq[k])[1]);
            idx = (idx + u) & 127;
        }
        {
            const ull* cs = (const ull*)&tab4[(16 * u) & 127];
            ffma2(acc, cs[0], ((const ull*)&pq[0])[0]);
            ffma2(acc, cs[1], ((const ull*)&pq[0])[1]);
        }
        float re, im;
        unpack2(acc, re, im);
        gD[(((size_t)b * 128 + u) * 16 + ky) * 64 + o] = make_float2(re, im);
    }
}

// ---------------- K5: inverse ky + both MLPs (W frags from global) ----------------
#define OFF_XHI   0u
#define OFF_XLO   18432u
#define OFF_HHI   36864u
#define OFF_HLO   71680u
#define SMEM_K5   106496

__global__ __launch_bounds__(256, 2) void k5_mma(
    const float* __restrict__ bb1, const float* __restrict__ bb2,
    const float* __restrict__ fb1, const float* __restrict__ fb2,
    float* __restrict__ out) {
    extern __shared__ __align__(16) char sm[];
    unsigned sb = smem_u32(sm);
    int t = threadIdx.x, w = t >> 5, l = t & 31;
    int blk = blockIdx.x;

    // ---- stage 1 scratch (aliases H region): E2 (32KB) + Dp (8KB)
    float2* E2 = (float2*)(sm + OFF_HHI);
    float* Dp = (float*)(sm + OFF_HHI + 32768);
    for (int e = t; e < 2048; e += 256)
        ((float4*)E2)[e] = ((const float4*)gE2)[e];
    for (int e = t; e < 1024; e += 256) {
        int ky = e >> 6, o = e & 63;
        float2 d = gD[(size_t)blk * 1024 + e];
        float sc = (ky ? 2.0f : 1.0f) * (1.0f / 16384.0f);
        Dp[(2 * ky) * 64 + o] = d.x * sc;
        Dp[(2 * ky + 1) * 64 + o] = -d.y * sc;
    }
    __syncthreads();

    // xo = E @ Dp (128x64, K=32) -> bf16 hi/lo A operand (144B rows)
    {
        int rg = t >> 4, cg = t & 15;
        int r0 = rg * 8, c0 = cg * 4;
        ull acc[8][2];
        #pragma unroll
        for (int j = 0; j < 8; j++) { acc[j][0] = 0ull; acc[j][1] = 0ull; }
        const ull* E2u = (const ull*)E2;
        for (int c = 0; c < 32; c++) {
            ulonglong2 dd = *(const ulonglong2*)&Dp[c * 64 + c0];
            #pragma unroll
            for (int j = 0; j < 8; j++) {
                ull e2 = E2u[(r0 + j) * 32 + c];
                ffma2(acc[j][0], e2, dd.x);
                ffma2(acc[j][1], e2, dd.y);
            }
        }
        #pragma unroll
        for (int j = 0; j < 8; j++) {
            float x0, x1, x2, x3;
            unpack2(acc[j][0], x0, x1);
            unpack2(acc[j][1], x2, x3);
            unsigned hA, lA, hB, lB;
            split2(x0, x1, hA, lA);
            split2(x2, x3, hB, lB);
            unsigned relb = (unsigned)(r0 + j) * 144u + (unsigned)c0 * 2u;
            *(uint2*)(sm + OFF_XHI + relb) = make_uint2(hA, hB);
            *(uint2*)(sm + OFF_XLO + relb) = make_uint2(lA, lB);
        }
    }

    size_t rowBase = (size_t)blk * 128;
    int wm = w & 1, wn = w >> 1;
    unsigned kA = ((l >> 4) & 1) * 8;
    unsigned rowA = (unsigned)(wm * 64 + (l & 7) + ((l >> 3) & 1) * 8);

    for (int p = 0; p < 2; p++) {
        __syncthreads();  // X ready / prior GEMM2 done reading H
        const float* B1 = p ? fb1 : bb1;
        const float* B2 = p ? fb2 : bb2;

        // ---- GEMM1: C1[128,128] = X @ W1, B-frags via LDG
        {
            float acc[4][4][4];
            #pragma unroll
            for (int a = 0; a < 4; a++)
                #pragma unroll
                for (int b = 0; b < 4; b++)
                    #pragma unroll
                    for (int c = 0; c < 4; c++) acc[a][b][c] = 0.f;

            unsigned aXhi = sb + OFF_XHI + rowA * 144 + kA * 2;
            unsigned aXlo = sb + OFF_XLO + rowA * 144 + kA * 2;
            const uint4* F1 = (const uint4*)gF1 + ((p * 4 + wn) * 4) * 4 * 32 + l;

            #pragma unroll
            for (int ki = 0; ki < 4; ki++) {
                unsigned kb = ki * 32;
                unsigned ah[4][4], al[4][4];
                uint4 bh[2], bl[2];
                #pragma unroll
                for (int mf = 0; mf < 4; mf++) {
                    ldm4(ah[mf], aXhi + mf * (16 * 144) + kb);
                    ldm4(al[mf], aXlo + mf * (16 * 144) + kb);
                }
                bh[0] = F1[(ki * 4 + 0) * 32];
                bh[1] = F1[(ki * 4 + 1) * 32];
                bl[0] = F1[(ki * 4 + 2) * 32];
                bl[1] = F1[(ki * 4 + 3) * 32];
                const unsigned* bhp = (const unsigned*)bh;
                const unsigned* blp = (const unsigned*)bl;
                #pragma unroll
                for (int mf = 0; mf < 4; mf++)
                    #pragma unroll
                    for (int nf = 0; nf < 4; nf++)
                        mma16816(acc[mf][nf], ah[mf], &bhp[nf * 2]);
                #pragma unroll
                for (int mf = 0; mf < 4; mf++)
                    #pragma unroll
                    for (int nf = 0; nf < 4; nf++)
                        mma16816(acc[mf][nf], ah[mf], &blp[nf * 2]);
                #pragma unroll
                for (int mf = 0; mf < 4; mf++)
                    #pragma unroll
                    for (int nf = 0; nf < 4; nf++)
                        mma16816(acc[mf][nf], al[mf], &bhp[nf * 2]);
            }
            // epilogue 1: bias + relu + split -> H (272B rows)
            int rbase = wm * 64 + (l >> 2);
            int ncol = 2 * (l & 3);
            #pragma unroll
            for (int nf = 0; nf < 4; nf++) {
                int n = wn * 32 + nf * 8 + ncol;
                float2 bv = *(const float2*)(B1 + n);
                #pragma unroll
                for (int mf = 0; mf < 4; mf++)
                    #pragma unroll
                    for (int half = 0; half < 2; half++) {
                        int r = rbase + mf * 16 + half * 8;
                        float v0 = fmaxf(acc[mf][nf][half * 2 + 0] + bv.x, 0.f);
                        float v1 = fmaxf(acc[mf][nf][half * 2 + 1] + bv.y, 0.f);
                        unsigned hp, lp;
                        split2(v0, v1, hp, lp);
                        unsigned off = (unsigned)r * 272u + (unsigned)n * 2u;
                        *(unsigned*)(sm + OFF_HHI + off) = hp;
                        *(unsigned*)(sm + OFF_HLO + off) = lp;
                    }
            }
        }
        __syncthreads();

        // ---- GEMM2: C2[128,64] = H @ W2, B-frags via LDG
        {
            float acc[4][2][4];
            #pragma unroll
            for (int a = 0; a < 4; a++)
                #pragma unroll
                for (int b = 0; b < 2; b++)
                    #pragma unroll
                    for (int c = 0; c < 4; c++) acc[a][b][c] = 0.f;

            unsigned aHhi = sb + OFF_HHI + rowA * 272 + kA * 2;
            unsigned aHlo = sb + OFF_HLO + rowA * 272 + kA * 2;
            const uint4* F2 = (const uint4*)gF2 + ((p * 4 + wn) * 8) * 2 * 32 + l;

            #pragma unroll
            for (int ki = 0; ki < 8; ki++) {
                unsigned kb = ki * 32;
                unsigned ah[4][4], al[4][4];
                uint4 bh4 = F2[(ki * 2 + 0) * 32];
                uint4 bl4 = F2[(ki * 2 + 1) * 32];
                const unsigned* bh = (const unsigned*)&bh4;
                const unsigned* bl = (const unsigned*)&bl4;
                #pragma unroll
                for (int mf = 0; mf < 4; mf++) {
                    ldm4(ah[mf], aHhi + mf * (16 * 272) + kb);
                    ldm4(al[mf], aHlo + mf * (16 * 272) + kb);
                }
                #pragma unroll
                for (int mf = 0; mf < 4; mf++)
                    #pragma unroll
                    for (int nf = 0; nf < 2; nf++)
                        mma16816(acc[mf][nf], ah[mf], &bh[nf * 2]);
                #pragma unroll
                for (int mf = 0; mf < 4; mf++)
                    #pragma unroll
                    for (int nf = 0; nf < 2; nf++)
                        mma16816(acc[mf][nf], ah[mf], &bl[nf * 2]);
                #pragma unroll
                for (int mf = 0; mf < 4; mf++)
                    #pragma unroll
                    for (int nf = 0; nf < 2; nf++)
                        mma16816(acc[mf][nf], al[mf], &bh[nf * 2]);
            }
            // epilogue 2: bias + store
            float* outp = out + (size_t)p * 33554432ull + rowBase * 64;
            int rbase = wm * 64 + (l >> 2);
            int ncol = 2 * (l & 3);
            #pragma unroll
            for (int nf = 0; nf < 2; nf++) {
                int n = wn * 16 + nf * 8 + ncol;
                float2 bv = *(const float2*)(B2 + n);
                #pragma unroll
                for (int mf = 0; mf < 4; mf++)
                    #pragma unroll
                    for (int half = 0; half < 2; half++) {
                        int r = rbase + mf * 16 + half * 8;
                        float2 val = make_float2(acc[mf][nf][half * 2 + 0] + bv.x,
                                                 acc[mf][nf][half * 2 + 1] + bv.y);
                        *(float2*)(outp + (size_t)r * 64 + n) = val;
                    }
            }
        }
    }
}

// ---------------------------------------------------------------------------
extern "C" void kernel_launch(void* const* d_in, const int* in_sizes, int n_in,
                              void* d_out, int out_size) {
    const float* x = (const float*)d_in[0];
    const float* w0 = (const float*)d_in[1];
    const float* w1 = (const float*)d_in[2];
    const float* w2 = (const float*)d_in[3];
    const float* w3 = (const float*)d_in[4];
    const float* bw1 = (const float*)d_in[5];
    const float* bb1 = (const float*)d_in[6];
    const float* bw2 = (const float*)d_in[7];
    const float* bb2 = (const float*)d_in[8];
    const float* fw1 = (const float*)d_in[9];
    const float* fb1 = (const float*)d_in[10];
    const float* fw2 = (const float*)d_in[11];
    const float* fb2 = (const float*)d_in[12];
    float* out = (float*)d_out;

    const int SM_PF = 71680;
    const int SM_K1 = 73216;
    const int SM_K2 = 81920;
    const int SM_K3B = (2048 + 4096 + 4096) * 8;
    cudaFuncSetAttribute(prep_frag, cudaFuncAttributeMaxDynamicSharedMemorySize, SM_PF);
    cudaFuncSetAttribute(k1_stageA, cudaFuncAttributeMaxDynamicSharedMemorySize, SM_K1);
    cudaFuncSetAttribute(k2_stageB, cudaFuncAttributeMaxDynamicSharedMemorySize, SM_K2);
    cudaFuncSetAttribute(k3b_mix2, cudaFuncAttributeMaxDynamicSharedMemorySize, SM_K3B);
    cudaFuncSetAttribute(k5_mma, cudaFuncAttributeMaxDynamicSharedMemorySize, SMEM_K5);

    prep_frag<<<2, 256, SM_PF>>>(bw1, fw1, bw2, fw2);
    prep_spec<<<256, 256>>>(w0, w1, w2, w3);
    prep_e<<<40, 256>>>();
    k1_stageA<<<NB * 128, 256, SM_K1>>>(x);
    k2_stageB<<<NB * 16, 256, SM_K2>>>();
    k3a_mix1<<<NB * 32, 256>>>();
    k3b_mix2<<<NB * 16, 256, SM_K3B>>>();
    k4_invkx<<<NB * 16, 256>>>();
    k5_mma<<<NB * 128, 256, SMEM_K5>>>(bb1, bb2, fb1, fb2, out);
}

// round 12
// speedup vs baseline: 3.5647x; 1.0137x over previous
#include <cuda_runtime.h>
#include <cuda_bf16.h>
#include <math.h>

#define NB 32

// ---------------- device globals ----------------
__device__ float2 gA[NB * 16 * 128 * 64];  // [b][ky][m][i]
__device__ float2 gY[NB * 32 * 16 * 64];
__device__ float2 gT[NB * 32 * 16 * 64];
__device__ float2 gF[NB * 16 * 32 * 64];
__device__ float2 gD[NB * 128 * 16 * 64];
// transposed spectral weights
__device__ float2 gW0t[65536], gW1t[65536], gW2t[65536], gW3t[65536];
// duplicated inverse-ky basis: E2[v*32+c] = {e,e}
__device__ __align__(16) float2 gE2[4096];
// packed twiddles: k1 [kg][n][4] {cos,-sin}; k2 [ug][m][4] {cos,sin}
__device__ __align__(16) float2 gTwK1p[4096];
__device__ __align__(16) float2 gTw2p[2048];
// pre-built mma B-fragments
__device__ __align__(16) unsigned gF1[16384];
__device__ __align__(16) unsigned gF2[16384];

// ---------------- helpers ----------------
typedef unsigned long long ull;
__device__ __forceinline__ ull pack2(float lo, float hi) {
    ull r;
    asm("mov.b64 %0, {%1,%2};" : "=l"(r) : "f"(lo), "f"(hi));
    return r;
}
__device__ __forceinline__ void unpack2(ull v, float& lo, float& hi) {
    asm("mov.b64 {%0,%1}, %2;" : "=f"(lo), "=f"(hi) : "l"(v));
}
__device__ __forceinline__ void ffma2(ull& d, ull a, ull b) {
    asm("fma.rn.f32x2 %0, %1, %2, %0;" : "+l"(d) : "l"(a), "l"(b));
}
__device__ __forceinline__ unsigned smem_u32(const void* p) {
    unsigned a;
    asm("{ .reg .u64 t; cvta.to.shared.u64 t, %1; cvt.u32.u64 %0, t; }" : "=r"(a) : "l"(p));
    return a;
}
__device__ __forceinline__ void ldm4(unsigned* r, unsigned addr) {
    asm volatile("ldmatrix.sync.aligned.m8n8.x4.shared.b16 {%0,%1,%2,%3}, [%4];"
                 : "=r"(r[0]), "=r"(r[1]), "=r"(r[2]), "=r"(r[3]) : "r"(addr));
}
__device__ __forceinline__ void mma16816(float* c, const unsigned* a, const unsigned* b) {
    asm volatile("mma.sync.aligned.m16n8k16.row.col.f32.bf16.bf16.f32 "
                 "{%0,%1,%2,%3}, {%4,%5,%6,%7}, {%8,%9}, {%0,%1,%2,%3};"
                 : "+f"(c[0]), "+f"(c[1]), "+f"(c[2]), "+f"(c[3])
                 : "r"(a[0]), "r"(a[1]), "r"(a[2]), "r"(a[3]), "r"(b[0]), "r"(b[1]));
}
__device__ __forceinline__ void split2(float v0, float v1, unsigned& hp, unsigned& lp) {
    asm("cvt.rn.bf16x2.f32 %0, %1, %2;" : "=r"(hp) : "f"(v1), "f"(v0));
    float h0 = __uint_as_float(hp << 16);
    float h1 = __uint_as_float(hp & 0xFFFF0000u);
    float l0 = v0 - h0, l1 = v1 - h1;
    asm("cvt.rn.bf16x2.f32 %0, %1, %2;" : "=r"(lp) : "f"(l1), "f"(l0));
}

// ---------------- prep: B-fragments via real ldmatrix ----------------
__global__ void prep_frag(const float* __restrict__ bw1, const float* __restrict__ fw1,
                          const float* __restrict__ bw2, const float* __restrict__ fw2) {
    extern __shared__ __align__(16) char ps[];
    int p = blockIdx.x, t = threadIdx.x, w = t >> 5, l = t & 31;
    const float* W1 = p ? fw1 : bw1;
    const float* W2 = p ? fw2 : bw2;
    for (int e = t; e < 9216; e += 256) {  // W1^T [128n][72k]
        int n = e / 72, k = e % 72;
        float v = (k < 64) ? W1[k * 128 + n] : 0.f;
        __nv_bfloat16 hi = __float2bfloat16(v);
        __nv_bfloat16 lo = __float2bfloat16(v - __bfloat162float(hi));
        ((unsigned short*)(ps + 0))[e] = __bfloat16_as_ushort(hi);
        ((unsigned short*)(ps + 18432))[e] = __bfloat16_as_ushort(lo);
    }
    for (int e = t; e < 8704; e += 256) {  // W2^T [64n][136k]
        int n = e / 136, k = e % 136;
        float v = (k < 128) ? W2[k * 64 + n] : 0.f;
        __nv_bfloat16 hi = __float2bfloat16(v);
        __nv_bfloat16 lo = __float2bfloat16(v - __bfloat162float(hi));
        ((unsigned short*)(ps + 36864))[e] = __bfloat16_as_ushort(hi);
        ((unsigned short*)(ps + 54272))[e] = __bfloat16_as_ushort(lo);
    }
    __syncthreads();
    unsigned sb = smem_u32(ps);
    unsigned kB = ((l >> 3) & 1) * 8;
    if (w < 4) {
        int wn = w;
        unsigned rowB = (unsigned)(wn * 32 + ((l >> 4) << 3) + (l & 7));
        for (int ki = 0; ki < 4; ki++)
            for (int term = 0; term < 2; term++)
                for (int h2 = 0; h2 < 2; h2++) {
                    unsigned r[4];
                    ldm4(r, sb + (term ? 18432u : 0u) + rowB * 144 + kB * 2 +
                            (unsigned)ki * 32 + (unsigned)h2 * (16 * 144));
                    ((uint4*)gF1)[((((p * 4 + wn) * 4 + ki) * 2 + term) * 2 + h2) * 32 + l] =
                        make_uint4(r[0], r[1], r[2], r[3]);
                }
    } else {
        int wn = w - 4;
        unsigned rowB = (unsigned)(wn * 16 + ((l >> 4) << 3) + (l & 7));
        for (int ki = 0; ki < 8; ki++)
            for (int term = 0; term < 2; term++) {
                unsigned r[4];
                ldm4(r, sb + (term ? 54272u : 36864u) + rowB * 272 + kB * 2 + (unsigned)ki * 32);
                ((uint4*)gF2)[(((p * 4 + wn) * 8 + ki) * 2 + term) * 32 + l] =
                    make_uint4(r[0], r[1], r[2], r[3]);
            }
    }
}

// ---------------- prep: transpose spectral weights ----------------
__global__ void prep_spec(const float* __restrict__ w0, const float* __restrict__ w1,
                          const float* __restrict__ w2, const float* __restrict__ w3) {
    int e = blockIdx.x * 256 + threadIdx.x;
    int lx = e >> 12, ij = e & 4095;
    int src = ij * 16 + lx;
    gW0t[e] = ((const float2*)w0)[src];
    gW1t[e] = ((const float2*)w1)[src];
    gW2t[e] = ((const float2*)w2)[src];
    gW3t[e] = ((const float2*)w3)[src];
}

// ---------------- prep: E table + packed twiddles ----------------
__global__ void prep_e() {
    int e = blockIdx.x * 256 + threadIdx.x;
    if (e < 4096) {
        int v = e >> 5, c = e & 31, k = c >> 1;
        float sv, cv;
        sincospif((float)(v * k) * (1.0f / 64.0f), &sv, &cv);
        float val = (c & 1) ? sv : cv;
        gE2[e] = make_float2(val, val);
    } else if (e < 8192) {
        int e2 = e - 4096;
        int kg = e2 >> 8, n = (e2 >> 2) & 63, j = e2 & 3;
        int ky = kg * 4 + j;
        float sv, cv;
        sincospif((float)(ky * n) * (1.0f / 64.0f), &sv, &cv);
        gTwK1p[e2] = make_float2(cv, -sv);
    } else if (e < 10240) {
        int e2 = e - 8192;
        int ug = e2 >> 9, m = (e2 >> 2) & 127, q = e2 & 3;
        int k = ug * 4 + q + 1;
        float sv, cv;
        sincospif((float)(k * m) * (1.0f / 64.0f), &sv, &cv);
        gTw2p[e2] = make_float2(cv, sv);
    }
}

// ---------------- K1: forward DFT along n (fold-on-load) ----------------
// dyn smem: sd 4032 f2 (32256) + twk 1024 f2 (8192) + r064 128 f (512) = 40960 B
__global__ __launch_bounds__(256) void k1_stageA(const float* __restrict__ x) {
    extern __shared__ float smf[];
    float2* sd = (float2*)smf;            // [n-1][i]
    float2* twk = (float2*)(smf + 8064);  // [kg][n][4]
    float* r064 = smf + 8064 + 2048;      // rows 0 and 64
    int bm = blockIdx.x, t = threadIdx.x;
    const float* xf = x + (size_t)bm * 8192;
    const float4* xg = (const float4*)xf;

    if (t < 64) r064[t] = xf[t];
    else if (t < 128) r064[t] = xf[4096 + (t - 64)];
    #pragma unroll
    for (int e = t; e < 512; e += 256) ((float4*)twk)[e] = ((const float4*)gTwK1p)[e];
    // fold directly from global: n = 1..63
    for (int e = t; e < 1008; e += 256) {
        int n = 1 + (e >> 4), i4 = e & 15;
        float4 a = xg[n * 16 + i4];
        float4 b = xg[(128 - n) * 16 + i4];
        float4* dst = (float4*)&sd[(n - 1) * 64 + i4 * 4];
        dst[0] = make_float4(a.x + b.x, a.x - b.x, a.y + b.y, a.y - b.y);
        dst[1] = make_float4(a.z + b.z, a.z - b.z, a.w + b.w, a.w - b.w);
    }
    __syncthreads();

    int i = t & 63, kg = t >> 6;
    int ky0 = kg * 4;
    float x0 = r064[i], x64 = r064[64 + i];
    const ull* sd2 = (const ull*)sd + i;
    const ulonglong2* twp = (const ulonglong2*)twk + kg * 128;
    ull a0 = pack2(x0 + x64, 0.f);
    ull a1 = pack2(x0 - x64, 0.f);
    ull a2 = pack2(x0 + x64, 0.f);
    ull a3 = pack2(x0 - x64, 0.f);
    #pragma unroll
    for (int n = 1; n <= 63; n++) {
        ull sdv = sd2[(n - 1) * 64];
        ulonglong2 t01 = twp[n * 2];
        ulonglong2 t23 = twp[n * 2 + 1];
        ffma2(a0, sdv, t01.x);
        ffma2(a1, sdv, t01.y);
        ffma2(a2, sdv, t23.x);
        ffma2(a3, sdv, t23.y);
    }
    // gA layout: [b][ky][m][i]
    int b = bm >> 7, m = bm & 127;
    float2* outp = gA + ((size_t)b * 16) * 8192 + (size_t)m * 64 + i;
    float lo, hi;
    unpack2(a0, lo, hi); outp[(size_t)(ky0 + 0) * 8192] = make_float2(lo, hi);
    unpack2(a1, lo, hi); outp[(size_t)(ky0 + 1) * 8192] = make_float2(lo, hi);
    unpack2(a2, lo, hi); outp[(size_t)(ky0 + 2) * 8192] = make_float2(lo, hi);
    unpack2(a3, lo, hi); outp[(size_t)(ky0 + 3) * 8192] = make_float2(lo, hi);
}

// ---------------- K2: forward DFT along m (linear stage from [b][ky][m][i]) ----------------
// dyn smem: As 64KB + tw 16KB = 81920 B
__global__ __launch_bounds__(256) void k2_stageB() {
    extern __shared__ float2 sm2[];
    float2* As = sm2;
    float2* tw = sm2 + 8192;
    int blk = blockIdx.x, b = blk >> 4, ky = blk & 15, t = threadIdx.x;
    const float4* src = (const float4*)(gA + (size_t)blk * 8192);
    #pragma unroll
    for (int e = t; e < 4096; e += 256) ((float4*)As)[e] = src[e];
    #pragma unroll
    for (int e = t; e < 1024; e += 256) ((float4*)tw)[e] = ((const float4*)gTw2p)[e];
    __syncthreads();

    int i = t & 63, ug = t >> 6;
    ull acc12[4], acc34[4];
    #pragma unroll
    for (int q = 0; q < 4; q++) { acc12[q] = 0ull; acc34[q] = 0ull; }
    const ulonglong2* twp = (const ulonglong2*)tw + ug * 256;
    float sx = 0.f, sy = 0.f;
    #pragma unroll 4
    for (int m = 0; m < 128; m++) {
        float2 a = As[m * 64 + i];
        ull axy = pack2(a.x, a.y), ayx = pack2(a.y, a.x);
        ulonglong2 t01 = twp[m * 2];
        ulonglong2 t23 = twp[m * 2 + 1];
        ffma2(acc12[0], axy, t01.x); ffma2(acc34[0], ayx, t01.x);
        ffma2(acc12[1], axy, t01.y); ffma2(acc34[1], ayx, t01.y);
        ffma2(acc12[2], axy, t23.x); ffma2(acc34[2], ayx, t23.x);
        ffma2(acc12[3], axy, t23.y); ffma2(acc34[3], ayx, t23.y);
        if (ug == 3) { sx += a.x; sy += a.y; }
    }
    float2* yb = gY + (((size_t)b * 32) * 16 + ky) * 64 + i;
    #pragma unroll
    for (int q = 0; q < 4; q++) {
        int k = ug * 4 + q + 1;
        float u1, u2, u3, u4;
        unpack2(acc12[q], u1, u2);
        unpack2(acc34[q], u3, u4);
        if (k < 16) yb[(size_t)k * 1024] = make_float2(u1 + u2, u3 - u4);
        yb[(size_t)(32 - k) * 1024] = make_float2(u1 - u2, u3 + u4);
    }
    if (ug == 3) yb[0] = make_float2(sx, sy);
}

// ---------------- K3a ----------------
__global__ __launch_bounds__(256) void k3a_mix1() {
    __shared__ float4 Ys4[16 * 64];
    __shared__ float2 Was[64 * 64];
    int blk = blockIdx.x, s = blk & 31, lx = s & 15, t = threadIdx.x;
    const float2* wt = (s < 16) ? gW0t : gW2t;
    for (int e = t; e < 1024; e += 256) {
        float2 y = gY[(size_t)blk * 1024 + e];
        Ys4[e] = make_float4(y.x, y.y, -y.y, y.x);
    }
    for (int e = t; e < 4096; e += 256) Was[e] = wt[lx * 4096 + e];
    __syncthreads();
    int j = t & 63, kg = t >> 6;
    ull acc[4];
    #pragma unroll
    for (int q = 0; q < 4; q++) acc[q] = 0ull;
    for (int ii = 0; ii < 64; ii++) {
        float2 wv = Was[ii * 64 + j];
        ull wr2 = pack2(wv.x, wv.x), wi2 = pack2(wv.y, wv.y);
        #pragma unroll
        for (int q = 0; q < 4; q++) {
            const ull* y2 = (const ull*)&Ys4[(kg * 4 + q) * 64 + ii];
            ffma2(acc[q], wr2, y2[0]);
            ffma2(acc[q], wi2, y2[1]);
        }
    }
    #pragma unroll
    for (int q = 0; q < 4; q++) {
        float re, im;
        unpack2(acc[q], re, im);
        gT[(size_t)blk * 1024 + (kg * 4 + q) * 64 + j] = make_float2(re, im);
    }
}

// ---------------- K3b (packed: Ts4 float4 + ffma2) ----------------
// dyn smem: Ts4 32KB + Wb0 32KB + Wb1 32KB = 98304 B
__global__ __launch_bounds__(256) void k3b_mix2() {
    extern __shared__ __align__(16) char smb[];
    float4* Ts4 = (float4*)smb;                 // 2048
    float2* Wb0 = (float2*)(smb + 32768);       // 4096
    float2* Wb1 = (float2*)(smb + 65536);       // 4096
    int blk = blockIdx.x, b = blk >> 4, ky = blk & 15, t = threadIdx.x;
    for (int e = t; e < 2048; e += 256) {
        int s_ = e >> 6, j = e & 63;
        float2 tv = gT[(((size_t)b * 32 + s_) * 16 + ky) * 64 + j];
        Ts4[e] = make_float4(tv.x, tv.y, -tv.y, tv.x);
    }
    for (int e = t; e < 4096; e += 256) {
        Wb0[e] = gW1t[ky * 4096 + e];
        Wb1[e] = gW3t[ky * 4096 + e];
    }
    __syncthreads();
    int o = t & 63, sg = t >> 6;
    const float2* Wb = (sg < 2) ? Wb0 : Wb1;
    ull acc[8];
    #pragma unroll
    for (int q = 0; q < 8; q++) acc[q] = 0ull;
    for (int j = 0; j < 64; j++) {
        float2 wv = Wb[j * 64 + o];
        ull wr2 = pack2(wv.x, wv.x), wi2 = pack2(wv.y, wv.y);
        #pragma unroll
        for (int q = 0; q < 8; q++) {
            ulonglong2 tp = *(const ulonglong2*)&Ts4[(sg * 8 + q) * 64 + j];
            ffma2(acc[q], wr2, tp.x);
            ffma2(acc[q], wi2, tp.y);
        }
    }
    #pragma unroll
    for (int q = 0; q < 8; q++) {
        int s_ = sg * 8 + q;
        float re, im;
        unpack2(acc[q], re, im);
        gF[(size_t)blk * 2048 + s_ * 64 + o] = make_float2(re, im);
    }
}

// ---------------- K4: inverse DFT over kx ----------------
__global__ __launch_bounds__(256) void k4_invkx() {
    __shared__ float2 Fs[32 * 64];
    __shared__ float4 PQ[16 * 64];
    __shared__ float4 tab4[128];
    int blk = blockIdx.x, b = blk >> 4, ky = blk & 15, t = threadIdx.x;
    for (int e = t; e < 2048; e += 256) Fs[e] = gF[(size_t)blk * 2048 + e];
    if (t < 128) {
        float sv, cv;
        sincospif((float)t * (1.0f / 64.0f), &sv, &cv);
        tab4[t] = make_float4(cv, cv, sv, sv);
    }
    __syncthreads();
    for (int e = t; e < 1024; e += 256) {
        int k = e >> 6, o = e & 63;
        if (k == 0) {
            float2 f = Fs[16 * 64 + o];
            PQ[o] = make_float4(f.x, f.y, f.y, -f.x);
        } else {
            float2 fa = Fs[k * 64 + o], fb = Fs[(32 - k) * 64 + o];
            PQ[k * 64 + o] = make_float4(fa.x + fb.x, fa.y + fb.y, -(fa.y - fb.y), fa.x - fb.x);
        }
    }
    __syncthreads();

    int o = t & 63, ug = t >> 6;
    float2 F0 = Fs[o];
    float4 pq[16];
    #pragma unroll
    for (int k = 0; k < 16; k++) pq[k] = PQ[k * 64 + o];

    for (int q = 0; q < 32; q++) {
        int u = ug * 32 + q;
        ull acc = pack2(F0.x, F0.y);
        int idx = u;
        #pragma unroll
        for (int k = 1; k < 16; k++) {
            const ull* cs = (const ull*)&tab4[idx];
            ffma2(acc, cs[0], ((const ull*)&pq[k])[0]);
            ffma2(acc, cs[1], ((const ull*)&pq[k])[1]);
            idx = (idx + u) & 127;
        }
        {
            const ull* cs = (const ull*)&tab4[(16 * u) & 127];
            ffma2(acc, cs[0], ((const ull*)&pq[0])[0]);
            ffma2(acc, cs[1], ((const ull*)&pq[0])[1]);
        }
        float re, im;
        unpack2(acc, re, im);
        gD[(((size_t)b * 128 + u) * 16 + ky) * 64 + o] = make_float2(re, im);
    }
}

// ---------------- K5: inverse ky + both MLPs (W frags from global) ----------------
#define OFF_XHI   0u
#define OFF_XLO   18432u
#define OFF_HHI   36864u
#define OFF_HLO   71680u
#define SMEM_K5   106496

__global__ __launch_bounds__(256, 2) void k5_mma(
    const float* __restrict__ bb1, const float* __restrict__ bb2,
    const float* __restrict__ fb1, const float* __restrict__ fb2,
    float* __restrict__ out) {
    extern __shared__ __align__(16) char sm[];
    unsigned sb = smem_u32(sm);
    int t = threadIdx.x, w = t >> 5, l = t & 31;
    int blk = blockIdx.x;

    float2* E2 = (float2*)(sm + OFF_HHI);
    float* Dp = (float*)(sm + OFF_HHI + 32768);
    for (int e = t; e < 2048; e += 256)
        ((float4*)E2)[e] = ((const float4*)gE2)[e];
    for (int e = t; e < 1024; e += 256) {
        int ky = e >> 6, o = e & 63;
        float2 d = gD[(size_t)blk * 1024 + e];
        float sc = (ky ? 2.0f : 1.0f) * (1.0f / 16384.0f);
        Dp[(2 * ky) * 64 + o] = d.x * sc;
        Dp[(2 * ky + 1) * 64 + o] = -d.y * sc;
    }
    __syncthreads();

    {
        int rg = t >> 4, cg = t & 15;
        int r0 = rg * 8, c0 = cg * 4;
        ull acc[8][2];
        #pragma unroll
        for (int j = 0; j < 8; j++) { acc[j][0] = 0ull; acc[j][1] = 0ull; }
        const ull* E2u = (const ull*)E2;
        for (int c = 0; c < 32; c++) {
            ulonglong2 dd = *(const ulonglong2*)&Dp[c * 64 + c0];
            #pragma unroll
            for (int j = 0; j < 8; j++) {
                ull e2 = E2u[(r0 + j) * 32 + c];
                ffma2(acc[j][0], e2, dd.x);
                ffma2(acc[j][1], e2, dd.y);
            }
        }
        #pragma unroll
        for (int j = 0; j < 8; j++) {
            float x0, x1, x2, x3;
            unpack2(acc[j][0], x0, x1);
            unpack2(acc[j][1], x2, x3);
            unsigned hA, lA, hB, lB;
            split2(x0, x1, hA, lA);
            split2(x2, x3, hB, lB);
            unsigned relb = (unsigned)(r0 + j) * 144u + (unsigned)c0 * 2u;
            *(uint2*)(sm + OFF_XHI + relb) = make_uint2(hA, hB);
            *(uint2*)(sm + OFF_XLO + relb) = make_uint2(lA, lB);
        }
    }

    size_t rowBase = (size_t)blk * 128;
    int wm = w & 1, wn = w >> 1;
    unsigned kA = ((l >> 4) & 1) * 8;
    unsigned rowA = (unsigned)(wm * 64 + (l & 7) + ((l >> 3) & 1) * 8);

    for (int p = 0; p < 2; p++) {
        __syncthreads();
        const float* B1 = p ? fb1 : bb1;
        const float* B2 = p ? fb2 : bb2;

        {
            float acc[4][4][4];
            #pragma unroll
            for (int a = 0; a < 4; a++)
                #pragma unroll
                for (int b = 0; b < 4; b++)
                    #pragma unroll
                    for (int c = 0; c < 4; c++) acc[a][b][c] = 0.f;

            unsigned aXhi = sb + OFF_XHI + rowA * 144 + kA * 2;
            unsigned aXlo = sb + OFF_XLO + rowA * 144 + kA * 2;
            const uint4* F1 = (const uint4*)gF1 + ((p * 4 + wn) * 4) * 4 * 32 + l;

            #pragma unroll
            for (int ki = 0; ki < 4; ki++) {
                unsigned kb = ki * 32;
                unsigned ah[4][4], al[4][4];
                uint4 bh[2], bl[2];
                #pragma unroll
                for (int mf = 0; mf < 4; mf++) {
                    ldm4(ah[mf], aXhi + mf * (16 * 144) + kb);
                    ldm4(al[mf], aXlo + mf * (16 * 144) + kb);
                }
                bh[0] = F1[(ki * 4 + 0) * 32];
                bh[1] = F1[(ki * 4 + 1) * 32];
                bl[0] = F1[(ki * 4 + 2) * 32];
                bl[1] = F1[(ki * 4 + 3) * 32];
                const unsigned* bhp = (const unsigned*)bh;
                const unsigned* blp = (const unsigned*)bl;
                #pragma unroll
                for (int mf = 0; mf < 4; mf++)
                    #pragma unroll
                    for (int nf = 0; nf < 4; nf++)
                        mma16816(acc[mf][nf], ah[mf], &bhp[nf * 2]);
                #pragma unroll
                for (int mf = 0; mf < 4; mf++)
                    #pragma unroll
                    for (int nf = 0; nf < 4; nf++)
                        mma16816(acc[mf][nf], ah[mf], &blp[nf * 2]);
                #pragma unroll
                for (int mf = 0; mf < 4; mf++)
                    #pragma unroll
                    for (int nf = 0; nf < 4; nf++)
                        mma16816(acc[mf][nf], al[mf], &bhp[nf * 2]);
            }
            int rbase = wm * 64 + (l >> 2);
            int ncol = 2 * (l & 3);
            #pragma unroll
            for (int nf = 0; nf < 4; nf++) {
                int n = wn * 32 + nf * 8 + ncol;
                float2 bv = *(const float2*)(B1 + n);
                #pragma unroll
                for (int mf = 0; mf < 4; mf++)
                    #pragma unroll
                    for (int half = 0; half < 2; half++) {
                        int r = rbase + mf * 16 + half * 8;
                        float v0 = fmaxf(acc[mf][nf][half * 2 + 0] + bv.x, 0.f);
                        float v1 = fmaxf(acc[mf][nf][half * 2 + 1] + bv.y, 0.f);
                        unsigned hp, lp;
                        split2(v0, v1, hp, lp);
                        unsigned off = (unsigned)r * 272u + (unsigned)n * 2u;
                        *(unsigned*)(sm + OFF_HHI + off) = hp;
                        *(unsigned*)(sm + OFF_HLO + off) = lp;
                    }
            }
        }
        __syncthreads();

        {
            float acc[4][2][4];
            #pragma unroll
            for (int a = 0; a < 4; a++)
                #pragma unroll
                for (int b = 0; b < 2; b++)
                    #pragma unroll
                    for (int c = 0; c < 4; c++) acc[a][b][c] = 0.f;

            unsigned aHhi = sb + OFF_HHI + rowA * 272 + kA * 2;
            unsigned aHlo = sb + OFF_HLO + rowA * 272 + kA * 2;
            const uint4* F2 = (const uint4*)gF2 + ((p * 4 + wn) * 8) * 2 * 32 + l;

            #pragma unroll
            for (int ki = 0; ki < 8; ki++) {
                unsigned kb = ki * 32;
                unsigned ah[4][4], al[4][4];
                uint4 bh4 = F2[(ki * 2 + 0) * 32];
                uint4 bl4 = F2[(ki * 2 + 1) * 32];
                const unsigned* bh = (const unsigned*)&bh4;
                const unsigned* bl = (const unsigned*)&bl4;
                #pragma unroll
                for (int mf = 0; mf < 4; mf++) {
                    ldm4(ah[mf], aHhi + mf * (16 * 272) + kb);
                    ldm4(al[mf], aHlo + mf * (16 * 272) + kb);
                }
                #pragma unroll
                for (int mf = 0; mf < 4; mf++)
                    #pragma unroll
                    for (int nf = 0; nf < 2; nf++)
                        mma16816(acc[mf][nf], ah[mf], &bh[nf * 2]);
                #pragma unroll
                for (int mf = 0; mf < 4; mf++)
                    #pragma unroll
                    for (int nf = 0; nf < 2; nf++)
                        mma16816(acc[mf][nf], ah[mf], &bl[nf * 2]);
                #pragma unroll
                for (int mf = 0; mf < 4; mf++)
                    #pragma unroll
                    for (int nf = 0; nf < 2; nf++)
                        mma16816(acc[mf][nf], al[mf], &bh[nf * 2]);
            }
            float* outp = out + (size_t)p * 33554432ull + rowBase * 64;
            int rbase = wm * 64 + (l >> 2);
            int ncol = 2 * (l & 3);
            #pragma unroll
            for (int nf = 0; nf < 2; nf++) {
                int n = wn * 16 + nf * 8 + ncol;
                float2 bv = *(const float2*)(B2 + n);
                #pragma unroll
                for (int mf = 0; mf < 4; mf++)
                    #pragma unroll
                    for (int half = 0; half < 2; half++) {
                        int r = rbase + mf * 16 + half * 8;
                        float2 val = make_float2(acc[mf][nf][half * 2 + 0] + bv.x,
                                                 acc[mf][nf][half * 2 + 1] + bv.y);
                        *(float2*)(outp + (size_t)r * 64 + n) = val;
                    }
            }
        }
    }
}

// ---------------------------------------------------------------------------
extern "C" void kernel_launch(void* const* d_in, const int* in_sizes, int n_in,
                              void* d_out, int out_size) {
    const float* x = (const float*)d_in[0];
    const float* w0 = (const float*)d_in[1];
    const float* w1 = (const float*)d_in[2];
    const float* w2 = (const float*)d_in[3];
    const float* w3 = (const float*)d_in[4];
    const float* bw1 = (const float*)d_in[5];
    const float* bb1 = (const float*)d_in[6];
    const float* bw2 = (const float*)d_in[7];
    const float* bb2 = (const float*)d_in[8];
    const float* fw1 = (const float*)d_in[9];
    const float* fb1 = (const float*)d_in[10];
    const float* fw2 = (const float*)d_in[11];
    const float* fb2 = (const float*)d_in[12];
    float* out = (float*)d_out;

    const int SM_PF = 71680;
    const int SM_K1 = 40960;
    const int SM_K2 = 81920;
    const int SM_K3B = 98304;
    cudaFuncSetAttribute(prep_frag, cudaFuncAttributeMaxDynamicSharedMemorySize, SM_PF);
    cudaFuncSetAttribute(k1_stageA, cudaFuncAttributeMaxDynamicSharedMemorySize, SM_K1);
    cudaFuncSetAttribute(k2_stageB, cudaFuncAttributeMaxDynamicSharedMemorySize, SM_K2);
    cudaFuncSetAttribute(k3b_mix2, cudaFuncAttributeMaxDynamicSharedMemorySize, SM_K3B);
    cudaFuncSetAttribute(k5_mma, cudaFuncAttributeMaxDynamicSharedMemorySize, SMEM_K5);

    prep_frag<<<2, 256, SM_PF>>>(bw1, fw1, bw2, fw2);
    prep_spec<<<256, 256>>>(w0, w1, w2, w3);
    prep_e<<<40, 256>>>();
    k1_stageA<<<NB * 128, 256, SM_K1>>>(x);
    k2_stageB<<<NB * 16, 256, SM_K2>>>();
    k3a_mix1<<<NB * 32, 256>>>();
    k3b_mix2<<<NB * 16, 256, SM_K3B>>>();
    k4_invkx<<<NB * 16, 256>>>();
    k5_mma<<<NB * 128, 256, SMEM_K5>>>(bb1, bb2, fb1, fb2, out);
}

// round 13
// speedup vs baseline: 3.6060x; 1.0116x over previous
#include <cuda_runtime.h>
#include <cuda_bf16.h>
#include <math.h>

#define NB 32

// ---------------- device globals ----------------
__device__ float2 gA[NB * 16 * 128 * 64];  // [b][ky][m][i]
__device__ float2 gY[NB * 32 * 16 * 64];
__device__ float2 gT[NB * 32 * 16 * 64];
__device__ float2 gD[NB * 128 * 16 * 64];
// transposed spectral weights
__device__ float2 gW0t[65536], gW1t[65536], gW2t[65536], gW3t[65536];
// duplicated inverse-ky basis: E2[v*32+c] = {e,e}
__device__ __align__(16) float2 gE2[4096];
// packed twiddles: k1 [kg][n][4] {cos,-sin}; k2 [ug][m][4] {cos,sin}
__device__ __align__(16) float2 gTwK1p[4096];
__device__ __align__(16) float2 gTw2p[2048];
// pre-built mma B-fragments
__device__ __align__(16) unsigned gF1[16384];
__device__ __align__(16) unsigned gF2[16384];

// ---------------- helpers ----------------
typedef unsigned long long ull;
__device__ __forceinline__ ull pack2(float lo, float hi) {
    ull r;
    asm("mov.b64 %0, {%1,%2};" : "=l"(r) : "f"(lo), "f"(hi));
    return r;
}
__device__ __forceinline__ void unpack2(ull v, float& lo, float& hi) {
    asm("mov.b64 {%0,%1}, %2;" : "=f"(lo), "=f"(hi) : "l"(v));
}
__device__ __forceinline__ void ffma2(ull& d, ull a, ull b) {
    asm("fma.rn.f32x2 %0, %1, %2, %0;" : "+l"(d) : "l"(a), "l"(b));
}
__device__ __forceinline__ unsigned smem_u32(const void* p) {
    unsigned a;
    asm("{ .reg .u64 t; cvta.to.shared.u64 t, %1; cvt.u32.u64 %0, t; }" : "=r"(a) : "l"(p));
    return a;
}
__device__ __forceinline__ void ldm4(unsigned* r, unsigned addr) {
    asm volatile("ldmatrix.sync.aligned.m8n8.x4.shared.b16 {%0,%1,%2,%3}, [%4];"
                 : "=r"(r[0]), "=r"(r[1]), "=r"(r[2]), "=r"(r[3]) : "r"(addr));
}
__device__ __forceinline__ void mma16816(float* c, const unsigned* a, const unsigned* b) {
    asm volatile("mma.sync.aligned.m16n8k16.row.col.f32.bf16.bf16.f32 "
                 "{%0,%1,%2,%3}, {%4,%5,%6,%7}, {%8,%9}, {%0,%1,%2,%3};"
                 : "+f"(c[0]), "+f"(c[1]), "+f"(c[2]), "+f"(c[3])
                 : "r"(a[0]), "r"(a[1]), "r"(a[2]), "r"(a[3]), "r"(b[0]), "r"(b[1]));
}
__device__ __forceinline__ void split2(float v0, float v1, unsigned& hp, unsigned& lp) {
    asm("cvt.rn.bf16x2.f32 %0, %1, %2;" : "=r"(hp) : "f"(v1), "f"(v0));
    float h0 = __uint_as_float(hp << 16);
    float h1 = __uint_as_float(hp & 0xFFFF0000u);
    float l0 = v0 - h0, l1 = v1 - h1;
    asm("cvt.rn.bf16x2.f32 %0, %1, %2;" : "=r"(lp) : "f"(l1), "f"(l0));
}

// ---------------- prep: B-fragments via real ldmatrix ----------------
__global__ void prep_frag(const float* __restrict__ bw1, const float* __restrict__ fw1,
                          const float* __restrict__ bw2, const float* __restrict__ fw2) {
    extern __shared__ __align__(16) char ps[];
    int p = blockIdx.x, t = threadIdx.x, w = t >> 5, l = t & 31;
    const float* W1 = p ? fw1 : bw1;
    const float* W2 = p ? fw2 : bw2;
    for (int e = t; e < 9216; e += 256) {
        int n = e / 72, k = e % 72;
        float v = (k < 64) ? W1[k * 128 + n] : 0.f;
        __nv_bfloat16 hi = __float2bfloat16(v);
        __nv_bfloat16 lo = __float2bfloat16(v - __bfloat162float(hi));
        ((unsigned short*)(ps + 0))[e] = __bfloat16_as_ushort(hi);
        ((unsigned short*)(ps + 18432))[e] = __bfloat16_as_ushort(lo);
    }
    for (int e = t; e < 8704; e += 256) {
        int n = e / 136, k = e % 136;
        float v = (k < 128) ? W2[k * 64 + n] : 0.f;
        __nv_bfloat16 hi = __float2bfloat16(v);
        __nv_bfloat16 lo = __float2bfloat16(v - __bfloat162float(hi));
        ((unsigned short*)(ps + 36864))[e] = __bfloat16_as_ushort(hi);
        ((unsigned short*)(ps + 54272))[e] = __bfloat16_as_ushort(lo);
    }
    __syncthreads();
    unsigned sb = smem_u32(ps);
    unsigned kB = ((l >> 3) & 1) * 8;
    if (w < 4) {
        int wn = w;
        unsigned rowB = (unsigned)(wn * 32 + ((l >> 4) << 3) + (l & 7));
        for (int ki = 0; ki < 4; ki++)
            for (int term = 0; term < 2; term++)
                for (int h2 = 0; h2 < 2; h2++) {
                    unsigned r[4];
                    ldm4(r, sb + (term ? 18432u : 0u) + rowB * 144 + kB * 2 +
                            (unsigned)ki * 32 + (unsigned)h2 * (16 * 144));
                    ((uint4*)gF1)[((((p * 4 + wn) * 4 + ki) * 2 + term) * 2 + h2) * 32 + l] =
                        make_uint4(r[0], r[1], r[2], r[3]);
                }
    } else {
        int wn = w - 4;
        unsigned rowB = (unsigned)(wn * 16 + ((l >> 4) << 3) + (l & 7));
        for (int ki = 0; ki < 8; ki++)
            for (int term = 0; term < 2; term++) {
                unsigned r[4];
                ldm4(r, sb + (term ? 54272u : 36864u) + rowB * 272 + kB * 2 + (unsigned)ki * 32);
                ((uint4*)gF2)[(((p * 4 + wn) * 8 + ki) * 2 + term) * 32 + l] =
                    make_uint4(r[0], r[1], r[2], r[3]);
            }
    }
}

// ---------------- prep: transpose spectral weights ----------------
__global__ void prep_spec(const float* __restrict__ w0, const float* __restrict__ w1,
                          const float* __restrict__ w2, const float* __restrict__ w3) {
    int e = blockIdx.x * 256 + threadIdx.x;
    int lx = e >> 12, ij = e & 4095;
    int src = ij * 16 + lx;
    gW0t[e] = ((const float2*)w0)[src];
    gW1t[e] = ((const float2*)w1)[src];
    gW2t[e] = ((const float2*)w2)[src];
    gW3t[e] = ((const float2*)w3)[src];
}

// ---------------- prep: E table + packed twiddles ----------------
__global__ void prep_e() {
    int e = blockIdx.x * 256 + threadIdx.x;
    if (e < 4096) {
        int v = e >> 5, c = e & 31, k = c >> 1;
        float sv, cv;
        sincospif((float)(v * k) * (1.0f / 64.0f), &sv, &cv);
        float val = (c & 1) ? sv : cv;
        gE2[e] = make_float2(val, val);
    } else if (e < 8192) {
        int e2 = e - 4096;
        int kg = e2 >> 8, n = (e2 >> 2) & 63, j = e2 & 3;
        int ky = kg * 4 + j;
        float sv, cv;
        sincospif((float)(ky * n) * (1.0f / 64.0f), &sv, &cv);
        gTwK1p[e2] = make_float2(cv, -sv);
    } else if (e < 10240) {
        int e2 = e - 8192;
        int ug = e2 >> 9, m = (e2 >> 2) & 127, q = e2 & 3;
        int k = ug * 4 + q + 1;
        float sv, cv;
        sincospif((float)(k * m) * (1.0f / 64.0f), &sv, &cv);
        gTw2p[e2] = make_float2(cv, sv);
    }
}

// ---------------- K1: forward DFT along n (fold-on-load) ----------------
__global__ __launch_bounds__(256) void k1_stageA(const float* __restrict__ x) {
    extern __shared__ float smf[];
    float2* sd = (float2*)smf;
    float2* twk = (float2*)(smf + 8064);
    float* r064 = smf + 8064 + 2048;
    int bm = blockIdx.x, t = threadIdx.x;
    const float* xf = x + (size_t)bm * 8192;
    const float4* xg = (const float4*)xf;

    if (t < 64) r064[t] = xf[t];
    else if (t < 128) r064[t] = xf[4096 + (t - 64)];
    #pragma unroll
    for (int e = t; e < 512; e += 256) ((float4*)twk)[e] = ((const float4*)gTwK1p)[e];
    for (int e = t; e < 1008; e += 256) {
        int n = 1 + (e >> 4), i4 = e & 15;
        float4 a = xg[n * 16 + i4];
        float4 b = xg[(128 - n) * 16 + i4];
        float4* dst = (float4*)&sd[(n - 1) * 64 + i4 * 4];
        dst[0] = make_float4(a.x + b.x, a.x - b.x, a.y + b.y, a.y - b.y);
        dst[1] = make_float4(a.z + b.z, a.z - b.z, a.w + b.w, a.w - b.w);
    }
    __syncthreads();

    int i = t & 63, kg = t >> 6;
    int ky0 = kg * 4;
    float x0 = r064[i], x64 = r064[64 + i];
    const ull* sd2 = (const ull*)sd + i;
    const ulonglong2* twp = (const ulonglong2*)twk + kg * 128;
    ull a0 = pack2(x0 + x64, 0.f);
    ull a1 = pack2(x0 - x64, 0.f);
    ull a2 = pack2(x0 + x64, 0.f);
    ull a3 = pack2(x0 - x64, 0.f);
    #pragma unroll
    for (int n = 1; n <= 63; n++) {
        ull sdv = sd2[(n - 1) * 64];
        ulonglong2 t01 = twp[n * 2];
        ulonglong2 t23 = twp[n * 2 + 1];
        ffma2(a0, sdv, t01.x);
        ffma2(a1, sdv, t01.y);
        ffma2(a2, sdv, t23.x);
        ffma2(a3, sdv, t23.y);
    }
    int b = bm >> 7, m = bm & 127;
    float2* outp = gA + ((size_t)b * 16) * 8192 + (size_t)m * 64 + i;
    float lo, hi;
    unpack2(a0, lo, hi); outp[(size_t)(ky0 + 0) * 8192] = make_float2(lo, hi);
    unpack2(a1, lo, hi); outp[(size_t)(ky0 + 1) * 8192] = make_float2(lo, hi);
    unpack2(a2, lo, hi); outp[(size_t)(ky0 + 2) * 8192] = make_float2(lo, hi);
    unpack2(a3, lo, hi); outp[(size_t)(ky0 + 3) * 8192] = make_float2(lo, hi);
}

// ---------------- K2: forward DFT along m (two half-passes, 48KB smem) ----------------
// dyn smem: As 32KB (4096 f2) + tw 16KB = 49152 B
__global__ __launch_bounds__(256) void k2_stageB() {
    extern __shared__ float2 sm2[];
    float2* As = sm2;         // 4096: half of m
    float2* tw = sm2 + 4096;  // 2048
    int blk = blockIdx.x, b = blk >> 4, ky = blk & 15, t = threadIdx.x;
    #pragma unroll
    for (int e = t; e < 1024; e += 256) ((float4*)tw)[e] = ((const float4*)gTw2p)[e];

    int i = t & 63, ug = t >> 6;
    ull acc12[4], acc34[4];
    #pragma unroll
    for (int q = 0; q < 4; q++) { acc12[q] = 0ull; acc34[q] = 0ull; }
    const ulonglong2* twp = (const ulonglong2*)tw + ug * 256;
    float sx = 0.f, sy = 0.f;

    const float4* src = (const float4*)(gA + (size_t)blk * 8192);
    #pragma unroll
    for (int ph = 0; ph < 2; ph++) {
        __syncthreads();
        #pragma unroll
        for (int e = t; e < 2048; e += 256) ((float4*)As)[e] = src[ph * 2048 + e];
        __syncthreads();
        #pragma unroll 4
        for (int mm = 0; mm < 64; mm++) {
            int m = ph * 64 + mm;
            float2 a = As[mm * 64 + i];
            ull axy = pack2(a.x, a.y), ayx = pack2(a.y, a.x);
            ulonglong2 t01 = twp[m * 2];
            ulonglong2 t23 = twp[m * 2 + 1];
            ffma2(acc12[0], axy, t01.x); ffma2(acc34[0], ayx, t01.x);
            ffma2(acc12[1], axy, t01.y); ffma2(acc34[1], ayx, t01.y);
            ffma2(acc12[2], axy, t23.x); ffma2(acc34[2], ayx, t23.x);
            ffma2(acc12[3], axy, t23.y); ffma2(acc34[3], ayx, t23.y);
            if (ug == 3) { sx += a.x; sy += a.y; }
        }
    }
    float2* yb = gY + (((size_t)b * 32) * 16 + ky) * 64 + i;
    #pragma unroll
    for (int q = 0; q < 4; q++) {
        int k = ug * 4 + q + 1;
        float u1, u2, u3, u4;
        unpack2(acc12[q], u1, u2);
        unpack2(acc34[q], u3, u4);
        if (k < 16) yb[(size_t)k * 1024] = make_float2(u1 + u2, u3 - u4);
        yb[(size_t)(32 - k) * 1024] = make_float2(u1 - u2, u3 + u4);
    }
    if (ug == 3) yb[0] = make_float2(sx, sy);
}

// ---------------- K3a ----------------
__global__ __launch_bounds__(256) void k3a_mix1() {
    __shared__ float4 Ys4[16 * 64];
    __shared__ float2 Was[64 * 64];
    int blk = blockIdx.x, s = blk & 31, lx = s & 15, t = threadIdx.x;
    const float2* wt = (s < 16) ? gW0t : gW2t;
    for (int e = t; e < 1024; e += 256) {
        float2 y = gY[(size_t)blk * 1024 + e];
        Ys4[e] = make_float4(y.x, y.y, -y.y, y.x);
    }
    for (int e = t; e < 4096; e += 256) Was[e] = wt[lx * 4096 + e];
    __syncthreads();
    int j = t & 63, kg = t >> 6;
    ull acc[4];
    #pragma unroll
    for (int q = 0; q < 4; q++) acc[q] = 0ull;
    for (int ii = 0; ii < 64; ii++) {
        float2 wv = Was[ii * 64 + j];
        ull wr2 = pack2(wv.x, wv.x), wi2 = pack2(wv.y, wv.y);
        #pragma unroll
        for (int q = 0; q < 4; q++) {
            const ull* y2 = (const ull*)&Ys4[(kg * 4 + q) * 64 + ii];
            ffma2(acc[q], wr2, y2[0]);
            ffma2(acc[q], wi2, y2[1]);
        }
    }
    #pragma unroll
    for (int q = 0; q < 4; q++) {
        float re, im;
        unpack2(acc[q], re, im);
        gT[(size_t)blk * 1024 + (kg * 4 + q) * 64 + j] = make_float2(re, im);
    }
}

// ---------------- K3b4 (fused): second channel mix + inverse DFT over kx ----------------
// dyn smem: Ts4 32KB @0 + Wb0 32KB @32K + Wb1 32KB @64K + tab4 2KB @96K = 100352 B
// After mix: Fs (16KB) aliases Wb0 @32K, PQ (16KB) aliases @48K.
__global__ __launch_bounds__(256) void k3b4_mix_inv() {
    extern __shared__ __align__(16) char smb[];
    float4* Ts4 = (float4*)smb;              // 2048
    float2* Wb0 = (float2*)(smb + 32768);    // 4096
    float2* Wb1 = (float2*)(smb + 65536);    // 4096
    float4* tab4 = (float4*)(smb + 98304);   // 128
    float2* Fs = (float2*)(smb + 32768);     // alias (after mix)
    float4* PQ = (float4*)(smb + 49152);     // alias (after mix)
    int blk = blockIdx.x, b = blk >> 4, ky = blk & 15, t = threadIdx.x;

    for (int e = t; e < 2048; e += 256) {
        int s_ = e >> 6, j = e & 63;
        float2 tv = gT[(((size_t)b * 32 + s_) * 16 + ky) * 64 + j];
        Ts4[e] = make_float4(tv.x, tv.y, -tv.y, tv.x);
    }
    for (int e = t; e < 4096; e += 256) {
        Wb0[e] = gW1t[ky * 4096 + e];
        Wb1[e] = gW3t[ky * 4096 + e];
    }
    if (t < 128) {
        float sv, cv;
        sincospif((float)t * (1.0f / 64.0f), &sv, &cv);
        tab4[t] = make_float4(cv, cv, sv, sv);
    }
    __syncthreads();

    int o = t & 63, sg = t >> 6;
    const float2* Wb = (sg < 2) ? Wb0 : Wb1;
    ull acc[8];
    #pragma unroll
    for (int q = 0; q < 8; q++) acc[q] = 0ull;
    for (int j = 0; j < 64; j++) {
        float2 wv = Wb[j * 64 + o];
        ull wr2 = pack2(wv.x, wv.x), wi2 = pack2(wv.y, wv.y);
        #pragma unroll
        for (int q = 0; q < 8; q++) {
            ulonglong2 tp = *(const ulonglong2*)&Ts4[(sg * 8 + q) * 64 + j];
            ffma2(acc[q], wr2, tp.x);
            ffma2(acc[q], wi2, tp.y);
        }
    }
    __syncthreads();  // Wb reads done; safe to overwrite Wb0 region with Fs
    #pragma unroll
    for (int q = 0; q < 8; q++) {
        int s_ = sg * 8 + q;
        float re, im;
        unpack2(acc[q], re, im);
        Fs[s_ * 64 + o] = make_float2(re, im);
    }
    __syncthreads();

    // build PQ pairs
    for (int e = t; e < 1024; e += 256) {
        int k = e >> 6, oo = e & 63;
        if (k == 0) {
            float2 f = Fs[16 * 64 + oo];
            PQ[oo] = make_float4(f.x, f.y, f.y, -f.x);
        } else {
            float2 fa = Fs[k * 64 + oo], fb = Fs[(32 - k) * 64 + oo];
            PQ[k * 64 + oo] = make_float4(fa.x + fb.x, fa.y + fb.y, -(fa.y - fb.y), fa.x - fb.x);
        }
    }
    __syncthreads();

    int ug = t >> 6;
    float2 F0 = Fs[o];
    float4 pq[16];
    #pragma unroll
    for (int k = 0; k < 16; k++) pq[k] = PQ[k * 64 + o];

    for (int q = 0; q < 32; q++) {
        int u = ug * 32 + q;
        ull acc2 = pack2(F0.x, F0.y);
        int idx = u;
        #pragma unroll
        for (int k = 1; k < 16; k++) {
            const ull* cs = (const ull*)&tab4[idx];
            ffma2(acc2, cs[0], ((const ull*)&pq[k])[0]);
            ffma2(acc2, cs[1], ((const ull*)&pq[k])[1]);
            idx = (idx + u) & 127;
        }
        {
            const ull* cs = (const ull*)&tab4[(16 * u) & 127];
            ffma2(acc2, cs[0], ((const ull*)&pq[0])[0]);
            ffma2(acc2, cs[1], ((const ull*)&pq[0])[1]);
        }
        float re, im;
        unpack2(acc2, re, im);
        gD[(((size_t)b * 128 + u) * 16 + ky) * 64 + o] = make_float2(re, im);
    }
}

// ---------------- K5: inverse ky + both MLPs (W frags from global) ----------------
#define OFF_XHI   0u
#define OFF_XLO   18432u
#define OFF_HHI   36864u
#define OFF_HLO   71680u
#define SMEM_K5   106496

__global__ __launch_bounds__(256, 2) void k5_mma(
    const float* __restrict__ bb1, const float* __restrict__ bb2,
    const float* __restrict__ fb1, const float* __restrict__ fb2,
    float* __restrict__ out) {
    extern __shared__ __align__(16) char sm[];
    unsigned sb = smem_u32(sm);
    int t = threadIdx.x, w = t >> 5, l = t & 31;
    int blk = blockIdx.x;

    float2* E2 = (float2*)(sm + OFF_HHI);
    float* Dp = (float*)(sm + OFF_HHI + 32768);
    for (int e = t; e < 2048; e += 256)
        ((float4*)E2)[e] = ((const float4*)gE2)[e];
    for (int e = t; e < 1024; e += 256) {
        int ky = e >> 6, o = e & 63;
        float2 d = gD[(size_t)blk * 1024 + e];
        float sc = (ky ? 2.0f : 1.0f) * (1.0f / 16384.0f);
        Dp[(2 * ky) * 64 + o] = d.x * sc;
        Dp[(2 * ky + 1) * 64 + o] = -d.y * sc;
    }
    __syncthreads();

    {
        int rg = t >> 4, cg = t & 15;
        int r0 = rg * 8, c0 = cg * 4;
        ull acc[8][2];
        #pragma unroll
        for (int j = 0; j < 8; j++) { acc[j][0] = 0ull; acc[j][1] = 0ull; }
        const ull* E2u = (const ull*)E2;
        for (int c = 0; c < 32; c++) {
            ulonglong2 dd = *(const ulonglong2*)&Dp[c * 64 + c0];
            #pragma unroll
            for (int j = 0; j < 8; j++) {
                ull e2 = E2u[(r0 + j) * 32 + c];
                ffma2(acc[j][0], e2, dd.x);
                ffma2(acc[j][1], e2, dd.y);
            }
        }
        #pragma unroll
        for (int j = 0; j < 8; j++) {
            float x0, x1, x2, x3;
            unpack2(acc[j][0], x0, x1);
            unpack2(acc[j][1], x2, x3);
            unsigned hA, lA, hB, lB;
            split2(x0, x1, hA, lA);
            split2(x2, x3, hB, lB);
            unsigned relb = (unsigned)(r0 + j) * 144u + (unsigned)c0 * 2u;
            *(uint2*)(sm + OFF_XHI + relb) = make_uint2(hA, hB);
            *(uint2*)(sm + OFF_XLO + relb) = make_uint2(lA, lB);
        }
    }

    size_t rowBase = (size_t)blk * 128;
    int wm = w & 1, wn = w >> 1;
    unsigned kA = ((l >> 4) & 1) * 8;
    unsigned rowA = (unsigned)(wm * 64 + (l & 7) + ((l >> 3) & 1) * 8);

    for (int p = 0; p < 2; p++) {
        __syncthreads();
        const float* B1 = p ? fb1 : bb1;
        const float* B2 = p ? fb2 : bb2;

        {
            float acc[4][4][4];
            #pragma unroll
            for (int a = 0; a < 4; a++)
                #pragma unroll
                for (int b = 0; b < 4; b++)
                    #pragma unroll
                    for (int c = 0; c < 4; c++) acc[a][b][c] = 0.f;

            unsigned aXhi = sb + OFF_XHI + rowA * 144 + kA * 2;
            unsigned aXlo = sb + OFF_XLO + rowA * 144 + kA * 2;
            const uint4* F1 = (const uint4*)gF1 + ((p * 4 + wn) * 4) * 4 * 32 + l;

            #pragma unroll
            for (int ki = 0; ki < 4; ki++) {
                unsigned kb = ki * 32;
                unsigned ah[4][4], al[4][4];
                uint4 bh[2], bl[2];
                #pragma unroll
                for (int mf = 0; mf < 4; mf++) {
                    ldm4(ah[mf], aXhi + mf * (16 * 144) + kb);
                    ldm4(al[mf], aXlo + mf * (16 * 144) + kb);
                }
                bh[0] = F1[(ki * 4 + 0) * 32];
                bh[1] = F1[(ki * 4 + 1) * 32];
                bl[0] = F1[(ki * 4 + 2) * 32];
                bl[1] = F1[(ki * 4 + 3) * 32];
                const unsigned* bhp = (const unsigned*)bh;
                const unsigned* blp = (const unsigned*)bl;
                #pragma unroll
                for (int mf = 0; mf < 4; mf++)
                    #pragma unroll
                    for (int nf = 0; nf < 4; nf++)
                        mma16816(acc[mf][nf], ah[mf], &bhp[nf * 2]);
                #pragma unroll
                for (int mf = 0; mf < 4; mf++)
                    #pragma unroll
                    for (int nf = 0; nf < 4; nf++)
                        mma16816(acc[mf][nf], ah[mf], &blp[nf * 2]);
                #pragma unroll
                for (int mf = 0; mf < 4; mf++)
                    #pragma unroll
                    for (int nf = 0; nf < 4; nf++)
                        mma16816(acc[mf][nf], al[mf], &bhp[nf * 2]);
            }
            int rbase = wm * 64 + (l >> 2);
            int ncol = 2 * (l & 3);
            #pragma unroll
            for (int nf = 0; nf < 4; nf++) {
                int n = wn * 32 + nf * 8 + ncol;
                float2 bv = *(const float2*)(B1 + n);
                #pragma unroll
                for (int mf = 0; mf < 4; mf++)
                    #pragma unroll
                    for (int half = 0; half < 2; half++) {
                        int r = rbase + mf * 16 + half * 8;
                        float v0 = fmaxf(acc[mf][nf][half * 2 + 0] + bv.x, 0.f);
                        float v1 = fmaxf(acc[mf][nf][half * 2 + 1] + bv.y, 0.f);
                        unsigned hp, lp;
                        split2(v0, v1, hp, lp);
                        unsigned off = (unsigned)r * 272u + (unsigned)n * 2u;
                        *(unsigned*)(sm + OFF_HHI + off) = hp;
                        *(unsigned*)(sm + OFF_HLO + off) = lp;
                    }
            }
        }
        __syncthreads();

        {
            float acc[4][2][4];
            #pragma unroll
            for (int a = 0; a < 4; a++)
                #pragma unroll
                for (int b = 0; b < 2; b++)
                    #pragma unroll
                    for (int c = 0; c < 4; c++) acc[a][b][c] = 0.f;

            unsigned aHhi = sb + OFF_HHI + rowA * 272 + kA * 2;
            unsigned aHlo = sb + OFF_HLO + rowA * 272 + kA * 2;
            const uint4* F2 = (const uint4*)gF2 + ((p * 4 + wn) * 8) * 2 * 32 + l;

            #pragma unroll
            for (int ki = 0; ki < 8; ki++) {
                unsigned kb = ki * 32;
                unsigned ah[4][4], al[4][4];
                uint4 bh4 = F2[(ki * 2 + 0) * 32];
                uint4 bl4 = F2[(ki * 2 + 1) * 32];
                const unsigned* bh = (const unsigned*)&bh4;
                const unsigned* bl = (const unsigned*)&bl4;
                #pragma unroll
                for (int mf = 0; mf < 4; mf++) {
                    ldm4(ah[mf], aHhi + mf * (16 * 272) + kb);
                    ldm4(al[mf], aHlo + mf * (16 * 272) + kb);
                }
                #pragma unroll
                for (int mf = 0; mf < 4; mf++)
                    #pragma unroll
                    for (int nf = 0; nf < 2; nf++)
                        mma16816(acc[mf][nf], ah[mf], &bh[nf * 2]);
                #pragma unroll
                for (int mf = 0; mf < 4; mf++)
                    #pragma unroll
                    for (int nf = 0; nf < 2; nf++)
                        mma16816(acc[mf][nf], ah[mf], &bl[nf * 2]);
                #pragma unroll
                for (int mf = 0; mf < 4; mf++)
                    #pragma unroll
                    for (int nf = 0; nf < 2; nf++)
                        mma16816(acc[mf][nf], al[mf], &bh[nf * 2]);
            }
            float* outp = out + (size_t)p * 33554432ull + rowBase * 64;
            int rbase = wm * 64 + (l >> 2);
            int ncol = 2 * (l & 3);
            #pragma unroll
            for (int nf = 0; nf < 2; nf++) {
                int n = wn * 16 + nf * 8 + ncol;
                float2 bv = *(const float2*)(B2 + n);
                #pragma unroll
                for (int mf = 0; mf < 4; mf++)
                    #pragma unroll
                    for (int half = 0; half < 2; half++) {
                        int r = rbase + mf * 16 + half * 8;
                        float2 val = make_float2(acc[mf][nf][half * 2 + 0] + bv.x,
                                                 acc[mf][nf][half * 2 + 1] + bv.y);
                        *(float2*)(outp + (size_t)r * 64 + n) = val;
                    }
            }
        }
    }
}

// ---------------------------------------------------------------------------
extern "C" void kernel_launch(void* const* d_in, const int* in_sizes, int n_in,
                              void* d_out, int out_size) {
    const float* x = (const float*)d_in[0];
    const float* w0 = (const float*)d_in[1];
    const float* w1 = (const float*)d_in[2];
    const float* w2 = (const float*)d_in[3];
    const float* w3 = (const float*)d_in[4];
    const float* bw1 = (const float*)d_in[5];
    const float* bb1 = (const float*)d_in[6];
    const float* bw2 = (const float*)d_in[7];
    const float* bb2 = (const float*)d_in[8];
    const float* fw1 = (const float*)d_in[9];
    const float* fb1 = (const float*)d_in[10];
    const float* fw2 = (const float*)d_in[11];
    const float* fb2 = (const float*)d_in[12];
    float* out = (float*)d_out;

    const int SM_PF = 71680;
    const int SM_K1 = 40960;
    const int SM_K2 = 49152;
    const int SM_K3B4 = 100352;
    cudaFuncSetAttribute(prep_frag, cudaFuncAttributeMaxDynamicSharedMemorySize, SM_PF);
    cudaFuncSetAttribute(k1_stageA, cudaFuncAttributeMaxDynamicSharedMemorySize, SM_K1);
    cudaFuncSetAttribute(k2_stageB, cudaFuncAttributeMaxDynamicSharedMemorySize, SM_K2);
    cudaFuncSetAttribute(k3b4_mix_inv, cudaFuncAttributeMaxDynamicSharedMemorySize, SM_K3B4);
    cudaFuncSetAttribute(k5_mma, cudaFuncAttributeMaxDynamicSharedMemorySize, SMEM_K5);

    prep_frag<<<2, 256, SM_PF>>>(bw1, fw1, bw2, fw2);
    prep_spec<<<256, 256>>>(w0, w1, w2, w3);
    prep_e<<<40, 256>>>();
    k1_stageA<<<NB * 128, 256, SM_K1>>>(x);
    k2_stageB<<<NB * 16, 256, SM_K2>>>();
    k3a_mix1<<<NB * 32, 256>>>();
    k3b4_mix_inv<<<NB * 16, 256, SM_K3B4>>>();
    k5_mma<<<NB * 128, 256, SMEM_K5>>>(bb1, bb2, fb1, fb2, out);
}